// round 8
// baseline (speedup 1.0000x reference)
#include <cuda_runtime.h>
#include <cstdint>

#define Bn   8
#define Nn   32768
#define FDn  32
#define NGn  1024
#define KCHUNK 2048   // kNN tile (points) per buffer

typedef unsigned long long u64;

// Scratch (no allocations allowed)
__device__ float4 g_packed[Bn * Nn];        // 4 MB, {x,y,z,0} per point
__device__ u64    g_px[Bn * Nn / 2];        // pair-SoA: {x[2i], x[2i+1]}
__device__ u64    g_py[Bn * Nn / 2];
__device__ u64    g_pz[Bn * Nn / 2];
__device__ int    g_sidx[Bn * NGn];         // FPS winner idx (-1 = not ready)

// Exact (non-FMA, left-to-right) squared distance == XLA sum((a-b)**2) f32.
__device__ __forceinline__ float d2f(float ax, float ay, float az,
                                     float bx, float by, float bz) {
    float dx = ax - bx, dy = ay - by, dz = az - bz;
    return __fadd_rn(__fadd_rn(__fmul_rn(dx, dx), __fmul_rn(dy, dy)),
                     __fmul_rn(dz, dz));
}

// ---------------------------------------------------------------------------
// small PTX helpers
// ---------------------------------------------------------------------------
__device__ __forceinline__ uint32_t s2u(const void* p) {
    return (uint32_t)__cvta_generic_to_shared(p);
}
__device__ __forceinline__ uint32_t ctarank() {
    uint32_t r; asm("mov.u32 %0, %%cluster_ctarank;" : "=r"(r)); return r;
}
__device__ __forceinline__ uint32_t mapa_u32(uint32_t addr, uint32_t rank) {
    uint32_t r;
    asm("mapa.shared::cluster.u32 %0, %1, %2;" : "=r"(r) : "r"(addr), "r"(rank));
    return r;
}
__device__ __forceinline__ void st_async_u64(uint32_t raddr, u64 v, uint32_t rmbar) {
    asm volatile("st.async.shared::cluster.mbarrier::complete_tx::bytes.u64 [%0], %1, [%2];"
                 :: "r"(raddr), "l"(v), "r"(rmbar) : "memory");
}
__device__ __forceinline__ void st_async_u32(uint32_t raddr, uint32_t v, uint32_t rmbar) {
    asm volatile("st.async.shared::cluster.mbarrier::complete_tx::bytes.u32 [%0], %1, [%2];"
                 :: "r"(raddr), "r"(v), "r"(rmbar) : "memory");
}
__device__ __forceinline__ void mbar_init(uint32_t addr, uint32_t cnt) {
    asm volatile("mbarrier.init.shared.b64 [%0], %1;" :: "r"(addr), "r"(cnt) : "memory");
}
__device__ __forceinline__ void mbar_expect_tx(uint32_t addr, uint32_t bytes) {
    asm volatile("mbarrier.arrive.expect_tx.shared.b64 _, [%0], %1;"
                 :: "r"(addr), "r"(bytes) : "memory");
}
__device__ __forceinline__ void mbar_wait_parity(uint32_t addr, uint32_t parity) {
    uint32_t done;
    asm volatile("{\n\t.reg .pred p;\n\t"
                 "mbarrier.try_wait.parity.acquire.cta.shared::cta.b64 p, [%1], %2;\n\t"
                 "selp.b32 %0, 1, 0, p;\n\t}"
                 : "=r"(done) : "r"(addr), "r"(parity) : "memory");
    while (!done) {
        asm volatile("{\n\t.reg .pred p;\n\t"
                     "mbarrier.try_wait.parity.acquire.cta.shared::cta.b64 p, [%1], %2, 0x989680;\n\t"
                     "selp.b32 %0, 1, 0, p;\n\t}"
                     : "=r"(done) : "r"(addr), "r"(parity) : "memory");
    }
}
__device__ __forceinline__ void cluster_sync_asm() {
    asm volatile("barrier.cluster.arrive.aligned;" ::: "memory");
    asm volatile("barrier.cluster.wait.aligned;" ::: "memory");
}
__device__ __forceinline__ void cp_async16(uint32_t saddr, const void* gaddr) {
    asm volatile("cp.async.cg.shared.global [%0], [%1], 16;"
                 :: "r"(saddr), "l"(gaddr) : "memory");
}
__device__ __forceinline__ void cp_commit() {
    asm volatile("cp.async.commit_group;" ::: "memory");
}
template<int N>
__device__ __forceinline__ void cp_wait() {
    asm volatile("cp.async.wait_group %0;" :: "n"(N) : "memory");
}
// packed f32x2 (sm_103a): IEEE-rn per lane, bit-exact vs scalar ops
__device__ __forceinline__ u64 addx2(u64 a, u64 b) {
    u64 r; asm("add.rn.f32x2 %0, %1, %2;" : "=l"(r) : "l"(a), "l"(b)); return r;
}
__device__ __forceinline__ u64 mulx2(u64 a, u64 b) {
    u64 r; asm("mul.rn.f32x2 %0, %1, %2;" : "=l"(r) : "l"(a), "l"(b)); return r;
}
__device__ __forceinline__ u64 packx2(float lo, float hi) {
    u64 r; asm("mov.b64 %0, {%1, %2};" : "=l"(r) : "f"(lo), "f"(hi)); return r;
}
__device__ __forceinline__ void unpackx2(float& lo, float& hi, u64 v) {
    asm("mov.b64 {%0, %1}, %2;" : "=f"(lo), "=f"(hi) : "l"(v));
}
__device__ __forceinline__ void st_release_i32(int* p, int v) {
    asm volatile("st.release.gpu.global.b32 [%0], %1;" :: "l"(p), "r"(v) : "memory");
}
__device__ __forceinline__ int ld_acquire_i32(const int* p) {
    int v;
    asm volatile("ld.acquire.gpu.global.b32 %0, [%1];" : "=r"(v) : "l"(p) : "memory");
    return v;
}

// ---------------------------------------------------------------------------
// Kernel 1: pack coords + pair-SoA arrays + g_sidx sentinels (every replay)
// ---------------------------------------------------------------------------
__global__ void pack_kernel(const float* __restrict__ coord) {
    int t = blockIdx.x * blockDim.x + threadIdx.x;   // points 4t..4t+3
    if (t < Bn * NGn) g_sidx[t] = -1;                // sentinel for overlap
    if (t * 4 >= Bn * Nn) return;
    const float4* c4 = (const float4*)(coord + (size_t)t * 12);
    float4 a = c4[0], b = c4[1], c = c4[2];
    g_packed[t * 4 + 0] = make_float4(a.x, a.y, a.z, 0.f);
    g_packed[t * 4 + 1] = make_float4(a.w, b.x, b.y, 0.f);
    g_packed[t * 4 + 2] = make_float4(b.z, b.w, c.x, 0.f);
    g_packed[t * 4 + 3] = make_float4(c.y, c.z, c.w, 0.f);
    g_px[2 * t]     = packx2(a.x, a.w);
    g_px[2 * t + 1] = packx2(b.z, c.y);
    g_py[2 * t]     = packx2(a.y, b.x);
    g_py[2 * t + 1] = packx2(b.w, c.z);
    g_pz[2 * t]     = packx2(a.z, b.y);
    g_pz[2 * t + 1] = packx2(c.x, c.w);
}

// ---------------------------------------------------------------------------
// FPS body (proven R7 design), dynamic-smem version. 16 CTAs x 256 thr x
// 8 pts/thread per batch; redux-only argmax at every level (jnp.argmax
// smallest-index tie-break preserved: lane/slot/rank order == index order);
// one candidate per CTA exchanged via st.async + mbarrier; winners published
// to g_sidx with st.release.gpu for the concurrently-running kNN CTAs.
// ---------------------------------------------------------------------------
__device__ __forceinline__ void fps_part(char* sm) {
    constexpr int C = 16, P = 8;
    constexpr int NW = 8;                 // warps
    constexpr int PTS = 2048;             // points per CTA

    float4*   tile  = (float4*)sm;                    // 32KB
    float4*   cand4 = (float4*)(sm + 32768);          // [2][16] {d2,x,y,z}
    uint32_t* candI = (uint32_t*)(sm + 33280);        // [2][16]
    u64*      slotK = (u64*)(sm + 33408);             // [8]
    u64*      mbarp = (u64*)(sm + 33472);             // [2]

    const unsigned FULL = 0xffffffffu;
    int tid = threadIdx.x, lane = tid & 31, wid = tid >> 5;
    uint32_t rank = ctarank();
    int b = blockIdx.x / C;
    uint32_t local_base = rank * PTS + (uint32_t)tid * P;
    int gbase = b * Nn + (int)local_base;
    const uint32_t TXB = (rank == 0) ? 20u * C : 16u * C;

    uint32_t mb0 = s2u(&mbarp[0]), mb1 = s2u(&mbarp[1]);
    if (tid == 0) { mbar_init(mb0, 1); mbar_init(mb1, 1); }

    uint32_t rC4[2], rI[2], rMB[2];
    if (wid == 0 && lane < C) {
#pragma unroll
        for (int q = 0; q < 2; q++) {
            rC4[q] = mapa_u32(s2u(&cand4[q * C + (int)rank]), (uint32_t)lane);
            rI[q]  = mapa_u32(s2u(&candI[q * C + (int)rank]), 0u);
            rMB[q] = mapa_u32(q ? mb1 : mb0, (uint32_t)lane);
        }
    }

    float dist[P];
    u64 pxp[P / 2], pyp[P / 2], pzp[P / 2];
    {
        float px[P], py[P], pz[P];
#pragma unroll
        for (int j = 0; j < P; j++) {
            float4 q = g_packed[gbase + j];
            px[j] = q.x; py[j] = q.y; pz[j] = q.z;
            tile[tid * P + j] = q;
        }
#pragma unroll
        for (int p = 0; p < P / 2; p++) {
            pxp[p] = packx2(px[2 * p], px[2 * p + 1]);
            pyp[p] = packx2(py[2 * p], py[2 * p + 1]);
            pzp[p] = packx2(pz[2 * p], pz[2 * p + 1]);
        }
        float4 p0 = g_packed[b * Nn];
#pragma unroll
        for (int j = 0; j < P; j++)
            dist[j] = d2f(px[j], py[j], pz[j], p0.x, p0.y, p0.z);
    }
    float bd = dist[0];
#pragma unroll
    for (int j = 1; j < P; j++) bd = fmaxf(bd, dist[j]);
    if (rank == 0 && tid == 0) st_release_i32(&g_sidx[b * NGn + 0], b * Nn);

    __syncthreads();
    cluster_sync_asm();   // mbarriers + tiles ready before any st.async

    for (int k = 1; k < NGn; k++) {
        int kb = k & 1;
        uint32_t parity = (uint32_t)(((k - 1) >> 1) & 1);
        uint32_t mbk = kb ? mb1 : mb0;
        if (tid == 0) mbar_expect_tx(mbk, TXB);

        // smallest j with dist[j] == bd (jnp.argmax tie-break)
        int bj = P - 1;
#pragma unroll
        for (int j = P - 2; j >= 0; j--) bj = (dist[j] == bd) ? j : bj;
        uint32_t myinv = 0xFFFFFFFFu - (local_base + (uint32_t)bj);

        uint32_t dbits = __float_as_uint(bd);
        uint32_t wmax  = __reduce_max_sync(FULL, dbits);
        uint32_t inv   = (dbits == wmax) ? myinv : 0u;
        uint32_t winv  = __reduce_max_sync(FULL, inv);
        if (lane == 0) slotK[wid] = ((u64)wmax << 32) | winv;
        __syncthreads();

        if (wid == 0) {
            u64 k0 = slotK[lane & (NW - 1)];
            uint32_t hi = (lane < NW) ? (uint32_t)(k0 >> 32) : 0u;
            uint32_t hm = __reduce_max_sync(FULL, hi);
            uint32_t lo = (hi == hm) ? (uint32_t)k0 : 0u;
            uint32_t lm = __reduce_max_sync(FULL, lo);
            uint32_t ci = 0xFFFFFFFFu - lm;
            float4 w = tile[ci & (PTS - 1)];
            if (lane < C) {
                st_async_u64(rC4[kb],
                             ((u64)__float_as_uint(w.x) << 32) | hm, rMB[kb]);
                st_async_u64(rC4[kb] + 8,
                             ((u64)__float_as_uint(w.z) << 32)
                             | __float_as_uint(w.y), rMB[kb]);
            }
            if (lane == 0) st_async_u32(rI[kb], ci, rMB[kb]);
        }

        mbar_wait_parity(mbk, parity);

        int cl = lane & (C - 1);
        float4 cv = cand4[kb * C + cl];
        uint32_t d = (lane < C) ? __float_as_uint(cv.x) : 0u;
        uint32_t m = __reduce_max_sync(FULL, d);
        int src = __ffs(__ballot_sync(FULL, d == m)) - 1;
        float gx = __shfl_sync(FULL, cv.y, src);
        float gy = __shfl_sync(FULL, cv.z, src);
        float gz = __shfl_sync(FULL, cv.w, src);
        if (rank == 0 && tid == 0)
            st_release_i32(&g_sidx[b * NGn + k], b * Nn + (int)candI[kb * C + src]);

        u64 ngx = packx2(-gx, -gx);
        u64 ngy = packx2(-gy, -gy);
        u64 ngz = packx2(-gz, -gz);
        bd = -1.f;
#pragma unroll
        for (int p = 0; p < P / 2; p++) {
            u64 dx = addx2(pxp[p], ngx);
            u64 dy = addx2(pyp[p], ngy);
            u64 dz = addx2(pzp[p], ngz);
            u64 s = addx2(addx2(mulx2(dx, dx), mulx2(dy, dy)), mulx2(dz, dz));
            float s0, s1; unpackx2(s0, s1, s);
            float m0 = fminf(dist[2 * p], s0);
            float m1 = fminf(dist[2 * p + 1], s1);
            dist[2 * p] = m0; dist[2 * p + 1] = m1;
            bd = fmaxf(bd, m0); bd = fmaxf(bd, m1);
        }
    }
}

// ---------------------------------------------------------------------------
// kNN body (dynamic smem, 256 thr = 8 warps, 1 sample/warp). Spins on
// g_sidx[s] (acquire) until FPS publishes it, then scans pair-SoA tiles.
// ---------------------------------------------------------------------------
__device__ __forceinline__ void knn_part(char* sm, int q,
                                         const float* __restrict__ coord,
                                         const float* __restrict__ feat,
                                         const int* __restrict__ labels,
                                         float* __restrict__ out) {
    u64* scx = (u64*)sm;               // [2][1024]
    u64* scy = (u64*)(sm + 16384);
    u64* scz = (u64*)(sm + 32768);
    const unsigned FULL = 0xffffffffu;
    int tid = threadIdx.x, lane = tid & 31, wid = tid >> 5;
    int b = q & 7;
    int kk = (q >> 3) * 8 + wid;       // low blockIdx -> early-ready samples
    int s = b * NGn + kk;

    // prefetch tile 0 (sample-independent) before spinning
    uint32_t base = s2u(sm);
    int pbase = b * (Nn / 2);
    {
        int po = pbase + tid * 4;
        uint32_t o = tid * 32;
        cp_async16(base + o,             &g_px[po]);
        cp_async16(base + o + 16,        &g_px[po + 2]);
        cp_async16(base + 16384 + o,     &g_py[po]);
        cp_async16(base + 16384 + o + 16,&g_py[po + 2]);
        cp_async16(base + 32768 + o,     &g_pz[po]);
        cp_async16(base + 32768 + o + 16,&g_pz[po + 2]);
        cp_commit();
    }

    // wait for this warp's sample index from the concurrently-running FPS
    int si;
    if (lane == 0) {
        for (;;) {
            si = ld_acquire_i32(&g_sidx[s]);
            if (si >= 0) break;
            __nanosleep(128);
        }
    }
    si = __shfl_sync(FULL, si, 0);
    float4 sp = g_packed[si];
    u64 nspx = packx2(-sp.x, -sp.x);
    u64 nspy = packx2(-sp.y, -sp.y);
    u64 nspz = packx2(-sp.z, -sp.z);

    float kd = 3.4028235e38f; unsigned ki = 0xffffffffu;
    float tmd = 3.4028235e38f; unsigned tmi = 0xffffffffu; int tml = 0;

    constexpr int NT = Nn / KCHUNK;    // 16 tiles
    for (int c = 0; c < NT; c++) {
        int buf = c & 1;
        if (c + 1 < NT) {
            int po = pbase + (c + 1) * 1024 + tid * 4;
            uint32_t o = (buf ^ 1) * 8192 + tid * 32;
            cp_async16(base + o,              &g_px[po]);
            cp_async16(base + o + 16,         &g_px[po + 2]);
            cp_async16(base + 16384 + o,      &g_py[po]);
            cp_async16(base + 16384 + o + 16, &g_py[po + 2]);
            cp_async16(base + 32768 + o,      &g_pz[po]);
            cp_async16(base + 32768 + o + 16, &g_pz[po + 2]);
            cp_commit();
            cp_wait<1>();
        } else {
            cp_wait<0>();
        }
        __syncthreads();
        int cbase = b * Nn + c * KCHUNK;
        for (int j = 0; j < KCHUNK / 64; j++) {
            int pi = buf * 1024 + j * 32 + lane;
            u64 dx = addx2(scx[pi], nspx);
            u64 dy = addx2(scy[pi], nspy);
            u64 dz = addx2(scz[pi], nspz);
            u64 ss = addx2(addx2(mulx2(dx, dx), mulx2(dy, dy)), mulx2(dz, dz));
            float d2A, d2B; unpackx2(d2A, d2B, ss);
            int gb = cbase + j * 64;
            unsigned giA = (unsigned)(gb + 2 * lane);
            unsigned giB = giA + 1;
            unsigned mA = __ballot_sync(FULL, (d2A < tmd) || (d2A == tmd && giA < tmi));
            unsigned mB = __ballot_sync(FULL, (d2B < tmd) || (d2B == tmd && giB < tmi));
            while (mA) {
                int ins = __ffs(mA) - 1; mA &= mA - 1;
                float cd = __shfl_sync(FULL, d2A, ins);
                unsigned cgi = (unsigned)(gb + 2 * ins);
                if ((cd < tmd) || (cd == tmd && cgi < tmi)) {
                    if (lane == tml) { kd = cd; ki = cgi; }
                    unsigned db = __float_as_uint(kd);
                    unsigned m  = __reduce_max_sync(FULL, db);
                    bool tie    = (db == m);
                    unsigned mi2 = __reduce_max_sync(FULL, tie ? ki : 0u);
                    tml = __ffs(__ballot_sync(FULL, tie && ki == mi2)) - 1;
                    tmd = __uint_as_float(m); tmi = mi2;
                }
            }
            while (mB) {
                int ins = __ffs(mB) - 1; mB &= mB - 1;
                float cd = __shfl_sync(FULL, d2B, ins);
                unsigned cgi = (unsigned)(gb + 2 * ins + 1);
                if ((cd < tmd) || (cd == tmd && cgi < tmi)) {
                    if (lane == tml) { kd = cd; ki = cgi; }
                    unsigned db = __float_as_uint(kd);
                    unsigned m  = __reduce_max_sync(FULL, db);
                    bool tie    = (db == m);
                    unsigned mi2 = __reduce_max_sync(FULL, tie ? ki : 0u);
                    tml = __ffs(__ballot_sync(FULL, tie && ki == mi2)) - 1;
                    tmd = __uint_as_float(m); tmi = mi2;
                }
            }
        }
        __syncthreads();
    }

    // ---- angles: angle = 2*atan2(sqrt(t - a.b), sqrt(t + a.b)), t=|a||b| ----
    float a_own = feat[(size_t)si * FDn + lane];
    float dot = 0.f, an2 = 0.f, bn2 = 0.f;
    const float4* frow = (const float4*)(feat + (size_t)ki * FDn);
#pragma unroll
    for (int g = 0; g < FDn / 4; g++) {
        float4 bv = frow[g];
        float a0 = __shfl_sync(FULL, a_own, g * 4 + 0);
        float a1 = __shfl_sync(FULL, a_own, g * 4 + 1);
        float a2 = __shfl_sync(FULL, a_own, g * 4 + 2);
        float a3 = __shfl_sync(FULL, a_own, g * 4 + 3);
        dot = fmaf(a0, bv.x, dot); an2 = fmaf(a0, a0, an2); bn2 = fmaf(bv.x, bv.x, bn2);
        dot = fmaf(a1, bv.y, dot); an2 = fmaf(a1, a1, an2); bn2 = fmaf(bv.y, bv.y, bn2);
        dot = fmaf(a2, bv.z, dot); an2 = fmaf(a2, a2, an2); bn2 = fmaf(bv.z, bv.z, bn2);
        dot = fmaf(a3, bv.w, dot); an2 = fmaf(a3, a3, an2); bn2 = fmaf(bv.w, bv.w, bn2);
    }
    float t = sqrtf(an2) * sqrtf(bn2);
    float ang = 2.f * atan2f(sqrtf(fmaxf(t - dot, 0.f)), sqrtf(fmaxf(t + dot, 0.f)));
    if (ki == (unsigned)si) ang = 0.f;
    float ssum = ang;
#pragma unroll
    for (int o = 16; o; o >>= 1) ssum += __shfl_xor_sync(FULL, ssum, o);
    float pc = ssum / 31.f;

    const int OFF_FEAT = Bn * NGn * 3;
    const int OFF_SW   = OFF_FEAT + Bn * NGn * (FDn + 1);
    const int OFF_LAB  = OFF_SW + Bn * NGn;
    const int OFF_SIDX = OFF_LAB + Bn * NGn;
    if (lane < 3) out[s * 3 + lane] = coord[si * 3 + lane];
    out[OFF_FEAT + s * 33 + lane] = a_own;
    if (lane == 0) {
        out[OFF_FEAT + s * 33 + 32] = pc;
        out[OFF_SW + s]   = pc > 0.087266f ? 1.f : 0.f;
        out[OFF_LAB + s]  = (float)labels[si];
        out[OFF_SIDX + s] = (float)si;
    }
}

// ---------------------------------------------------------------------------
// Fused kernel: blockIdx < 128 -> FPS clusters; else kNN CTAs (overlapped).
// kNN clusters never execute cluster-scope ops. 1152 CTAs = 72 x 16-clusters.
// ---------------------------------------------------------------------------
__global__ void __cluster_dims__(16, 1, 1) __launch_bounds__(256, 1)
fused_kernel(const float* __restrict__ coord, const float* __restrict__ feat,
             const int* __restrict__ labels, float* __restrict__ out) {
    extern __shared__ char sm[];
    if (blockIdx.x < 128) fps_part(sm);
    else knn_part(sm, blockIdx.x - 128, coord, feat, labels, out);
}

// ---------------------------------------------------------------------------
// Fallback path (if non-portable cluster-16 rejected): R5-proven fps8 +
// standalone knn (512 thr), serialized.
// ---------------------------------------------------------------------------
__global__ void __cluster_dims__(8, 1, 1) __launch_bounds__(1024, 1)
fps_kernel8() {
    constexpr int C = 8, T = 1024, P = 4;
    constexpr int NW = T / 32;
    constexpr int PTS = T * P;
    constexpr uint32_t TXB = 20u * C;

    __shared__ uint32_t slotD[NW], slotI[NW];
    __shared__ float    slotX[NW], slotY[NW], slotZ[NW];
    __shared__ u64      candDI[2][C];
    __shared__ u64      candXY[2][C];
    __shared__ uint32_t candZ[2][C];
    __shared__ u64      mbarrier_s[2];

    const unsigned FULL = 0xffffffffu;
    int tid = threadIdx.x, lane = tid & 31, wid = tid >> 5;
    uint32_t rank = ctarank();
    int b = blockIdx.x / C;
    uint32_t local_base = rank * PTS + (uint32_t)tid * P;
    int gbase = b * Nn + (int)local_base;

    uint32_t mb0 = s2u(&mbarrier_s[0]), mb1 = s2u(&mbarrier_s[1]);
    if (tid == 0) { mbar_init(mb0, 1); mbar_init(mb1, 1); }

    uint32_t rDI[2], rXY[2], rZ[2], rMB[2];
    if (wid == 0 && lane < C) {
#pragma unroll
        for (int q = 0; q < 2; q++) {
            rDI[q] = mapa_u32(s2u(&candDI[q][rank]), (uint32_t)lane);
            rXY[q] = mapa_u32(s2u(&candXY[q][rank]), (uint32_t)lane);
            rZ[q]  = mapa_u32(s2u(&candZ[q][rank]),  (uint32_t)lane);
            rMB[q] = mapa_u32(q ? mb1 : mb0, (uint32_t)lane);
        }
    }

    float px[P], py[P], pz[P], dist[P];
#pragma unroll
    for (int j = 0; j < P; j++) {
        float4 q = g_packed[gbase + j];
        px[j] = q.x; py[j] = q.y; pz[j] = q.z;
    }

    float4 p0 = g_packed[b * Nn];
    float bd = -1.f; int bj = 0;
#pragma unroll
    for (int j = 0; j < P; j++) {
        float d = d2f(px[j], py[j], pz[j], p0.x, p0.y, p0.z);
        dist[j] = d;
        if (d > bd) { bd = d; bj = j; }
    }
    if (rank == 0 && tid == 0) g_sidx[b * NGn + 0] = b * Nn;

    __syncthreads();
    cluster_sync_asm();

    for (int k = 1; k < NGn; k++) {
        int kb = k & 1;
        uint32_t parity = (uint32_t)(((k - 1) >> 1) & 1);
        uint32_t mbk = kb ? mb1 : mb0;
        if (tid == 0) mbar_expect_tx(mbk, TXB);

        float cx, cy, cz;
        {
            int j = bj;
            float x01 = (j & 1) ? px[1] : px[0], x23 = (j & 1) ? px[3] : px[2];
            float y01 = (j & 1) ? py[1] : py[0], y23 = (j & 1) ? py[3] : py[2];
            float z01 = (j & 1) ? pz[1] : pz[0], z23 = (j & 1) ? pz[3] : pz[2];
            cx = (j & 2) ? x23 : x01; cy = (j & 2) ? y23 : y01; cz = (j & 2) ? z23 : z01;
        }
        uint32_t myidx = local_base + (uint32_t)bj;

        uint32_t dbits = __float_as_uint(bd);
        uint32_t wmax  = __reduce_max_sync(FULL, dbits);
        int wsrc = __ffs(__ballot_sync(FULL, dbits == wmax)) - 1;
        uint32_t widx = __shfl_sync(FULL, myidx, wsrc);
        float wx = __shfl_sync(FULL, cx, wsrc);
        float wy = __shfl_sync(FULL, cy, wsrc);
        float wz = __shfl_sync(FULL, cz, wsrc);
        if (lane == 0) {
            slotD[wid] = wmax; slotI[wid] = widx;
            slotX[wid] = wx; slotY[wid] = wy; slotZ[wid] = wz;
        }
        __syncthreads();

        if (wid == 0) {
            int sl = lane & (NW - 1);
            uint32_t d = (lane < NW) ? slotD[sl] : 0u;
            uint32_t i = slotI[sl];
            float x = slotX[sl], y = slotY[sl], z = slotZ[sl];
            uint32_t m = __reduce_max_sync(FULL, d);
            int src = __ffs(__ballot_sync(FULL, d == m)) - 1;
            uint32_t ci = __shfl_sync(FULL, i, src);
            float fx = __shfl_sync(FULL, x, src);
            float fy = __shfl_sync(FULL, y, src);
            float fz = __shfl_sync(FULL, z, src);
            if (lane < C) {
                st_async_u64(rDI[kb], ((u64)m << 32) | ci, rMB[kb]);
                st_async_u64(rXY[kb],
                             ((u64)__float_as_uint(fy) << 32) | __float_as_uint(fx),
                             rMB[kb]);
                st_async_u32(rZ[kb], __float_as_uint(fz), rMB[kb]);
            }
        }

        mbar_wait_parity(mbk, parity);

        int cl = lane & (C - 1);
        u64 di = candDI[kb][cl];
        u64 xy = candXY[kb][cl];
        uint32_t zz = candZ[kb][cl];
        uint32_t d = (lane < C) ? (uint32_t)(di >> 32) : 0u;
        uint32_t m = __reduce_max_sync(FULL, d);
        int src = __ffs(__ballot_sync(FULL, d == m)) - 1;
        uint32_t wl = __shfl_sync(FULL, (uint32_t)di, src);
        u64 wxy = __shfl_sync(FULL, xy, src);
        uint32_t wzb = __shfl_sync(FULL, zz, src);
        float gx = __uint_as_float((uint32_t)wxy);
        float gy = __uint_as_float((uint32_t)(wxy >> 32));
        float gz = __uint_as_float(wzb);
        if (rank == 0 && tid == 0) g_sidx[b * NGn + k] = b * Nn + (int)wl;

        bd = -1.f; bj = 0;
#pragma unroll
        for (int j = 0; j < P; j++) {
            float nd = d2f(px[j], py[j], pz[j], gx, gy, gz);
            float mn = fminf(dist[j], nd);
            dist[j] = mn;
            if (mn > bd) { bd = mn; bj = j; }
        }
    }
}

__global__ void __launch_bounds__(512, 1)
knn_kernel(const float* __restrict__ coord, const float* __restrict__ feat,
           const int* __restrict__ labels, float* __restrict__ out) {
    __shared__ u64 scx[2][KCHUNK / 2];
    __shared__ u64 scy[2][KCHUNK / 2];
    __shared__ u64 scz[2][KCHUNK / 2];
    const unsigned FULL = 0xffffffffu;
    int tid = threadIdx.x, lane = tid & 31, wid = tid >> 5;
    int s = blockIdx.x * 16 + wid;
    int b = s >> 10;
    int si = g_sidx[s];
    float4 sp = g_packed[si];
    u64 nspx = packx2(-sp.x, -sp.x);
    u64 nspy = packx2(-sp.y, -sp.y);
    u64 nspz = packx2(-sp.z, -sp.z);

    float kd = 3.4028235e38f; unsigned ki = 0xffffffffu;
    float tmd = 3.4028235e38f; unsigned tmi = 0xffffffffu; int tml = 0;

    constexpr int NT = Nn / KCHUNK;
    int pbase = b * (Nn / 2);
    auto stage = [&](int buf, int c) {
        int po = pbase + c * (KCHUNK / 2) + tid * 2;
        cp_async16(s2u(&scx[buf][tid * 2]), &g_px[po]);
        cp_async16(s2u(&scy[buf][tid * 2]), &g_py[po]);
        cp_async16(s2u(&scz[buf][tid * 2]), &g_pz[po]);
        cp_commit();
    };
    stage(0, 0);
    for (int c = 0; c < NT; c++) {
        int buf = c & 1;
        if (c + 1 < NT) { stage(buf ^ 1, c + 1); cp_wait<1>(); }
        else           { cp_wait<0>(); }
        __syncthreads();
        int cbase = b * Nn + c * KCHUNK;
        for (int j = 0; j < KCHUNK / 64; j++) {
            int pi = j * 32 + lane;
            u64 dx = addx2(scx[buf][pi], nspx);
            u64 dy = addx2(scy[buf][pi], nspy);
            u64 dz = addx2(scz[buf][pi], nspz);
            u64 ss = addx2(addx2(mulx2(dx, dx), mulx2(dy, dy)), mulx2(dz, dz));
            float d2A, d2B; unpackx2(d2A, d2B, ss);
            int gb = cbase + j * 64;
            unsigned giA = (unsigned)(gb + 2 * lane);
            unsigned giB = giA + 1;
            unsigned mA = __ballot_sync(FULL, (d2A < tmd) || (d2A == tmd && giA < tmi));
            unsigned mB = __ballot_sync(FULL, (d2B < tmd) || (d2B == tmd && giB < tmi));
            while (mA) {
                int ins = __ffs(mA) - 1; mA &= mA - 1;
                float cd = __shfl_sync(FULL, d2A, ins);
                unsigned cgi = (unsigned)(gb + 2 * ins);
                if ((cd < tmd) || (cd == tmd && cgi < tmi)) {
                    if (lane == tml) { kd = cd; ki = cgi; }
                    unsigned db = __float_as_uint(kd);
                    unsigned m  = __reduce_max_sync(FULL, db);
                    bool tie    = (db == m);
                    unsigned mi2 = __reduce_max_sync(FULL, tie ? ki : 0u);
                    tml = __ffs(__ballot_sync(FULL, tie && ki == mi2)) - 1;
                    tmd = __uint_as_float(m); tmi = mi2;
                }
            }
            while (mB) {
                int ins = __ffs(mB) - 1; mB &= mB - 1;
                float cd = __shfl_sync(FULL, d2B, ins);
                unsigned cgi = (unsigned)(gb + 2 * ins + 1);
                if ((cd < tmd) || (cd == tmd && cgi < tmi)) {
                    if (lane == tml) { kd = cd; ki = cgi; }
                    unsigned db = __float_as_uint(kd);
                    unsigned m  = __reduce_max_sync(FULL, db);
                    bool tie    = (db == m);
                    unsigned mi2 = __reduce_max_sync(FULL, tie ? ki : 0u);
                    tml = __ffs(__ballot_sync(FULL, tie && ki == mi2)) - 1;
                    tmd = __uint_as_float(m); tmi = mi2;
                }
            }
        }
        __syncthreads();
    }

    float a_own = feat[(size_t)si * FDn + lane];
    float dot = 0.f, an2 = 0.f, bn2 = 0.f;
    const float4* frow = (const float4*)(feat + (size_t)ki * FDn);
#pragma unroll
    for (int g = 0; g < FDn / 4; g++) {
        float4 bv = frow[g];
        float a0 = __shfl_sync(FULL, a_own, g * 4 + 0);
        float a1 = __shfl_sync(FULL, a_own, g * 4 + 1);
        float a2 = __shfl_sync(FULL, a_own, g * 4 + 2);
        float a3 = __shfl_sync(FULL, a_own, g * 4 + 3);
        dot = fmaf(a0, bv.x, dot); an2 = fmaf(a0, a0, an2); bn2 = fmaf(bv.x, bv.x, bn2);
        dot = fmaf(a1, bv.y, dot); an2 = fmaf(a1, a1, an2); bn2 = fmaf(bv.y, bv.y, bn2);
        dot = fmaf(a2, bv.z, dot); an2 = fmaf(a2, a2, an2); bn2 = fmaf(bv.z, bv.z, bn2);
        dot = fmaf(a3, bv.w, dot); an2 = fmaf(a3, a3, an2); bn2 = fmaf(bv.w, bv.w, bn2);
    }
    float t = sqrtf(an2) * sqrtf(bn2);
    float ang = 2.f * atan2f(sqrtf(fmaxf(t - dot, 0.f)), sqrtf(fmaxf(t + dot, 0.f)));
    if (ki == (unsigned)si) ang = 0.f;
    float ssum = ang;
#pragma unroll
    for (int o = 16; o; o >>= 1) ssum += __shfl_xor_sync(FULL, ssum, o);
    float pc = ssum / 31.f;

    const int OFF_FEAT = Bn * NGn * 3;
    const int OFF_SW   = OFF_FEAT + Bn * NGn * (FDn + 1);
    const int OFF_LAB  = OFF_SW + Bn * NGn;
    const int OFF_SIDX = OFF_LAB + Bn * NGn;
    if (lane < 3) out[s * 3 + lane] = coord[si * 3 + lane];
    out[OFF_FEAT + s * 33 + lane] = a_own;
    if (lane == 0) {
        out[OFF_FEAT + s * 33 + 32] = pc;
        out[OFF_SW + s]   = pc > 0.087266f ? 1.f : 0.f;
        out[OFF_LAB + s]  = (float)labels[si];
        out[OFF_SIDX + s] = (float)si;
    }
}

// ---------------------------------------------------------------------------
extern "C" void kernel_launch(void* const* d_in, const int* in_sizes, int n_in,
                              void* d_out, int out_size) {
    const float* coord  = (const float*)d_in[0];
    const float* feat   = (const float*)d_in[1];
    const int*   labels = (const int*)d_in[2];
    float* out = (float*)d_out;

    pack_kernel<<<(Bn * Nn / 4 + 255) / 256, 256>>>(coord);

    cudaError_t rc = cudaFuncSetAttribute(
        (const void*)fused_kernel,
        cudaFuncAttributeNonPortableClusterSizeAllowed, 1);
    if (rc == cudaSuccess) {
        fused_kernel<<<128 + 1024, 256, 49152>>>(coord, feat, labels, out);
    } else {
        (void)cudaGetLastError();
        fps_kernel8<<<Bn * 8, 1024>>>();
        knn_kernel<<<(Bn * NGn) / 16, 512>>>(coord, feat, labels, out);
    }
}

// round 10
// speedup vs baseline: 1.2406x; 1.2406x over previous
#include <cuda_runtime.h>
#include <cstdint>

#define Bn   8
#define Nn   32768
#define FDn  32
#define NGn  1024
#define KCHUNK 2048   // kNN tile (points) per buffer

typedef unsigned long long u64;

// Scratch (no allocations allowed)
__device__ float4 g_packed[Bn * Nn];        // 4 MB, {x,y,z,0} per point
__device__ u64    g_px[Bn * Nn / 2];        // pair-SoA: {x[2i], x[2i+1]}
__device__ u64    g_py[Bn * Nn / 2];
__device__ u64    g_pz[Bn * Nn / 2];
__device__ int    g_sidx[Bn * NGn];         // FPS-selected global point idx

// Exact (non-FMA, left-to-right) squared distance == XLA sum((a-b)**2) f32.
__device__ __forceinline__ float d2f(float ax, float ay, float az,
                                     float bx, float by, float bz) {
    float dx = ax - bx, dy = ay - by, dz = az - bz;
    return __fadd_rn(__fadd_rn(__fmul_rn(dx, dx), __fmul_rn(dy, dy)),
                     __fmul_rn(dz, dz));
}

// ---------------------------------------------------------------------------
// small PTX helpers
// ---------------------------------------------------------------------------
__device__ __forceinline__ uint32_t s2u(const void* p) {
    return (uint32_t)__cvta_generic_to_shared(p);
}
__device__ __forceinline__ uint32_t ctarank() {
    uint32_t r; asm("mov.u32 %0, %%cluster_ctarank;" : "=r"(r)); return r;
}
__device__ __forceinline__ uint32_t mapa_u32(uint32_t addr, uint32_t rank) {
    uint32_t r;
    asm("mapa.shared::cluster.u32 %0, %1, %2;" : "=r"(r) : "r"(addr), "r"(rank));
    return r;
}
__device__ __forceinline__ void st_async_u64(uint32_t raddr, u64 v, uint32_t rmbar) {
    asm volatile("st.async.shared::cluster.mbarrier::complete_tx::bytes.u64 [%0], %1, [%2];"
                 :: "r"(raddr), "l"(v), "r"(rmbar) : "memory");
}
__device__ __forceinline__ void st_async_u32(uint32_t raddr, uint32_t v, uint32_t rmbar) {
    asm volatile("st.async.shared::cluster.mbarrier::complete_tx::bytes.u32 [%0], %1, [%2];"
                 :: "r"(raddr), "r"(v), "r"(rmbar) : "memory");
}
__device__ __forceinline__ void mbar_init(uint32_t addr, uint32_t cnt) {
    asm volatile("mbarrier.init.shared.b64 [%0], %1;" :: "r"(addr), "r"(cnt) : "memory");
}
__device__ __forceinline__ void mbar_expect_tx(uint32_t addr, uint32_t bytes) {
    asm volatile("mbarrier.arrive.expect_tx.shared.b64 _, [%0], %1;"
                 :: "r"(addr), "r"(bytes) : "memory");
}
__device__ __forceinline__ void mbar_wait_parity(uint32_t addr, uint32_t parity) {
    uint32_t done;
    asm volatile("{\n\t.reg .pred p;\n\t"
                 "mbarrier.try_wait.parity.acquire.cta.shared::cta.b64 p, [%1], %2;\n\t"
                 "selp.b32 %0, 1, 0, p;\n\t}"
                 : "=r"(done) : "r"(addr), "r"(parity) : "memory");
    while (!done) {
        asm volatile("{\n\t.reg .pred p;\n\t"
                     "mbarrier.try_wait.parity.acquire.cta.shared::cta.b64 p, [%1], %2, 0x989680;\n\t"
                     "selp.b32 %0, 1, 0, p;\n\t}"
                     : "=r"(done) : "r"(addr), "r"(parity) : "memory");
    }
}
__device__ __forceinline__ void cluster_sync_asm() {
    asm volatile("barrier.cluster.arrive.aligned;" ::: "memory");
    asm volatile("barrier.cluster.wait.aligned;" ::: "memory");
}
__device__ __forceinline__ void cp_async16(uint32_t saddr, const void* gaddr) {
    asm volatile("cp.async.cg.shared.global [%0], [%1], 16;"
                 :: "r"(saddr), "l"(gaddr) : "memory");
}
__device__ __forceinline__ void cp_commit() {
    asm volatile("cp.async.commit_group;" ::: "memory");
}
template<int N>
__device__ __forceinline__ void cp_wait() {
    asm volatile("cp.async.wait_group %0;" :: "n"(N) : "memory");
}
// packed f32x2 (sm_103a): add/mul only — IEEE-rn per lane, bit-exact vs scalar
__device__ __forceinline__ u64 addx2(u64 a, u64 b) {
    u64 r; asm("add.rn.f32x2 %0, %1, %2;" : "=l"(r) : "l"(a), "l"(b)); return r;
}
__device__ __forceinline__ u64 mulx2(u64 a, u64 b) {
    u64 r; asm("mul.rn.f32x2 %0, %1, %2;" : "=l"(r) : "l"(a), "l"(b)); return r;
}
__device__ __forceinline__ u64 packx2(float lo, float hi) {
    u64 r; asm("mov.b64 %0, {%1, %2};" : "=l"(r) : "f"(lo), "f"(hi)); return r;
}
__device__ __forceinline__ void unpackx2(float& lo, float& hi, u64 v) {
    asm("mov.b64 {%0, %1}, %2;" : "=f"(lo), "=f"(hi) : "l"(v));
}

// ---------------------------------------------------------------------------
// Kernel 1: pack coords [N,3] AoS -> float4 AND pair-SoA u64 arrays
// ---------------------------------------------------------------------------
__global__ void pack_kernel(const float* __restrict__ coord) {
    int t = blockIdx.x * blockDim.x + threadIdx.x;   // points 4t..4t+3
    if (t * 4 >= Bn * Nn) return;
    const float4* c4 = (const float4*)(coord + (size_t)t * 12);
    float4 a = c4[0], b = c4[1], c = c4[2];
    g_packed[t * 4 + 0] = make_float4(a.x, a.y, a.z, 0.f);
    g_packed[t * 4 + 1] = make_float4(a.w, b.x, b.y, 0.f);
    g_packed[t * 4 + 2] = make_float4(b.z, b.w, c.x, 0.f);
    g_packed[t * 4 + 3] = make_float4(c.y, c.z, c.w, 0.f);
    g_px[2 * t]     = packx2(a.x, a.w);
    g_px[2 * t + 1] = packx2(b.z, c.y);
    g_py[2 * t]     = packx2(a.y, b.x);
    g_py[2 * t + 1] = packx2(b.w, c.z);
    g_pz[2 * t]     = packx2(a.z, b.y);
    g_pz[2 * t + 1] = packx2(c.x, c.w);
}

// ---------------------------------------------------------------------------
// FPS: cluster of 16 CTAs x 256 thr x 8 pts/thread per batch (proven R7
// design). redux-only argmax at every level (jnp.argmax smallest-index
// tie-break preserved: lane/slot/rank order == index order). One candidate
// {d2,x,y,z} per CTA exchanged via st.async + mbarrier; winner index shipped
// to rank 0 only. Winner coords from 32KB smem tile (broadcast LDS.128).
// Distance update: packed f32x2 add/mul + scalar min/max (bit-exact).
// ---------------------------------------------------------------------------
__global__ void __cluster_dims__(16, 1, 1) __launch_bounds__(256, 1)
fps_kernel16() {
    constexpr int C = 16, T = 256, P = 8;
    constexpr int NW = T / 32;            // 8 warps
    constexpr int PTS = T * P;            // 2048 points per CTA

    __shared__ __align__(16) float4 tile[PTS];          // 32KB coord tile
    __shared__ u64 slotK[NW];                            // {d2bits, ~idx}
    __shared__ __align__(16) float4 cand4[2][C];         // {d2, x, y, z}
    __shared__ uint32_t candI[2][C];                     // idx (rank0 only)
    __shared__ u64 mbarrier_s[2];

    const unsigned FULL = 0xffffffffu;
    int tid = threadIdx.x, lane = tid & 31, wid = tid >> 5;
    uint32_t rank = ctarank();
    int b = blockIdx.x / C;
    uint32_t local_base = rank * PTS + (uint32_t)tid * P;
    int gbase = b * Nn + (int)local_base;
    const uint32_t TXB = (rank == 0) ? 20u * C : 16u * C;

    uint32_t mb0 = s2u(&mbarrier_s[0]), mb1 = s2u(&mbarrier_s[1]);
    if (tid == 0) { mbar_init(mb0, 1); mbar_init(mb1, 1); }

    // hoisted remote addresses (warp0 only; rI targets rank 0)
    uint32_t rC4[2], rI[2], rMB[2];
    if (wid == 0 && lane < C) {
#pragma unroll
        for (int q = 0; q < 2; q++) {
            rC4[q] = mapa_u32(s2u(&cand4[q][rank]), (uint32_t)lane);
            rI[q]  = mapa_u32(s2u(&candI[q][rank]), 0u);
            rMB[q] = mapa_u32(q ? mb1 : mb0, (uint32_t)lane);
        }
    }

    float dist[P];
    u64 pxp[P / 2], pyp[P / 2], pzp[P / 2];
    {
        float px[P], py[P], pz[P];
#pragma unroll
        for (int j = 0; j < P; j++) {
            float4 q = g_packed[gbase + j];
            px[j] = q.x; py[j] = q.y; pz[j] = q.z;
            tile[tid * P + j] = q;
        }
#pragma unroll
        for (int p = 0; p < P / 2; p++) {
            pxp[p] = packx2(px[2 * p], px[2 * p + 1]);
            pyp[p] = packx2(py[2 * p], py[2 * p + 1]);
            pzp[p] = packx2(pz[2 * p], pz[2 * p + 1]);
        }
        float4 p0 = g_packed[b * Nn];
#pragma unroll
        for (int j = 0; j < P; j++)
            dist[j] = d2f(px[j], py[j], pz[j], p0.x, p0.y, p0.z);
    }
    float bd = dist[0];
#pragma unroll
    for (int j = 1; j < P; j++) bd = fmaxf(bd, dist[j]);
    if (rank == 0 && tid == 0) g_sidx[b * NGn + 0] = b * Nn;

    __syncthreads();
    cluster_sync_asm();   // mbarriers + tiles ready before any st.async

    for (int k = 1; k < NGn; k++) {
        int kb = k & 1;
        uint32_t parity = (uint32_t)(((k - 1) >> 1) & 1);
        uint32_t mbk = kb ? mb1 : mb0;
        if (tid == 0) mbar_expect_tx(mbk, TXB);

        // smallest j with dist[j] == bd (jnp.argmax tie-break)
        int bj = P - 1;
#pragma unroll
        for (int j = P - 2; j >= 0; j--) bj = (dist[j] == bd) ? j : bj;
        uint32_t myinv = 0xFFFFFFFFu - (local_base + (uint32_t)bj);

        // warp argmax: redux(d2) then redux(~idx among tied)
        uint32_t dbits = __float_as_uint(bd);
        uint32_t wmax  = __reduce_max_sync(FULL, dbits);
        uint32_t inv   = (dbits == wmax) ? myinv : 0u;
        uint32_t winv  = __reduce_max_sync(FULL, inv);
        if (lane == 0) slotK[wid] = ((u64)wmax << 32) | winv;
        __syncthreads();

        if (wid == 0) {
            u64 k0 = slotK[lane & (NW - 1)];
            uint32_t hi = (lane < NW) ? (uint32_t)(k0 >> 32) : 0u;
            uint32_t hm = __reduce_max_sync(FULL, hi);
            uint32_t lo = (hi == hm) ? (uint32_t)k0 : 0u;
            uint32_t lm = __reduce_max_sync(FULL, lo);
            uint32_t ci = 0xFFFFFFFFu - lm;         // batch-local winner idx
            float4 w = tile[ci & (PTS - 1)];        // broadcast LDS.128
            if (lane < C) {
                st_async_u64(rC4[kb],
                             ((u64)__float_as_uint(w.x) << 32) | hm, rMB[kb]);
                st_async_u64(rC4[kb] + 8,
                             ((u64)__float_as_uint(w.z) << 32)
                             | __float_as_uint(w.y), rMB[kb]);
            }
            if (lane == 0) st_async_u32(rI[kb], ci, rMB[kb]);
        }

        mbar_wait_parity(mbk, parity);

        // cluster pick: lane r holds candidate of CTA r via one LDS.128;
        // winner candidate re-read with a broadcast LDS.128 (no shfl chain)
        int cl = lane & (C - 1);
        float4 cv = cand4[kb][cl];     // {d2, x, y, z}
        uint32_t d = (lane < C) ? __float_as_uint(cv.x) : 0u;
        uint32_t m = __reduce_max_sync(FULL, d);
        int src = __ffs(__ballot_sync(FULL, d == m)) - 1;  // smallest rank==idx
        float4 wv = cand4[kb][src];    // broadcast (N=1) LDS.128
        if (rank == 0 && tid == 0)
            g_sidx[b * NGn + k] = b * Nn + (int)candI[kb][src];

        // packed-f32x2 dist update (pre-negated winner), scalar min/max
        u64 ngx = packx2(-wv.y, -wv.y);
        u64 ngy = packx2(-wv.z, -wv.z);
        u64 ngz = packx2(-wv.w, -wv.w);
        bd = -1.f;
#pragma unroll
        for (int p = 0; p < P / 2; p++) {
            u64 dx = addx2(pxp[p], ngx);
            u64 dy = addx2(pyp[p], ngy);
            u64 dz = addx2(pzp[p], ngz);
            u64 s = addx2(addx2(mulx2(dx, dx), mulx2(dy, dy)), mulx2(dz, dz));
            float s0, s1; unpackx2(s0, s1, s);
            float m0 = fminf(dist[2 * p], s0);
            float m1 = fminf(dist[2 * p + 1], s1);
            dist[2 * p] = m0; dist[2 * p + 1] = m1;
            bd = fmaxf(bd, m0); bd = fmaxf(bd, m1);
        }
    }
}

// ---------------------------------------------------------------------------
// FPS fallback (cluster 8 x 1024, P=4) — only if cluster size 16 is rejected.
// ---------------------------------------------------------------------------
__global__ void __cluster_dims__(8, 1, 1) __launch_bounds__(1024, 1)
fps_kernel8() {
    constexpr int C = 8, T = 1024, P = 4;
    constexpr int NW = T / 32;
    constexpr int PTS = T * P;
    constexpr uint32_t TXB = 20u * C;

    __shared__ uint32_t slotD[NW], slotI[NW];
    __shared__ float    slotX[NW], slotY[NW], slotZ[NW];
    __shared__ u64      candDI[2][C];
    __shared__ u64      candXY[2][C];
    __shared__ uint32_t candZ[2][C];
    __shared__ u64      mbarrier_s[2];

    const unsigned FULL = 0xffffffffu;
    int tid = threadIdx.x, lane = tid & 31, wid = tid >> 5;
    uint32_t rank = ctarank();
    int b = blockIdx.x / C;
    uint32_t local_base = rank * PTS + (uint32_t)tid * P;
    int gbase = b * Nn + (int)local_base;

    uint32_t mb0 = s2u(&mbarrier_s[0]), mb1 = s2u(&mbarrier_s[1]);
    if (tid == 0) { mbar_init(mb0, 1); mbar_init(mb1, 1); }

    uint32_t rDI[2], rXY[2], rZ[2], rMB[2];
    if (wid == 0 && lane < C) {
#pragma unroll
        for (int q = 0; q < 2; q++) {
            rDI[q] = mapa_u32(s2u(&candDI[q][rank]), (uint32_t)lane);
            rXY[q] = mapa_u32(s2u(&candXY[q][rank]), (uint32_t)lane);
            rZ[q]  = mapa_u32(s2u(&candZ[q][rank]),  (uint32_t)lane);
            rMB[q] = mapa_u32(q ? mb1 : mb0, (uint32_t)lane);
        }
    }

    float px[P], py[P], pz[P], dist[P];
#pragma unroll
    for (int j = 0; j < P; j++) {
        float4 q = g_packed[gbase + j];
        px[j] = q.x; py[j] = q.y; pz[j] = q.z;
    }

    float4 p0 = g_packed[b * Nn];
    float bd = -1.f; int bj = 0;
#pragma unroll
    for (int j = 0; j < P; j++) {
        float d = d2f(px[j], py[j], pz[j], p0.x, p0.y, p0.z);
        dist[j] = d;
        if (d > bd) { bd = d; bj = j; }
    }
    if (rank == 0 && tid == 0) g_sidx[b * NGn + 0] = b * Nn;

    __syncthreads();
    cluster_sync_asm();

    for (int k = 1; k < NGn; k++) {
        int kb = k & 1;
        uint32_t parity = (uint32_t)(((k - 1) >> 1) & 1);
        uint32_t mbk = kb ? mb1 : mb0;
        if (tid == 0) mbar_expect_tx(mbk, TXB);

        float cx, cy, cz;
        {
            int j = bj;
            float x01 = (j & 1) ? px[1] : px[0], x23 = (j & 1) ? px[3] : px[2];
            float y01 = (j & 1) ? py[1] : py[0], y23 = (j & 1) ? py[3] : py[2];
            float z01 = (j & 1) ? pz[1] : pz[0], z23 = (j & 1) ? pz[3] : pz[2];
            cx = (j & 2) ? x23 : x01; cy = (j & 2) ? y23 : y01; cz = (j & 2) ? z23 : z01;
        }
        uint32_t myidx = local_base + (uint32_t)bj;

        uint32_t dbits = __float_as_uint(bd);
        uint32_t wmax  = __reduce_max_sync(FULL, dbits);
        int wsrc = __ffs(__ballot_sync(FULL, dbits == wmax)) - 1;
        uint32_t widx = __shfl_sync(FULL, myidx, wsrc);
        float wx = __shfl_sync(FULL, cx, wsrc);
        float wy = __shfl_sync(FULL, cy, wsrc);
        float wz = __shfl_sync(FULL, cz, wsrc);
        if (lane == 0) {
            slotD[wid] = wmax; slotI[wid] = widx;
            slotX[wid] = wx; slotY[wid] = wy; slotZ[wid] = wz;
        }
        __syncthreads();

        if (wid == 0) {
            int sl = lane & (NW - 1);
            uint32_t d = (lane < NW) ? slotD[sl] : 0u;
            uint32_t i = slotI[sl];
            float x = slotX[sl], y = slotY[sl], z = slotZ[sl];
            uint32_t m = __reduce_max_sync(FULL, d);
            int src = __ffs(__ballot_sync(FULL, d == m)) - 1;
            uint32_t ci = __shfl_sync(FULL, i, src);
            float fx = __shfl_sync(FULL, x, src);
            float fy = __shfl_sync(FULL, y, src);
            float fz = __shfl_sync(FULL, z, src);
            if (lane < C) {
                st_async_u64(rDI[kb], ((u64)m << 32) | ci, rMB[kb]);
                st_async_u64(rXY[kb],
                             ((u64)__float_as_uint(fy) << 32) | __float_as_uint(fx),
                             rMB[kb]);
                st_async_u32(rZ[kb], __float_as_uint(fz), rMB[kb]);
            }
        }

        mbar_wait_parity(mbk, parity);

        int cl = lane & (C - 1);
        u64 di = candDI[kb][cl];
        u64 xy = candXY[kb][cl];
        uint32_t zz = candZ[kb][cl];
        uint32_t d = (lane < C) ? (uint32_t)(di >> 32) : 0u;
        uint32_t m = __reduce_max_sync(FULL, d);
        int src = __ffs(__ballot_sync(FULL, d == m)) - 1;
        uint32_t wl = __shfl_sync(FULL, (uint32_t)di, src);
        u64 wxy = __shfl_sync(FULL, xy, src);
        uint32_t wzb = __shfl_sync(FULL, zz, src);
        float gx = __uint_as_float((uint32_t)wxy);
        float gy = __uint_as_float((uint32_t)(wxy >> 32));
        float gz = __uint_as_float(wzb);
        if (rank == 0 && tid == 0) g_sidx[b * NGn + k] = b * Nn + (int)wl;

        bd = -1.f; bj = 0;
#pragma unroll
        for (int j = 0; j < P; j++) {
            float nd = d2f(px[j], py[j], pz[j], gx, gy, gz);
            float mn = fminf(dist[j], nd);
            dist[j] = mn;
            if (mn > bd) { bd = mn; bj = j; }
        }
    }
}

// ---------------------------------------------------------------------------
// Kernel 3: kNN (top-32 by (d2, idx) lex order) + angle/curvature + outputs.
// Pair-SoA scan: 3 LDS.64 + 8 packed-f32x2 ops per 64 points (bit-exact);
// neighbor gi computed from ballot src (no shfl). Kept set is insertion-
// order independent (replace-lex-max). cp.async double-buffered 24KB tiles.
// ---------------------------------------------------------------------------
__global__ void __launch_bounds__(512, 1)
knn_kernel(const float* __restrict__ coord, const float* __restrict__ feat,
           const int* __restrict__ labels, float* __restrict__ out) {
    __shared__ u64 scx[2][KCHUNK / 2];
    __shared__ u64 scy[2][KCHUNK / 2];
    __shared__ u64 scz[2][KCHUNK / 2];
    const unsigned FULL = 0xffffffffu;
    int tid = threadIdx.x, lane = tid & 31, wid = tid >> 5;
    int s = blockIdx.x * 16 + wid;   // sample id [0, 8192)
    int b = s >> 10;                 // batch
    int si = g_sidx[s];
    float4 sp = g_packed[si];
    u64 nspx = packx2(-sp.x, -sp.x);
    u64 nspy = packx2(-sp.y, -sp.y);
    u64 nspz = packx2(-sp.z, -sp.z);

    float kd = 3.4028235e38f; unsigned ki = 0xffffffffu;    // kept (per lane)
    float tmd = 3.4028235e38f; unsigned tmi = 0xffffffffu; int tml = 0;

    constexpr int NT = Nn / KCHUNK;      // 16 tiles
    int pbase = b * (Nn / 2);
    auto stage = [&](int buf, int c) {
        int po = pbase + c * (KCHUNK / 2) + tid * 2;
        cp_async16(s2u(&scx[buf][tid * 2]), &g_px[po]);
        cp_async16(s2u(&scy[buf][tid * 2]), &g_py[po]);
        cp_async16(s2u(&scz[buf][tid * 2]), &g_pz[po]);
        cp_commit();
    };
    stage(0, 0);
    for (int c = 0; c < NT; c++) {
        int buf = c & 1;
        if (c + 1 < NT) { stage(buf ^ 1, c + 1); cp_wait<1>(); }
        else           { cp_wait<0>(); }
        __syncthreads();
        int cbase = b * Nn + c * KCHUNK;
        for (int j = 0; j < KCHUNK / 64; j++) {
            int pi = j * 32 + lane;
            u64 dx = addx2(scx[buf][pi], nspx);
            u64 dy = addx2(scy[buf][pi], nspy);
            u64 dz = addx2(scz[buf][pi], nspz);
            u64 ss = addx2(addx2(mulx2(dx, dx), mulx2(dy, dy)), mulx2(dz, dz));
            float d2A, d2B; unpackx2(d2A, d2B, ss);
            int gb = cbase + j * 64;
            unsigned giA = (unsigned)(gb + 2 * lane);
            unsigned giB = giA + 1;
            unsigned mA = __ballot_sync(FULL, (d2A < tmd) || (d2A == tmd && giA < tmi));
            unsigned mB = __ballot_sync(FULL, (d2B < tmd) || (d2B == tmd && giB < tmi));
            while (mA) {
                int ins = __ffs(mA) - 1; mA &= mA - 1;
                float cd = __shfl_sync(FULL, d2A, ins);
                unsigned cgi = (unsigned)(gb + 2 * ins);
                if ((cd < tmd) || (cd == tmd && cgi < tmi)) {
                    if (lane == tml) { kd = cd; ki = cgi; }
                    unsigned db = __float_as_uint(kd);
                    unsigned m  = __reduce_max_sync(FULL, db);
                    bool tie    = (db == m);
                    unsigned mi2 = __reduce_max_sync(FULL, tie ? ki : 0u);
                    tml = __ffs(__ballot_sync(FULL, tie && ki == mi2)) - 1;
                    tmd = __uint_as_float(m); tmi = mi2;
                }
            }
            while (mB) {
                int ins = __ffs(mB) - 1; mB &= mB - 1;
                float cd = __shfl_sync(FULL, d2B, ins);
                unsigned cgi = (unsigned)(gb + 2 * ins + 1);
                if ((cd < tmd) || (cd == tmd && cgi < tmi)) {
                    if (lane == tml) { kd = cd; ki = cgi; }
                    unsigned db = __float_as_uint(kd);
                    unsigned m  = __reduce_max_sync(FULL, db);
                    bool tie    = (db == m);
                    unsigned mi2 = __reduce_max_sync(FULL, tie ? ki : 0u);
                    tml = __ffs(__ballot_sync(FULL, tie && ki == mi2)) - 1;
                    tmd = __uint_as_float(m); tmi = mi2;
                }
            }
        }
        __syncthreads();   // scan done before next overwrite of buf
    }

    // ---- angles: angle = 2*atan2(sqrt(t - a.b), sqrt(t + a.b)), t=|a||b| ----
    float a_own = feat[(size_t)si * FDn + lane];
    float dot = 0.f, an2 = 0.f, bn2 = 0.f;
    const float4* frow = (const float4*)(feat + (size_t)ki * FDn);
#pragma unroll
    for (int g = 0; g < FDn / 4; g++) {
        float4 bv = frow[g];
        float a0 = __shfl_sync(FULL, a_own, g * 4 + 0);
        float a1 = __shfl_sync(FULL, a_own, g * 4 + 1);
        float a2 = __shfl_sync(FULL, a_own, g * 4 + 2);
        float a3 = __shfl_sync(FULL, a_own, g * 4 + 3);
        dot = fmaf(a0, bv.x, dot); an2 = fmaf(a0, a0, an2); bn2 = fmaf(bv.x, bv.x, bn2);
        dot = fmaf(a1, bv.y, dot); an2 = fmaf(a1, a1, an2); bn2 = fmaf(bv.y, bv.y, bn2);
        dot = fmaf(a2, bv.z, dot); an2 = fmaf(a2, a2, an2); bn2 = fmaf(bv.z, bv.z, bn2);
        dot = fmaf(a3, bv.w, dot); an2 = fmaf(a3, a3, an2); bn2 = fmaf(bv.w, bv.w, bn2);
    }
    float t = sqrtf(an2) * sqrtf(bn2);
    float ang = 2.f * atan2f(sqrtf(fmaxf(t - dot, 0.f)), sqrtf(fmaxf(t + dot, 0.f)));
    if (ki == (unsigned)si) ang = 0.f;   // self neighbor contributes 0
    float ssum = ang;
#pragma unroll
    for (int o = 16; o; o >>= 1) ssum += __shfl_xor_sync(FULL, ssum, o);
    float pc = ssum / 31.f;

    // ---- outputs (tuple flattened+concatenated as float32) ----
    const int OFF_FEAT = Bn * NGn * 3;
    const int OFF_SW   = OFF_FEAT + Bn * NGn * (FDn + 1);
    const int OFF_LAB  = OFF_SW + Bn * NGn;
    const int OFF_SIDX = OFF_LAB + Bn * NGn;
    if (lane < 3) out[s * 3 + lane] = coord[si * 3 + lane];
    out[OFF_FEAT + s * 33 + lane] = a_own;
    if (lane == 0) {
        out[OFF_FEAT + s * 33 + 32] = pc;
        out[OFF_SW + s]   = pc > 0.087266f ? 1.f : 0.f;
        out[OFF_LAB + s]  = (float)labels[si];
        out[OFF_SIDX + s] = (float)si;
    }
}

// ---------------------------------------------------------------------------
extern "C" void kernel_launch(void* const* d_in, const int* in_sizes, int n_in,
                              void* d_out, int out_size) {
    const float* coord  = (const float*)d_in[0];
    const float* feat   = (const float*)d_in[1];
    const int*   labels = (const int*)d_in[2];
    float* out = (float*)d_out;

    pack_kernel<<<(Bn * Nn / 4 + 255) / 256, 256>>>(coord);

    cudaError_t rc = cudaFuncSetAttribute(
        (const void*)fps_kernel16,
        cudaFuncAttributeNonPortableClusterSizeAllowed, 1);
    if (rc == cudaSuccess) {
        fps_kernel16<<<Bn * 16, 256>>>();
    } else {
        (void)cudaGetLastError();
        fps_kernel8<<<Bn * 8, 1024>>>();
    }

    knn_kernel<<<(Bn * NGn) / 16, 512>>>(coord, feat, labels, out);
}

// round 11
// speedup vs baseline: 1.2848x; 1.0356x over previous
#include <cuda_runtime.h>
#include <cstdint>

#define Bn   8
#define Nn   32768
#define FDn  32
#define NGn  1024
#define KCHUNK 2048   // kNN tile (points) per buffer

typedef unsigned long long u64;

// Scratch (no allocations allowed)
__device__ float4 g_packed[Bn * Nn];        // 4 MB, {x,y,z,0} per point
__device__ u64    g_px[Bn * Nn / 2];        // pair-SoA: {x[2i], x[2i+1]}
__device__ u64    g_py[Bn * Nn / 2];
__device__ u64    g_pz[Bn * Nn / 2];
__device__ int    g_sidx[Bn * NGn];         // FPS-selected global point idx

// Exact (non-FMA, left-to-right) squared distance == XLA sum((a-b)**2) f32.
__device__ __forceinline__ float d2f(float ax, float ay, float az,
                                     float bx, float by, float bz) {
    float dx = ax - bx, dy = ay - by, dz = az - bz;
    return __fadd_rn(__fadd_rn(__fmul_rn(dx, dx), __fmul_rn(dy, dy)),
                     __fmul_rn(dz, dz));
}

// ---------------------------------------------------------------------------
// small PTX helpers
// ---------------------------------------------------------------------------
__device__ __forceinline__ uint32_t s2u(const void* p) {
    return (uint32_t)__cvta_generic_to_shared(p);
}
__device__ __forceinline__ uint32_t ctarank() {
    uint32_t r; asm("mov.u32 %0, %%cluster_ctarank;" : "=r"(r)); return r;
}
__device__ __forceinline__ uint32_t mapa_u32(uint32_t addr, uint32_t rank) {
    uint32_t r;
    asm("mapa.shared::cluster.u32 %0, %1, %2;" : "=r"(r) : "r"(addr), "r"(rank));
    return r;
}
__device__ __forceinline__ void st_async_u64(uint32_t raddr, u64 v, uint32_t rmbar) {
    asm volatile("st.async.shared::cluster.mbarrier::complete_tx::bytes.u64 [%0], %1, [%2];"
                 :: "r"(raddr), "l"(v), "r"(rmbar) : "memory");
}
__device__ __forceinline__ void st_async_u32(uint32_t raddr, uint32_t v, uint32_t rmbar) {
    asm volatile("st.async.shared::cluster.mbarrier::complete_tx::bytes.u32 [%0], %1, [%2];"
                 :: "r"(raddr), "r"(v), "r"(rmbar) : "memory");
}
__device__ __forceinline__ void mbar_init(uint32_t addr, uint32_t cnt) {
    asm volatile("mbarrier.init.shared.b64 [%0], %1;" :: "r"(addr), "r"(cnt) : "memory");
}
__device__ __forceinline__ void mbar_expect_tx(uint32_t addr, uint32_t bytes) {
    asm volatile("mbarrier.arrive.expect_tx.shared.b64 _, [%0], %1;"
                 :: "r"(addr), "r"(bytes) : "memory");
}
__device__ __forceinline__ void mbar_wait_parity(uint32_t addr, uint32_t parity) {
    uint32_t done;
    asm volatile("{\n\t.reg .pred p;\n\t"
                 "mbarrier.try_wait.parity.acquire.cta.shared::cta.b64 p, [%1], %2;\n\t"
                 "selp.b32 %0, 1, 0, p;\n\t}"
                 : "=r"(done) : "r"(addr), "r"(parity) : "memory");
    while (!done) {
        asm volatile("{\n\t.reg .pred p;\n\t"
                     "mbarrier.try_wait.parity.acquire.cta.shared::cta.b64 p, [%1], %2, 0x989680;\n\t"
                     "selp.b32 %0, 1, 0, p;\n\t}"
                     : "=r"(done) : "r"(addr), "r"(parity) : "memory");
    }
}
__device__ __forceinline__ void cluster_sync_asm() {
    asm volatile("barrier.cluster.arrive.aligned;" ::: "memory");
    asm volatile("barrier.cluster.wait.aligned;" ::: "memory");
}
__device__ __forceinline__ void cp_async16(uint32_t saddr, const void* gaddr) {
    asm volatile("cp.async.cg.shared.global [%0], [%1], 16;"
                 :: "r"(saddr), "l"(gaddr) : "memory");
}
__device__ __forceinline__ void cp_commit() {
    asm volatile("cp.async.commit_group;" ::: "memory");
}
template<int N>
__device__ __forceinline__ void cp_wait() {
    asm volatile("cp.async.wait_group %0;" :: "n"(N) : "memory");
}
// packed f32x2 (sm_103a): add/mul only — IEEE-rn per lane, bit-exact vs scalar
__device__ __forceinline__ u64 addx2(u64 a, u64 b) {
    u64 r; asm("add.rn.f32x2 %0, %1, %2;" : "=l"(r) : "l"(a), "l"(b)); return r;
}
__device__ __forceinline__ u64 mulx2(u64 a, u64 b) {
    u64 r; asm("mul.rn.f32x2 %0, %1, %2;" : "=l"(r) : "l"(a), "l"(b)); return r;
}
__device__ __forceinline__ u64 packx2(float lo, float hi) {
    u64 r; asm("mov.b64 %0, {%1, %2};" : "=l"(r) : "f"(lo), "f"(hi)); return r;
}
__device__ __forceinline__ void unpackx2(float& lo, float& hi, u64 v) {
    asm("mov.b64 {%0, %1}, %2;" : "=f"(lo), "=f"(hi) : "l"(v));
}

// ---------------------------------------------------------------------------
// Kernel 1: pack coords [N,3] AoS -> float4 AND pair-SoA u64 arrays
// ---------------------------------------------------------------------------
__global__ void pack_kernel(const float* __restrict__ coord) {
    int t = blockIdx.x * blockDim.x + threadIdx.x;   // points 4t..4t+3
    if (t * 4 >= Bn * Nn) return;
    const float4* c4 = (const float4*)(coord + (size_t)t * 12);
    float4 a = c4[0], b = c4[1], c = c4[2];
    g_packed[t * 4 + 0] = make_float4(a.x, a.y, a.z, 0.f);
    g_packed[t * 4 + 1] = make_float4(a.w, b.x, b.y, 0.f);
    g_packed[t * 4 + 2] = make_float4(b.z, b.w, c.x, 0.f);
    g_packed[t * 4 + 3] = make_float4(c.y, c.z, c.w, 0.f);
    g_px[2 * t]     = packx2(a.x, a.w);
    g_px[2 * t + 1] = packx2(b.z, c.y);
    g_py[2 * t]     = packx2(a.y, b.x);
    g_py[2 * t + 1] = packx2(b.w, c.z);
    g_pz[2 * t]     = packx2(a.z, b.y);
    g_pz[2 * t + 1] = packx2(c.x, c.w);
}

// ---------------------------------------------------------------------------
// FPS: EXACT R7 design (proven 771us). Cluster of 16 CTAs x 256 thr x 8
// pts/thread per batch. redux-only argmax at every level (jnp.argmax
// smallest-index tie-break preserved: lane/slot/rank order == index order).
// One candidate {d2,x,y,z} per CTA exchanged via st.async + mbarrier; winner
// index to rank 0 only. Winner coords broadcast from smem tile at the send
// stage; pick stage broadcasts via 3-shfl chain (LDS-pick regressed in R10).
// ---------------------------------------------------------------------------
__global__ void __cluster_dims__(16, 1, 1) __launch_bounds__(256, 1)
fps_kernel16() {
    constexpr int C = 16, T = 256, P = 8;
    constexpr int NW = T / 32;            // 8 warps
    constexpr int PTS = T * P;            // 2048 points per CTA

    __shared__ __align__(16) float4 tile[PTS];          // 32KB coord tile
    __shared__ u64 slotK[NW];                            // {d2bits, ~idx}
    __shared__ __align__(16) float4 cand4[2][C];         // {d2, x, y, z}
    __shared__ uint32_t candI[2][C];                     // idx (rank0 only)
    __shared__ u64 mbarrier_s[2];

    const unsigned FULL = 0xffffffffu;
    int tid = threadIdx.x, lane = tid & 31, wid = tid >> 5;
    uint32_t rank = ctarank();
    int b = blockIdx.x / C;
    uint32_t local_base = rank * PTS + (uint32_t)tid * P;
    int gbase = b * Nn + (int)local_base;
    const uint32_t TXB = (rank == 0) ? 20u * C : 16u * C;

    uint32_t mb0 = s2u(&mbarrier_s[0]), mb1 = s2u(&mbarrier_s[1]);
    if (tid == 0) { mbar_init(mb0, 1); mbar_init(mb1, 1); }

    // hoisted remote addresses (warp0 only; rI targets rank 0)
    uint32_t rC4[2], rI[2], rMB[2];
    if (wid == 0 && lane < C) {
#pragma unroll
        for (int q = 0; q < 2; q++) {
            rC4[q] = mapa_u32(s2u(&cand4[q][rank]), (uint32_t)lane);
            rI[q]  = mapa_u32(s2u(&candI[q][rank]), 0u);
            rMB[q] = mapa_u32(q ? mb1 : mb0, (uint32_t)lane);
        }
    }

    float dist[P];
    u64 pxp[P / 2], pyp[P / 2], pzp[P / 2];
    {
        float px[P], py[P], pz[P];
#pragma unroll
        for (int j = 0; j < P; j++) {
            float4 q = g_packed[gbase + j];
            px[j] = q.x; py[j] = q.y; pz[j] = q.z;
            tile[tid * P + j] = q;
        }
#pragma unroll
        for (int p = 0; p < P / 2; p++) {
            pxp[p] = packx2(px[2 * p], px[2 * p + 1]);
            pyp[p] = packx2(py[2 * p], py[2 * p + 1]);
            pzp[p] = packx2(pz[2 * p], pz[2 * p + 1]);
        }
        float4 p0 = g_packed[b * Nn];
#pragma unroll
        for (int j = 0; j < P; j++)
            dist[j] = d2f(px[j], py[j], pz[j], p0.x, p0.y, p0.z);
    }
    float bd = dist[0];
#pragma unroll
    for (int j = 1; j < P; j++) bd = fmaxf(bd, dist[j]);
    if (rank == 0 && tid == 0) g_sidx[b * NGn + 0] = b * Nn;

    __syncthreads();
    cluster_sync_asm();   // mbarriers + tiles ready before any st.async

    for (int k = 1; k < NGn; k++) {
        int kb = k & 1;
        uint32_t parity = (uint32_t)(((k - 1) >> 1) & 1);
        uint32_t mbk = kb ? mb1 : mb0;
        if (tid == 0) mbar_expect_tx(mbk, TXB);

        // smallest j with dist[j] == bd (jnp.argmax tie-break)
        int bj = P - 1;
#pragma unroll
        for (int j = P - 2; j >= 0; j--) bj = (dist[j] == bd) ? j : bj;
        uint32_t myinv = 0xFFFFFFFFu - (local_base + (uint32_t)bj);

        // warp argmax: redux(d2) then redux(~idx among tied)
        uint32_t dbits = __float_as_uint(bd);
        uint32_t wmax  = __reduce_max_sync(FULL, dbits);
        uint32_t inv   = (dbits == wmax) ? myinv : 0u;
        uint32_t winv  = __reduce_max_sync(FULL, inv);
        if (lane == 0) slotK[wid] = ((u64)wmax << 32) | winv;
        __syncthreads();

        if (wid == 0) {
            u64 k0 = slotK[lane & (NW - 1)];
            uint32_t hi = (lane < NW) ? (uint32_t)(k0 >> 32) : 0u;
            uint32_t hm = __reduce_max_sync(FULL, hi);
            uint32_t lo = (hi == hm) ? (uint32_t)k0 : 0u;
            uint32_t lm = __reduce_max_sync(FULL, lo);
            uint32_t ci = 0xFFFFFFFFu - lm;         // batch-local winner idx
            float4 w = tile[ci & (PTS - 1)];        // broadcast LDS.128
            if (lane < C) {
                st_async_u64(rC4[kb],
                             ((u64)__float_as_uint(w.x) << 32) | hm, rMB[kb]);
                st_async_u64(rC4[kb] + 8,
                             ((u64)__float_as_uint(w.z) << 32)
                             | __float_as_uint(w.y), rMB[kb]);
            }
            if (lane == 0) st_async_u32(rI[kb], ci, rMB[kb]);
        }

        mbar_wait_parity(mbk, parity);

        // cluster pick: lane r holds candidate of CTA r (one LDS.128);
        // winner broadcast via 3-shfl chain (R7-proven form)
        int cl = lane & (C - 1);
        float4 cv = cand4[kb][cl];     // {d2, x, y, z}
        uint32_t d = (lane < C) ? __float_as_uint(cv.x) : 0u;
        uint32_t m = __reduce_max_sync(FULL, d);
        int src = __ffs(__ballot_sync(FULL, d == m)) - 1;  // smallest rank==idx
        float gx = __shfl_sync(FULL, cv.y, src);
        float gy = __shfl_sync(FULL, cv.z, src);
        float gz = __shfl_sync(FULL, cv.w, src);
        if (rank == 0 && tid == 0)
            g_sidx[b * NGn + k] = b * Nn + (int)candI[kb][src];

        // packed-f32x2 dist update (pre-negated winner), scalar min/max
        u64 ngx = packx2(-gx, -gx);
        u64 ngy = packx2(-gy, -gy);
        u64 ngz = packx2(-gz, -gz);
        bd = -1.f;
#pragma unroll
        for (int p = 0; p < P / 2; p++) {
            u64 dx = addx2(pxp[p], ngx);
            u64 dy = addx2(pyp[p], ngy);
            u64 dz = addx2(pzp[p], ngz);
            u64 s = addx2(addx2(mulx2(dx, dx), mulx2(dy, dy)), mulx2(dz, dz));
            float s0, s1; unpackx2(s0, s1, s);
            float m0 = fminf(dist[2 * p], s0);
            float m1 = fminf(dist[2 * p + 1], s1);
            dist[2 * p] = m0; dist[2 * p + 1] = m1;
            bd = fmaxf(bd, m0); bd = fmaxf(bd, m1);
        }
    }
}

// ---------------------------------------------------------------------------
// FPS fallback (cluster 8 x 1024, P=4) — only if cluster size 16 is rejected.
// ---------------------------------------------------------------------------
__global__ void __cluster_dims__(8, 1, 1) __launch_bounds__(1024, 1)
fps_kernel8() {
    constexpr int C = 8, T = 1024, P = 4;
    constexpr int NW = T / 32;
    constexpr int PTS = T * P;
    constexpr uint32_t TXB = 20u * C;

    __shared__ uint32_t slotD[NW], slotI[NW];
    __shared__ float    slotX[NW], slotY[NW], slotZ[NW];
    __shared__ u64      candDI[2][C];
    __shared__ u64      candXY[2][C];
    __shared__ uint32_t candZ[2][C];
    __shared__ u64      mbarrier_s[2];

    const unsigned FULL = 0xffffffffu;
    int tid = threadIdx.x, lane = tid & 31, wid = tid >> 5;
    uint32_t rank = ctarank();
    int b = blockIdx.x / C;
    uint32_t local_base = rank * PTS + (uint32_t)tid * P;
    int gbase = b * Nn + (int)local_base;

    uint32_t mb0 = s2u(&mbarrier_s[0]), mb1 = s2u(&mbarrier_s[1]);
    if (tid == 0) { mbar_init(mb0, 1); mbar_init(mb1, 1); }

    uint32_t rDI[2], rXY[2], rZ[2], rMB[2];
    if (wid == 0 && lane < C) {
#pragma unroll
        for (int q = 0; q < 2; q++) {
            rDI[q] = mapa_u32(s2u(&candDI[q][rank]), (uint32_t)lane);
            rXY[q] = mapa_u32(s2u(&candXY[q][rank]), (uint32_t)lane);
            rZ[q]  = mapa_u32(s2u(&candZ[q][rank]),  (uint32_t)lane);
            rMB[q] = mapa_u32(q ? mb1 : mb0, (uint32_t)lane);
        }
    }

    float px[P], py[P], pz[P], dist[P];
#pragma unroll
    for (int j = 0; j < P; j++) {
        float4 q = g_packed[gbase + j];
        px[j] = q.x; py[j] = q.y; pz[j] = q.z;
    }

    float4 p0 = g_packed[b * Nn];
    float bd = -1.f; int bj = 0;
#pragma unroll
    for (int j = 0; j < P; j++) {
        float d = d2f(px[j], py[j], pz[j], p0.x, p0.y, p0.z);
        dist[j] = d;
        if (d > bd) { bd = d; bj = j; }
    }
    if (rank == 0 && tid == 0) g_sidx[b * NGn + 0] = b * Nn;

    __syncthreads();
    cluster_sync_asm();

    for (int k = 1; k < NGn; k++) {
        int kb = k & 1;
        uint32_t parity = (uint32_t)(((k - 1) >> 1) & 1);
        uint32_t mbk = kb ? mb1 : mb0;
        if (tid == 0) mbar_expect_tx(mbk, TXB);

        float cx, cy, cz;
        {
            int j = bj;
            float x01 = (j & 1) ? px[1] : px[0], x23 = (j & 1) ? px[3] : px[2];
            float y01 = (j & 1) ? py[1] : py[0], y23 = (j & 1) ? py[3] : py[2];
            float z01 = (j & 1) ? pz[1] : pz[0], z23 = (j & 1) ? pz[3] : pz[2];
            cx = (j & 2) ? x23 : x01; cy = (j & 2) ? y23 : y01; cz = (j & 2) ? z23 : z01;
        }
        uint32_t myidx = local_base + (uint32_t)bj;

        uint32_t dbits = __float_as_uint(bd);
        uint32_t wmax  = __reduce_max_sync(FULL, dbits);
        int wsrc = __ffs(__ballot_sync(FULL, dbits == wmax)) - 1;
        uint32_t widx = __shfl_sync(FULL, myidx, wsrc);
        float wx = __shfl_sync(FULL, cx, wsrc);
        float wy = __shfl_sync(FULL, cy, wsrc);
        float wz = __shfl_sync(FULL, cz, wsrc);
        if (lane == 0) {
            slotD[wid] = wmax; slotI[wid] = widx;
            slotX[wid] = wx; slotY[wid] = wy; slotZ[wid] = wz;
        }
        __syncthreads();

        if (wid == 0) {
            int sl = lane & (NW - 1);
            uint32_t d = (lane < NW) ? slotD[sl] : 0u;
            uint32_t i = slotI[sl];
            float x = slotX[sl], y = slotY[sl], z = slotZ[sl];
            uint32_t m = __reduce_max_sync(FULL, d);
            int src = __ffs(__ballot_sync(FULL, d == m)) - 1;
            uint32_t ci = __shfl_sync(FULL, i, src);
            float fx = __shfl_sync(FULL, x, src);
            float fy = __shfl_sync(FULL, y, src);
            float fz = __shfl_sync(FULL, z, src);
            if (lane < C) {
                st_async_u64(rDI[kb], ((u64)m << 32) | ci, rMB[kb]);
                st_async_u64(rXY[kb],
                             ((u64)__float_as_uint(fy) << 32) | __float_as_uint(fx),
                             rMB[kb]);
                st_async_u32(rZ[kb], __float_as_uint(fz), rMB[kb]);
            }
        }

        mbar_wait_parity(mbk, parity);

        int cl = lane & (C - 1);
        u64 di = candDI[kb][cl];
        u64 xy = candXY[kb][cl];
        uint32_t zz = candZ[kb][cl];
        uint32_t d = (lane < C) ? (uint32_t)(di >> 32) : 0u;
        uint32_t m = __reduce_max_sync(FULL, d);
        int src = __ffs(__ballot_sync(FULL, d == m)) - 1;
        uint32_t wl = __shfl_sync(FULL, (uint32_t)di, src);
        u64 wxy = __shfl_sync(FULL, xy, src);
        uint32_t wzb = __shfl_sync(FULL, zz, src);
        float gx = __uint_as_float((uint32_t)wxy);
        float gy = __uint_as_float((uint32_t)(wxy >> 32));
        float gz = __uint_as_float(wzb);
        if (rank == 0 && tid == 0) g_sidx[b * NGn + k] = b * Nn + (int)wl;

        bd = -1.f; bj = 0;
#pragma unroll
        for (int j = 0; j < P; j++) {
            float nd = d2f(px[j], py[j], pz[j], gx, gy, gz);
            float mn = fminf(dist[j], nd);
            dist[j] = mn;
            if (mn > bd) { bd = mn; bj = j; }
        }
    }
}

// ---------------------------------------------------------------------------
// Kernel 3: kNN (top-32 by (d2, idx) lex order) + angle/curvature + outputs.
// Pair-SoA scan with combined early-skip ballot: most 64-point groups insert
// nothing, so one ballot on (condA||condB) gates the per-half ballots and
// insertion loops (pure control-flow short-circuit; kept set unchanged —
// replace-lex-max is insertion-order independent).
// ---------------------------------------------------------------------------
__global__ void __launch_bounds__(512, 1)
knn_kernel(const float* __restrict__ coord, const float* __restrict__ feat,
           const int* __restrict__ labels, float* __restrict__ out) {
    __shared__ u64 scx[2][KCHUNK / 2];
    __shared__ u64 scy[2][KCHUNK / 2];
    __shared__ u64 scz[2][KCHUNK / 2];
    const unsigned FULL = 0xffffffffu;
    int tid = threadIdx.x, lane = tid & 31, wid = tid >> 5;
    int s = blockIdx.x * 16 + wid;   // sample id [0, 8192)
    int b = s >> 10;                 // batch
    int si = g_sidx[s];
    float4 sp = g_packed[si];
    u64 nspx = packx2(-sp.x, -sp.x);
    u64 nspy = packx2(-sp.y, -sp.y);
    u64 nspz = packx2(-sp.z, -sp.z);

    float kd = 3.4028235e38f; unsigned ki = 0xffffffffu;    // kept (per lane)
    float tmd = 3.4028235e38f; unsigned tmi = 0xffffffffu; int tml = 0;

    constexpr int NT = Nn / KCHUNK;      // 16 tiles
    int pbase = b * (Nn / 2);
    auto stage = [&](int buf, int c) {
        int po = pbase + c * (KCHUNK / 2) + tid * 2;
        cp_async16(s2u(&scx[buf][tid * 2]), &g_px[po]);
        cp_async16(s2u(&scy[buf][tid * 2]), &g_py[po]);
        cp_async16(s2u(&scz[buf][tid * 2]), &g_pz[po]);
        cp_commit();
    };
    stage(0, 0);
    for (int c = 0; c < NT; c++) {
        int buf = c & 1;
        if (c + 1 < NT) { stage(buf ^ 1, c + 1); cp_wait<1>(); }
        else           { cp_wait<0>(); }
        __syncthreads();
        int cbase = b * Nn + c * KCHUNK;
        for (int j = 0; j < KCHUNK / 64; j++) {
            int pi = j * 32 + lane;
            u64 dx = addx2(scx[buf][pi], nspx);
            u64 dy = addx2(scy[buf][pi], nspy);
            u64 dz = addx2(scz[buf][pi], nspz);
            u64 ss = addx2(addx2(mulx2(dx, dx), mulx2(dy, dy)), mulx2(dz, dz));
            float d2A, d2B; unpackx2(d2A, d2B, ss);
            int gb = cbase + j * 64;
            unsigned giA = (unsigned)(gb + 2 * lane);
            unsigned giB = giA + 1;
            bool cA = (d2A < tmd) || (d2A == tmd && giA < tmi);
            bool cB = (d2B < tmd) || (d2B == tmd && giB < tmi);
            if (__ballot_sync(FULL, cA || cB) == 0u) continue;  // common case
            unsigned mA = __ballot_sync(FULL, cA);
            unsigned mB = __ballot_sync(FULL, cB);
            while (mA) {
                int ins = __ffs(mA) - 1; mA &= mA - 1;
                float cd = __shfl_sync(FULL, d2A, ins);
                unsigned cgi = (unsigned)(gb + 2 * ins);
                if ((cd < tmd) || (cd == tmd && cgi < tmi)) {
                    if (lane == tml) { kd = cd; ki = cgi; }
                    unsigned db = __float_as_uint(kd);
                    unsigned m  = __reduce_max_sync(FULL, db);
                    bool tie    = (db == m);
                    unsigned mi2 = __reduce_max_sync(FULL, tie ? ki : 0u);
                    tml = __ffs(__ballot_sync(FULL, tie && ki == mi2)) - 1;
                    tmd = __uint_as_float(m); tmi = mi2;
                }
            }
            while (mB) {
                int ins = __ffs(mB) - 1; mB &= mB - 1;
                float cd = __shfl_sync(FULL, d2B, ins);
                unsigned cgi = (unsigned)(gb + 2 * ins + 1);
                if ((cd < tmd) || (cd == tmd && cgi < tmi)) {
                    if (lane == tml) { kd = cd; ki = cgi; }
                    unsigned db = __float_as_uint(kd);
                    unsigned m  = __reduce_max_sync(FULL, db);
                    bool tie    = (db == m);
                    unsigned mi2 = __reduce_max_sync(FULL, tie ? ki : 0u);
                    tml = __ffs(__ballot_sync(FULL, tie && ki == mi2)) - 1;
                    tmd = __uint_as_float(m); tmi = mi2;
                }
            }
        }
        __syncthreads();   // scan done before next overwrite of buf
    }

    // ---- angles: angle = 2*atan2(sqrt(t - a.b), sqrt(t + a.b)), t=|a||b| ----
    float a_own = feat[(size_t)si * FDn + lane];
    float dot = 0.f, an2 = 0.f, bn2 = 0.f;
    const float4* frow = (const float4*)(feat + (size_t)ki * FDn);
#pragma unroll
    for (int g = 0; g < FDn / 4; g++) {
        float4 bv = frow[g];
        float a0 = __shfl_sync(FULL, a_own, g * 4 + 0);
        float a1 = __shfl_sync(FULL, a_own, g * 4 + 1);
        float a2 = __shfl_sync(FULL, a_own, g * 4 + 2);
        float a3 = __shfl_sync(FULL, a_own, g * 4 + 3);
        dot = fmaf(a0, bv.x, dot); an2 = fmaf(a0, a0, an2); bn2 = fmaf(bv.x, bv.x, bn2);
        dot = fmaf(a1, bv.y, dot); an2 = fmaf(a1, a1, an2); bn2 = fmaf(bv.y, bv.y, bn2);
        dot = fmaf(a2, bv.z, dot); an2 = fmaf(a2, a2, an2); bn2 = fmaf(bv.z, bv.z, bn2);
        dot = fmaf(a3, bv.w, dot); an2 = fmaf(a3, a3, an2); bn2 = fmaf(bv.w, bv.w, bn2);
    }
    float t = sqrtf(an2) * sqrtf(bn2);
    float ang = 2.f * atan2f(sqrtf(fmaxf(t - dot, 0.f)), sqrtf(fmaxf(t + dot, 0.f)));
    if (ki == (unsigned)si) ang = 0.f;   // self neighbor contributes 0
    float ssum = ang;
#pragma unroll
    for (int o = 16; o; o >>= 1) ssum += __shfl_xor_sync(FULL, ssum, o);
    float pc = ssum / 31.f;

    // ---- outputs (tuple flattened+concatenated as float32) ----
    const int OFF_FEAT = Bn * NGn * 3;
    const int OFF_SW   = OFF_FEAT + Bn * NGn * (FDn + 1);
    const int OFF_LAB  = OFF_SW + Bn * NGn;
    const int OFF_SIDX = OFF_LAB + Bn * NGn;
    if (lane < 3) out[s * 3 + lane] = coord[si * 3 + lane];
    out[OFF_FEAT + s * 33 + lane] = a_own;
    if (lane == 0) {
        out[OFF_FEAT + s * 33 + 32] = pc;
        out[OFF_SW + s]   = pc > 0.087266f ? 1.f : 0.f;
        out[OFF_LAB + s]  = (float)labels[si];
        out[OFF_SIDX + s] = (float)si;
    }
}

// ---------------------------------------------------------------------------
extern "C" void kernel_launch(void* const* d_in, const int* in_sizes, int n_in,
                              void* d_out, int out_size) {
    const float* coord  = (const float*)d_in[0];
    const float* feat   = (const float*)d_in[1];
    const int*   labels = (const int*)d_in[2];
    float* out = (float*)d_out;

    pack_kernel<<<(Bn * Nn / 4 + 255) / 256, 256>>>(coord);

    cudaError_t rc = cudaFuncSetAttribute(
        (const void*)fps_kernel16,
        cudaFuncAttributeNonPortableClusterSizeAllowed, 1);
    if (rc == cudaSuccess) {
        fps_kernel16<<<Bn * 16, 256>>>();
    } else {
        (void)cudaGetLastError();
        fps_kernel8<<<Bn * 8, 1024>>>();
    }

    knn_kernel<<<(Bn * NGn) / 16, 512>>>(coord, feat, labels, out);
}

// round 12
// speedup vs baseline: 1.3576x; 1.0567x over previous
#include <cuda_runtime.h>
#include <cstdint>

#define Bn   8
#define Nn   32768
#define FDn  32
#define NGn  1024
#define KCHUNK 2048   // kNN tile (points) per buffer

typedef unsigned long long u64;

// Scratch (no allocations allowed)
__device__ float4 g_packed[Bn * Nn];        // 4 MB, {x,y,z,0} per point
__device__ u64    g_px[Bn * Nn / 2];        // pair-SoA: {x[2i], x[2i+1]}
__device__ u64    g_py[Bn * Nn / 2];
__device__ u64    g_pz[Bn * Nn / 2];
__device__ int    g_sidx[Bn * NGn];         // FPS-selected global point idx

// Exact (non-FMA, left-to-right) squared distance == XLA sum((a-b)**2) f32.
__device__ __forceinline__ float d2f(float ax, float ay, float az,
                                     float bx, float by, float bz) {
    float dx = ax - bx, dy = ay - by, dz = az - bz;
    return __fadd_rn(__fadd_rn(__fmul_rn(dx, dx), __fmul_rn(dy, dy)),
                     __fmul_rn(dz, dz));
}

// ---------------------------------------------------------------------------
// small PTX helpers
// ---------------------------------------------------------------------------
__device__ __forceinline__ uint32_t s2u(const void* p) {
    return (uint32_t)__cvta_generic_to_shared(p);
}
__device__ __forceinline__ uint32_t ctarank() {
    uint32_t r; asm("mov.u32 %0, %%cluster_ctarank;" : "=r"(r)); return r;
}
__device__ __forceinline__ uint32_t mapa_u32(uint32_t addr, uint32_t rank) {
    uint32_t r;
    asm("mapa.shared::cluster.u32 %0, %1, %2;" : "=r"(r) : "r"(addr), "r"(rank));
    return r;
}
__device__ __forceinline__ void st_async_u64(uint32_t raddr, u64 v, uint32_t rmbar) {
    asm volatile("st.async.shared::cluster.mbarrier::complete_tx::bytes.u64 [%0], %1, [%2];"
                 :: "r"(raddr), "l"(v), "r"(rmbar) : "memory");
}
__device__ __forceinline__ void st_async_u32(uint32_t raddr, uint32_t v, uint32_t rmbar) {
    asm volatile("st.async.shared::cluster.mbarrier::complete_tx::bytes.u32 [%0], %1, [%2];"
                 :: "r"(raddr), "r"(v), "r"(rmbar) : "memory");
}
__device__ __forceinline__ void mbar_init(uint32_t addr, uint32_t cnt) {
    asm volatile("mbarrier.init.shared.b64 [%0], %1;" :: "r"(addr), "r"(cnt) : "memory");
}
__device__ __forceinline__ void mbar_expect_tx(uint32_t addr, uint32_t bytes) {
    asm volatile("mbarrier.arrive.expect_tx.shared.b64 _, [%0], %1;"
                 :: "r"(addr), "r"(bytes) : "memory");
}
__device__ __forceinline__ void mbar_wait_parity(uint32_t addr, uint32_t parity) {
    uint32_t done;
    asm volatile("{\n\t.reg .pred p;\n\t"
                 "mbarrier.try_wait.parity.acquire.cta.shared::cta.b64 p, [%1], %2;\n\t"
                 "selp.b32 %0, 1, 0, p;\n\t}"
                 : "=r"(done) : "r"(addr), "r"(parity) : "memory");
    while (!done) {
        asm volatile("{\n\t.reg .pred p;\n\t"
                     "mbarrier.try_wait.parity.acquire.cta.shared::cta.b64 p, [%1], %2, 0x989680;\n\t"
                     "selp.b32 %0, 1, 0, p;\n\t}"
                     : "=r"(done) : "r"(addr), "r"(parity) : "memory");
    }
}
__device__ __forceinline__ void cluster_sync_asm() {
    asm volatile("barrier.cluster.arrive.aligned;" ::: "memory");
    asm volatile("barrier.cluster.wait.aligned;" ::: "memory");
}
__device__ __forceinline__ void cp_async16(uint32_t saddr, const void* gaddr) {
    asm volatile("cp.async.cg.shared.global [%0], [%1], 16;"
                 :: "r"(saddr), "l"(gaddr) : "memory");
}
__device__ __forceinline__ void cp_commit() {
    asm volatile("cp.async.commit_group;" ::: "memory");
}
template<int N>
__device__ __forceinline__ void cp_wait() {
    asm volatile("cp.async.wait_group %0;" :: "n"(N) : "memory");
}
// packed f32x2 (sm_103a): add/mul only — IEEE-rn per lane, bit-exact vs scalar
__device__ __forceinline__ u64 addx2(u64 a, u64 b) {
    u64 r; asm("add.rn.f32x2 %0, %1, %2;" : "=l"(r) : "l"(a), "l"(b)); return r;
}
__device__ __forceinline__ u64 mulx2(u64 a, u64 b) {
    u64 r; asm("mul.rn.f32x2 %0, %1, %2;" : "=l"(r) : "l"(a), "l"(b)); return r;
}
__device__ __forceinline__ u64 packx2(float lo, float hi) {
    u64 r; asm("mov.b64 %0, {%1, %2};" : "=l"(r) : "f"(lo), "f"(hi)); return r;
}
__device__ __forceinline__ void unpackx2(float& lo, float& hi, u64 v) {
    asm("mov.b64 {%0, %1}, %2;" : "=f"(lo), "=f"(hi) : "l"(v));
}

// ---------------------------------------------------------------------------
// Kernel 1: pack coords [N,3] AoS -> float4 AND pair-SoA u64 arrays
// ---------------------------------------------------------------------------
__global__ void pack_kernel(const float* __restrict__ coord) {
    int t = blockIdx.x * blockDim.x + threadIdx.x;   // points 4t..4t+3
    if (t * 4 >= Bn * Nn) return;
    const float4* c4 = (const float4*)(coord + (size_t)t * 12);
    float4 a = c4[0], b = c4[1], c = c4[2];
    g_packed[t * 4 + 0] = make_float4(a.x, a.y, a.z, 0.f);
    g_packed[t * 4 + 1] = make_float4(a.w, b.x, b.y, 0.f);
    g_packed[t * 4 + 2] = make_float4(b.z, b.w, c.x, 0.f);
    g_packed[t * 4 + 3] = make_float4(c.y, c.z, c.w, 0.f);
    g_px[2 * t]     = packx2(a.x, a.w);
    g_px[2 * t + 1] = packx2(b.z, c.y);
    g_py[2 * t]     = packx2(a.y, b.x);
    g_py[2 * t + 1] = packx2(b.w, c.z);
    g_pz[2 * t]     = packx2(a.z, b.y);
    g_pz[2 * t + 1] = packx2(c.x, c.w);
}

// ---------------------------------------------------------------------------
// FPS: EXACT R7 design (proven 771us). Cluster of 16 CTAs x 256 thr x 8
// pts/thread per batch. redux-only argmax at every level (jnp.argmax
// smallest-index tie-break preserved: lane/slot/rank order == index order).
// One candidate {d2,x,y,z} per CTA exchanged via st.async + mbarrier; winner
// index to rank 0 only. Winner coords from 32KB smem tile at send stage;
// pick stage broadcasts via 3-shfl chain.
// ---------------------------------------------------------------------------
__global__ void __cluster_dims__(16, 1, 1) __launch_bounds__(256, 1)
fps_kernel16() {
    constexpr int C = 16, T = 256, P = 8;
    constexpr int NW = T / 32;            // 8 warps
    constexpr int PTS = T * P;            // 2048 points per CTA

    __shared__ __align__(16) float4 tile[PTS];          // 32KB coord tile
    __shared__ u64 slotK[NW];                            // {d2bits, ~idx}
    __shared__ __align__(16) float4 cand4[2][C];         // {d2, x, y, z}
    __shared__ uint32_t candI[2][C];                     // idx (rank0 only)
    __shared__ u64 mbarrier_s[2];

    const unsigned FULL = 0xffffffffu;
    int tid = threadIdx.x, lane = tid & 31, wid = tid >> 5;
    uint32_t rank = ctarank();
    int b = blockIdx.x / C;
    uint32_t local_base = rank * PTS + (uint32_t)tid * P;
    int gbase = b * Nn + (int)local_base;
    const uint32_t TXB = (rank == 0) ? 20u * C : 16u * C;

    uint32_t mb0 = s2u(&mbarrier_s[0]), mb1 = s2u(&mbarrier_s[1]);
    if (tid == 0) { mbar_init(mb0, 1); mbar_init(mb1, 1); }

    // hoisted remote addresses (warp0 only; rI targets rank 0)
    uint32_t rC4[2], rI[2], rMB[2];
    if (wid == 0 && lane < C) {
#pragma unroll
        for (int q = 0; q < 2; q++) {
            rC4[q] = mapa_u32(s2u(&cand4[q][rank]), (uint32_t)lane);
            rI[q]  = mapa_u32(s2u(&candI[q][rank]), 0u);
            rMB[q] = mapa_u32(q ? mb1 : mb0, (uint32_t)lane);
        }
    }

    float dist[P];
    u64 pxp[P / 2], pyp[P / 2], pzp[P / 2];
    {
        float px[P], py[P], pz[P];
#pragma unroll
        for (int j = 0; j < P; j++) {
            float4 q = g_packed[gbase + j];
            px[j] = q.x; py[j] = q.y; pz[j] = q.z;
            tile[tid * P + j] = q;
        }
#pragma unroll
        for (int p = 0; p < P / 2; p++) {
            pxp[p] = packx2(px[2 * p], px[2 * p + 1]);
            pyp[p] = packx2(py[2 * p], py[2 * p + 1]);
            pzp[p] = packx2(pz[2 * p], pz[2 * p + 1]);
        }
        float4 p0 = g_packed[b * Nn];
#pragma unroll
        for (int j = 0; j < P; j++)
            dist[j] = d2f(px[j], py[j], pz[j], p0.x, p0.y, p0.z);
    }
    float bd = dist[0];
#pragma unroll
    for (int j = 1; j < P; j++) bd = fmaxf(bd, dist[j]);
    if (rank == 0 && tid == 0) g_sidx[b * NGn + 0] = b * Nn;

    __syncthreads();
    cluster_sync_asm();   // mbarriers + tiles ready before any st.async

    for (int k = 1; k < NGn; k++) {
        int kb = k & 1;
        uint32_t parity = (uint32_t)(((k - 1) >> 1) & 1);
        uint32_t mbk = kb ? mb1 : mb0;
        if (tid == 0) mbar_expect_tx(mbk, TXB);

        // smallest j with dist[j] == bd (jnp.argmax tie-break)
        int bj = P - 1;
#pragma unroll
        for (int j = P - 2; j >= 0; j--) bj = (dist[j] == bd) ? j : bj;
        uint32_t myinv = 0xFFFFFFFFu - (local_base + (uint32_t)bj);

        // warp argmax: redux(d2) then redux(~idx among tied)
        uint32_t dbits = __float_as_uint(bd);
        uint32_t wmax  = __reduce_max_sync(FULL, dbits);
        uint32_t inv   = (dbits == wmax) ? myinv : 0u;
        uint32_t winv  = __reduce_max_sync(FULL, inv);
        if (lane == 0) slotK[wid] = ((u64)wmax << 32) | winv;
        __syncthreads();

        if (wid == 0) {
            u64 k0 = slotK[lane & (NW - 1)];
            uint32_t hi = (lane < NW) ? (uint32_t)(k0 >> 32) : 0u;
            uint32_t hm = __reduce_max_sync(FULL, hi);
            uint32_t lo = (hi == hm) ? (uint32_t)k0 : 0u;
            uint32_t lm = __reduce_max_sync(FULL, lo);
            uint32_t ci = 0xFFFFFFFFu - lm;         // batch-local winner idx
            float4 w = tile[ci & (PTS - 1)];        // broadcast LDS.128
            if (lane < C) {
                st_async_u64(rC4[kb],
                             ((u64)__float_as_uint(w.x) << 32) | hm, rMB[kb]);
                st_async_u64(rC4[kb] + 8,
                             ((u64)__float_as_uint(w.z) << 32)
                             | __float_as_uint(w.y), rMB[kb]);
            }
            if (lane == 0) st_async_u32(rI[kb], ci, rMB[kb]);
        }

        mbar_wait_parity(mbk, parity);

        // cluster pick: lane r holds candidate of CTA r (one LDS.128);
        // winner broadcast via 3-shfl chain (R7-proven form)
        int cl = lane & (C - 1);
        float4 cv = cand4[kb][cl];     // {d2, x, y, z}
        uint32_t d = (lane < C) ? __float_as_uint(cv.x) : 0u;
        uint32_t m = __reduce_max_sync(FULL, d);
        int src = __ffs(__ballot_sync(FULL, d == m)) - 1;  // smallest rank==idx
        float gx = __shfl_sync(FULL, cv.y, src);
        float gy = __shfl_sync(FULL, cv.z, src);
        float gz = __shfl_sync(FULL, cv.w, src);
        if (rank == 0 && tid == 0)
            g_sidx[b * NGn + k] = b * Nn + (int)candI[kb][src];

        // packed-f32x2 dist update (pre-negated winner), scalar min/max
        u64 ngx = packx2(-gx, -gx);
        u64 ngy = packx2(-gy, -gy);
        u64 ngz = packx2(-gz, -gz);
        bd = -1.f;
#pragma unroll
        for (int p = 0; p < P / 2; p++) {
            u64 dx = addx2(pxp[p], ngx);
            u64 dy = addx2(pyp[p], ngy);
            u64 dz = addx2(pzp[p], ngz);
            u64 s = addx2(addx2(mulx2(dx, dx), mulx2(dy, dy)), mulx2(dz, dz));
            float s0, s1; unpackx2(s0, s1, s);
            float m0 = fminf(dist[2 * p], s0);
            float m1 = fminf(dist[2 * p + 1], s1);
            dist[2 * p] = m0; dist[2 * p + 1] = m1;
            bd = fmaxf(bd, m0); bd = fmaxf(bd, m1);
        }
    }
}

// ---------------------------------------------------------------------------
// FPS fallback (cluster 8 x 1024, P=4) — only if cluster size 16 is rejected.
// ---------------------------------------------------------------------------
__global__ void __cluster_dims__(8, 1, 1) __launch_bounds__(1024, 1)
fps_kernel8() {
    constexpr int C = 8, T = 1024, P = 4;
    constexpr int NW = T / 32;
    constexpr int PTS = T * P;
    constexpr uint32_t TXB = 20u * C;

    __shared__ uint32_t slotD[NW], slotI[NW];
    __shared__ float    slotX[NW], slotY[NW], slotZ[NW];
    __shared__ u64      candDI[2][C];
    __shared__ u64      candXY[2][C];
    __shared__ uint32_t candZ[2][C];
    __shared__ u64      mbarrier_s[2];

    const unsigned FULL = 0xffffffffu;
    int tid = threadIdx.x, lane = tid & 31, wid = tid >> 5;
    uint32_t rank = ctarank();
    int b = blockIdx.x / C;
    uint32_t local_base = rank * PTS + (uint32_t)tid * P;
    int gbase = b * Nn + (int)local_base;

    uint32_t mb0 = s2u(&mbarrier_s[0]), mb1 = s2u(&mbarrier_s[1]);
    if (tid == 0) { mbar_init(mb0, 1); mbar_init(mb1, 1); }

    uint32_t rDI[2], rXY[2], rZ[2], rMB[2];
    if (wid == 0 && lane < C) {
#pragma unroll
        for (int q = 0; q < 2; q++) {
            rDI[q] = mapa_u32(s2u(&candDI[q][rank]), (uint32_t)lane);
            rXY[q] = mapa_u32(s2u(&candXY[q][rank]), (uint32_t)lane);
            rZ[q]  = mapa_u32(s2u(&candZ[q][rank]),  (uint32_t)lane);
            rMB[q] = mapa_u32(q ? mb1 : mb0, (uint32_t)lane);
        }
    }

    float px[P], py[P], pz[P], dist[P];
#pragma unroll
    for (int j = 0; j < P; j++) {
        float4 q = g_packed[gbase + j];
        px[j] = q.x; py[j] = q.y; pz[j] = q.z;
    }

    float4 p0 = g_packed[b * Nn];
    float bd = -1.f; int bj = 0;
#pragma unroll
    for (int j = 0; j < P; j++) {
        float d = d2f(px[j], py[j], pz[j], p0.x, p0.y, p0.z);
        dist[j] = d;
        if (d > bd) { bd = d; bj = j; }
    }
    if (rank == 0 && tid == 0) g_sidx[b * NGn + 0] = b * Nn;

    __syncthreads();
    cluster_sync_asm();

    for (int k = 1; k < NGn; k++) {
        int kb = k & 1;
        uint32_t parity = (uint32_t)(((k - 1) >> 1) & 1);
        uint32_t mbk = kb ? mb1 : mb0;
        if (tid == 0) mbar_expect_tx(mbk, TXB);

        float cx, cy, cz;
        {
            int j = bj;
            float x01 = (j & 1) ? px[1] : px[0], x23 = (j & 1) ? px[3] : px[2];
            float y01 = (j & 1) ? py[1] : py[0], y23 = (j & 1) ? py[3] : py[2];
            float z01 = (j & 1) ? pz[1] : pz[0], z23 = (j & 1) ? pz[3] : pz[2];
            cx = (j & 2) ? x23 : x01; cy = (j & 2) ? y23 : y01; cz = (j & 2) ? z23 : z01;
        }
        uint32_t myidx = local_base + (uint32_t)bj;

        uint32_t dbits = __float_as_uint(bd);
        uint32_t wmax  = __reduce_max_sync(FULL, dbits);
        int wsrc = __ffs(__ballot_sync(FULL, dbits == wmax)) - 1;
        uint32_t widx = __shfl_sync(FULL, myidx, wsrc);
        float wx = __shfl_sync(FULL, cx, wsrc);
        float wy = __shfl_sync(FULL, cy, wsrc);
        float wz = __shfl_sync(FULL, cz, wsrc);
        if (lane == 0) {
            slotD[wid] = wmax; slotI[wid] = widx;
            slotX[wid] = wx; slotY[wid] = wy; slotZ[wid] = wz;
        }
        __syncthreads();

        if (wid == 0) {
            int sl = lane & (NW - 1);
            uint32_t d = (lane < NW) ? slotD[sl] : 0u;
            uint32_t i = slotI[sl];
            float x = slotX[sl], y = slotY[sl], z = slotZ[sl];
            uint32_t m = __reduce_max_sync(FULL, d);
            int src = __ffs(__ballot_sync(FULL, d == m)) - 1;
            uint32_t ci = __shfl_sync(FULL, i, src);
            float fx = __shfl_sync(FULL, x, src);
            float fy = __shfl_sync(FULL, y, src);
            float fz = __shfl_sync(FULL, z, src);
            if (lane < C) {
                st_async_u64(rDI[kb], ((u64)m << 32) | ci, rMB[kb]);
                st_async_u64(rXY[kb],
                             ((u64)__float_as_uint(fy) << 32) | __float_as_uint(fx),
                             rMB[kb]);
                st_async_u32(rZ[kb], __float_as_uint(fz), rMB[kb]);
            }
        }

        mbar_wait_parity(mbk, parity);

        int cl = lane & (C - 1);
        u64 di = candDI[kb][cl];
        u64 xy = candXY[kb][cl];
        uint32_t zz = candZ[kb][cl];
        uint32_t d = (lane < C) ? (uint32_t)(di >> 32) : 0u;
        uint32_t m = __reduce_max_sync(FULL, d);
        int src = __ffs(__ballot_sync(FULL, d == m)) - 1;
        uint32_t wl = __shfl_sync(FULL, (uint32_t)di, src);
        u64 wxy = __shfl_sync(FULL, xy, src);
        uint32_t wzb = __shfl_sync(FULL, zz, src);
        float gx = __uint_as_float((uint32_t)wxy);
        float gy = __uint_as_float((uint32_t)(wxy >> 32));
        float gz = __uint_as_float(wzb);
        if (rank == 0 && tid == 0) g_sidx[b * NGn + k] = b * Nn + (int)wl;

        bd = -1.f; bj = 0;
#pragma unroll
        for (int j = 0; j < P; j++) {
            float nd = d2f(px[j], py[j], pz[j], gx, gy, gz);
            float mn = fminf(dist[j], nd);
            dist[j] = mn;
            if (mn > bd) { bd = mn; bj = j; }
        }
    }
}

// ---------------------------------------------------------------------------
// Kernel 3: kNN (top-32 by (d2, idx) lex order) + angle/curvature + outputs.
// Wide scan: 128 points/group via ulonglong2 LDS.128 on pair-SoA tiles
// (4 d2 values per lane per group), one combined early-skip ballot gating
// four insertion masks. Kept set unchanged (replace-lex-max is insertion-
// order independent).
// ---------------------------------------------------------------------------
__global__ void __launch_bounds__(512, 1)
knn_kernel(const float* __restrict__ coord, const float* __restrict__ feat,
           const int* __restrict__ labels, float* __restrict__ out) {
    __shared__ __align__(16) u64 scx[2][KCHUNK / 2];
    __shared__ __align__(16) u64 scy[2][KCHUNK / 2];
    __shared__ __align__(16) u64 scz[2][KCHUNK / 2];
    const unsigned FULL = 0xffffffffu;
    int tid = threadIdx.x, lane = tid & 31, wid = tid >> 5;
    int s = blockIdx.x * 16 + wid;   // sample id [0, 8192)
    int b = s >> 10;                 // batch
    int si = g_sidx[s];
    float4 sp = g_packed[si];
    u64 nspx = packx2(-sp.x, -sp.x);
    u64 nspy = packx2(-sp.y, -sp.y);
    u64 nspz = packx2(-sp.z, -sp.z);

    float kd = 3.4028235e38f; unsigned ki = 0xffffffffu;    // kept (per lane)
    float tmd = 3.4028235e38f; unsigned tmi = 0xffffffffu; int tml = 0;

    constexpr int NT = Nn / KCHUNK;      // 16 tiles
    int pbase = b * (Nn / 2);
    auto stage = [&](int buf, int c) {
        int po = pbase + c * (KCHUNK / 2) + tid * 2;
        cp_async16(s2u(&scx[buf][tid * 2]), &g_px[po]);
        cp_async16(s2u(&scy[buf][tid * 2]), &g_py[po]);
        cp_async16(s2u(&scz[buf][tid * 2]), &g_pz[po]);
        cp_commit();
    };
    stage(0, 0);
    for (int c = 0; c < NT; c++) {
        int buf = c & 1;
        if (c + 1 < NT) { stage(buf ^ 1, c + 1); cp_wait<1>(); }
        else           { cp_wait<0>(); }
        __syncthreads();
        int cbase = b * Nn + c * KCHUNK;
        const ulonglong2* sx2 = (const ulonglong2*)scx[buf];
        const ulonglong2* sy2 = (const ulonglong2*)scy[buf];
        const ulonglong2* sz2 = (const ulonglong2*)scz[buf];
        for (int j = 0; j < KCHUNK / 128; j++) {         // 16 groups of 128
            int pi = j * 32 + lane;
            ulonglong2 vx = sx2[pi], vy = sy2[pi], vz = sz2[pi];
            u64 dx0 = addx2(vx.x, nspx), dx1 = addx2(vx.y, nspx);
            u64 dy0 = addx2(vy.x, nspy), dy1 = addx2(vy.y, nspy);
            u64 dz0 = addx2(vz.x, nspz), dz1 = addx2(vz.y, nspz);
            u64 s0 = addx2(addx2(mulx2(dx0, dx0), mulx2(dy0, dy0)), mulx2(dz0, dz0));
            u64 s1 = addx2(addx2(mulx2(dx1, dx1), mulx2(dy1, dy1)), mulx2(dz1, dz1));
            float dA, dB, dC, dD;
            unpackx2(dA, dB, s0);
            unpackx2(dC, dD, s1);
            int gb = cbase + j * 128;                    // group base point idx
            unsigned giA = (unsigned)(gb + 4 * lane);
            bool cA = (dA < tmd) || (dA == tmd && giA < tmi);
            bool cB = (dB < tmd) || (dB == tmd && giA + 1 < tmi);
            bool cC = (dC < tmd) || (dC == tmd && giA + 2 < tmi);
            bool cD = (dD < tmd) || (dD == tmd && giA + 3 < tmi);
            if (__ballot_sync(FULL, cA || cB || cC || cD) == 0u) continue;
            unsigned mA = __ballot_sync(FULL, cA);
            unsigned mB = __ballot_sync(FULL, cB);
            unsigned mC = __ballot_sync(FULL, cC);
            unsigned mD = __ballot_sync(FULL, cD);
#pragma unroll
            for (int h = 0; h < 4; h++) {
                unsigned mm = (h == 0) ? mA : (h == 1) ? mB : (h == 2) ? mC : mD;
                float dv = (h == 0) ? dA : (h == 1) ? dB : (h == 2) ? dC : dD;
                while (mm) {
                    int ins = __ffs(mm) - 1; mm &= mm - 1;
                    float cd = __shfl_sync(FULL, dv, ins);
                    unsigned cgi = (unsigned)(gb + 4 * ins + h);
                    if ((cd < tmd) || (cd == tmd && cgi < tmi)) {
                        if (lane == tml) { kd = cd; ki = cgi; }
                        unsigned db = __float_as_uint(kd);
                        unsigned m  = __reduce_max_sync(FULL, db);
                        bool tie    = (db == m);
                        unsigned mi2 = __reduce_max_sync(FULL, tie ? ki : 0u);
                        tml = __ffs(__ballot_sync(FULL, tie && ki == mi2)) - 1;
                        tmd = __uint_as_float(m); tmi = mi2;
                    }
                }
            }
        }
        __syncthreads();   // scan done before next overwrite of buf
    }

    // ---- angles: angle = 2*atan2(sqrt(t - a.b), sqrt(t + a.b)), t=|a||b| ----
    float a_own = feat[(size_t)si * FDn + lane];
    float dot = 0.f, an2 = 0.f, bn2 = 0.f;
    const float4* frow = (const float4*)(feat + (size_t)ki * FDn);
#pragma unroll
    for (int g = 0; g < FDn / 4; g++) {
        float4 bv = frow[g];
        float a0 = __shfl_sync(FULL, a_own, g * 4 + 0);
        float a1 = __shfl_sync(FULL, a_own, g * 4 + 1);
        float a2 = __shfl_sync(FULL, a_own, g * 4 + 2);
        float a3 = __shfl_sync(FULL, a_own, g * 4 + 3);
        dot = fmaf(a0, bv.x, dot); an2 = fmaf(a0, a0, an2); bn2 = fmaf(bv.x, bv.x, bn2);
        dot = fmaf(a1, bv.y, dot); an2 = fmaf(a1, a1, an2); bn2 = fmaf(bv.y, bv.y, bn2);
        dot = fmaf(a2, bv.z, dot); an2 = fmaf(a2, a2, an2); bn2 = fmaf(bv.z, bv.z, bn2);
        dot = fmaf(a3, bv.w, dot); an2 = fmaf(a3, a3, an2); bn2 = fmaf(bv.w, bv.w, bn2);
    }
    float t = sqrtf(an2) * sqrtf(bn2);
    float ang = 2.f * atan2f(sqrtf(fmaxf(t - dot, 0.f)), sqrtf(fmaxf(t + dot, 0.f)));
    if (ki == (unsigned)si) ang = 0.f;   // self neighbor contributes 0
    float ssum = ang;
#pragma unroll
    for (int o = 16; o; o >>= 1) ssum += __shfl_xor_sync(FULL, ssum, o);
    float pc = ssum / 31.f;

    // ---- outputs (tuple flattened+concatenated as float32) ----
    const int OFF_FEAT = Bn * NGn * 3;
    const int OFF_SW   = OFF_FEAT + Bn * NGn * (FDn + 1);
    const int OFF_LAB  = OFF_SW + Bn * NGn;
    const int OFF_SIDX = OFF_LAB + Bn * NGn;
    if (lane < 3) out[s * 3 + lane] = coord[si * 3 + lane];
    out[OFF_FEAT + s * 33 + lane] = a_own;
    if (lane == 0) {
        out[OFF_FEAT + s * 33 + 32] = pc;
        out[OFF_SW + s]   = pc > 0.087266f ? 1.f : 0.f;
        out[OFF_LAB + s]  = (float)labels[si];
        out[OFF_SIDX + s] = (float)si;
    }
}

// ---------------------------------------------------------------------------
extern "C" void kernel_launch(void* const* d_in, const int* in_sizes, int n_in,
                              void* d_out, int out_size) {
    const float* coord  = (const float*)d_in[0];
    const float* feat   = (const float*)d_in[1];
    const int*   labels = (const int*)d_in[2];
    float* out = (float*)d_out;

    pack_kernel<<<(Bn * Nn / 4 + 255) / 256, 256>>>(coord);

    cudaError_t rc = cudaFuncSetAttribute(
        (const void*)fps_kernel16,
        cudaFuncAttributeNonPortableClusterSizeAllowed, 1);
    if (rc == cudaSuccess) {
        fps_kernel16<<<Bn * 16, 256>>>();
    } else {
        (void)cudaGetLastError();
        fps_kernel8<<<Bn * 8, 1024>>>();
    }

    knn_kernel<<<(Bn * NGn) / 16, 512>>>(coord, feat, labels, out);
}

// round 13
// speedup vs baseline: 1.4010x; 1.0320x over previous
#include <cuda_runtime.h>
#include <cstdint>

#define Bn   8
#define Nn   32768
#define FDn  32
#define NGn  1024
#define KCHUNK 2048   // kNN tile (points) per buffer

typedef unsigned long long u64;

// Scratch (no allocations allowed)
__device__ float4 g_packed[Bn * Nn];        // 4 MB, {x,y,z,0} per point
__device__ u64    g_px[Bn * Nn / 2];        // pair-SoA: {x[2i], x[2i+1]}
__device__ u64    g_py[Bn * Nn / 2];
__device__ u64    g_pz[Bn * Nn / 2];
__device__ int    g_sidx[Bn * NGn];         // FPS-selected global point idx

// Exact (non-FMA, left-to-right) squared distance == XLA sum((a-b)**2) f32.
__device__ __forceinline__ float d2f(float ax, float ay, float az,
                                     float bx, float by, float bz) {
    float dx = ax - bx, dy = ay - by, dz = az - bz;
    return __fadd_rn(__fadd_rn(__fmul_rn(dx, dx), __fmul_rn(dy, dy)),
                     __fmul_rn(dz, dz));
}

// ---------------------------------------------------------------------------
// small PTX helpers
// ---------------------------------------------------------------------------
__device__ __forceinline__ uint32_t s2u(const void* p) {
    return (uint32_t)__cvta_generic_to_shared(p);
}
__device__ __forceinline__ uint32_t ctarank() {
    uint32_t r; asm("mov.u32 %0, %%cluster_ctarank;" : "=r"(r)); return r;
}
__device__ __forceinline__ uint32_t mapa_u32(uint32_t addr, uint32_t rank) {
    uint32_t r;
    asm("mapa.shared::cluster.u32 %0, %1, %2;" : "=r"(r) : "r"(addr), "r"(rank));
    return r;
}
__device__ __forceinline__ void st_async_u64(uint32_t raddr, u64 v, uint32_t rmbar) {
    asm volatile("st.async.shared::cluster.mbarrier::complete_tx::bytes.u64 [%0], %1, [%2];"
                 :: "r"(raddr), "l"(v), "r"(rmbar) : "memory");
}
__device__ __forceinline__ void st_async_u32(uint32_t raddr, uint32_t v, uint32_t rmbar) {
    asm volatile("st.async.shared::cluster.mbarrier::complete_tx::bytes.u32 [%0], %1, [%2];"
                 :: "r"(raddr), "r"(v), "r"(rmbar) : "memory");
}
__device__ __forceinline__ void mbar_init(uint32_t addr, uint32_t cnt) {
    asm volatile("mbarrier.init.shared.b64 [%0], %1;" :: "r"(addr), "r"(cnt) : "memory");
}
__device__ __forceinline__ void mbar_expect_tx(uint32_t addr, uint32_t bytes) {
    asm volatile("mbarrier.arrive.expect_tx.shared.b64 _, [%0], %1;"
                 :: "r"(addr), "r"(bytes) : "memory");
}
__device__ __forceinline__ void mbar_wait_parity(uint32_t addr, uint32_t parity) {
    uint32_t done;
    asm volatile("{\n\t.reg .pred p;\n\t"
                 "mbarrier.try_wait.parity.acquire.cta.shared::cta.b64 p, [%1], %2;\n\t"
                 "selp.b32 %0, 1, 0, p;\n\t}"
                 : "=r"(done) : "r"(addr), "r"(parity) : "memory");
    while (!done) {
        asm volatile("{\n\t.reg .pred p;\n\t"
                     "mbarrier.try_wait.parity.acquire.cta.shared::cta.b64 p, [%1], %2, 0x989680;\n\t"
                     "selp.b32 %0, 1, 0, p;\n\t}"
                     : "=r"(done) : "r"(addr), "r"(parity) : "memory");
    }
}
__device__ __forceinline__ void cluster_sync_asm() {
    asm volatile("barrier.cluster.arrive.aligned;" ::: "memory");
    asm volatile("barrier.cluster.wait.aligned;" ::: "memory");
}
__device__ __forceinline__ void cp_async16(uint32_t saddr, const void* gaddr) {
    asm volatile("cp.async.cg.shared.global [%0], [%1], 16;"
                 :: "r"(saddr), "l"(gaddr) : "memory");
}
__device__ __forceinline__ void cp_commit() {
    asm volatile("cp.async.commit_group;" ::: "memory");
}
template<int N>
__device__ __forceinline__ void cp_wait() {
    asm volatile("cp.async.wait_group %0;" :: "n"(N) : "memory");
}
// packed f32x2 (sm_103a): add/mul only — IEEE-rn per lane, bit-exact vs scalar
__device__ __forceinline__ u64 addx2(u64 a, u64 b) {
    u64 r; asm("add.rn.f32x2 %0, %1, %2;" : "=l"(r) : "l"(a), "l"(b)); return r;
}
__device__ __forceinline__ u64 mulx2(u64 a, u64 b) {
    u64 r; asm("mul.rn.f32x2 %0, %1, %2;" : "=l"(r) : "l"(a), "l"(b)); return r;
}
__device__ __forceinline__ u64 packx2(float lo, float hi) {
    u64 r; asm("mov.b64 %0, {%1, %2};" : "=l"(r) : "f"(lo), "f"(hi)); return r;
}
__device__ __forceinline__ void unpackx2(float& lo, float& hi, u64 v) {
    asm("mov.b64 {%0, %1}, %2;" : "=f"(lo), "=f"(hi) : "l"(v));
}

// ---------------------------------------------------------------------------
// Kernel 1: pack coords [N,3] AoS -> float4 AND pair-SoA u64 arrays
// ---------------------------------------------------------------------------
__global__ void pack_kernel(const float* __restrict__ coord) {
    int t = blockIdx.x * blockDim.x + threadIdx.x;   // points 4t..4t+3
    if (t * 4 >= Bn * Nn) return;
    const float4* c4 = (const float4*)(coord + (size_t)t * 12);
    float4 a = c4[0], b = c4[1], c = c4[2];
    g_packed[t * 4 + 0] = make_float4(a.x, a.y, a.z, 0.f);
    g_packed[t * 4 + 1] = make_float4(a.w, b.x, b.y, 0.f);
    g_packed[t * 4 + 2] = make_float4(b.z, b.w, c.x, 0.f);
    g_packed[t * 4 + 3] = make_float4(c.y, c.z, c.w, 0.f);
    g_px[2 * t]     = packx2(a.x, a.w);
    g_px[2 * t + 1] = packx2(b.z, c.y);
    g_py[2 * t]     = packx2(a.y, b.x);
    g_py[2 * t + 1] = packx2(b.w, c.z);
    g_pz[2 * t]     = packx2(a.z, b.y);
    g_pz[2 * t + 1] = packx2(c.x, c.w);
}

// ---------------------------------------------------------------------------
// FPS: EXACT R7 design (proven). Cluster of 16 CTAs x 256 thr x 8 pts/thread
// per batch. redux-only argmax at every level (jnp.argmax smallest-index
// tie-break preserved: lane/slot/rank order == index order). One candidate
// {d2,x,y,z} per CTA exchanged via st.async + mbarrier; winner index to
// rank 0 only. Winner coords from 32KB smem tile at send stage; pick stage
// broadcasts via 3-shfl chain.
// ---------------------------------------------------------------------------
__global__ void __cluster_dims__(16, 1, 1) __launch_bounds__(256, 1)
fps_kernel16() {
    constexpr int C = 16, T = 256, P = 8;
    constexpr int NW = T / 32;            // 8 warps
    constexpr int PTS = T * P;            // 2048 points per CTA

    __shared__ __align__(16) float4 tile[PTS];          // 32KB coord tile
    __shared__ u64 slotK[NW];                            // {d2bits, ~idx}
    __shared__ __align__(16) float4 cand4[2][C];         // {d2, x, y, z}
    __shared__ uint32_t candI[2][C];                     // idx (rank0 only)
    __shared__ u64 mbarrier_s[2];

    const unsigned FULL = 0xffffffffu;
    int tid = threadIdx.x, lane = tid & 31, wid = tid >> 5;
    uint32_t rank = ctarank();
    int b = blockIdx.x / C;
    uint32_t local_base = rank * PTS + (uint32_t)tid * P;
    int gbase = b * Nn + (int)local_base;
    const uint32_t TXB = (rank == 0) ? 20u * C : 16u * C;

    uint32_t mb0 = s2u(&mbarrier_s[0]), mb1 = s2u(&mbarrier_s[1]);
    if (tid == 0) { mbar_init(mb0, 1); mbar_init(mb1, 1); }

    // hoisted remote addresses (warp0 only; rI targets rank 0)
    uint32_t rC4[2], rI[2], rMB[2];
    if (wid == 0 && lane < C) {
#pragma unroll
        for (int q = 0; q < 2; q++) {
            rC4[q] = mapa_u32(s2u(&cand4[q][rank]), (uint32_t)lane);
            rI[q]  = mapa_u32(s2u(&candI[q][rank]), 0u);
            rMB[q] = mapa_u32(q ? mb1 : mb0, (uint32_t)lane);
        }
    }

    float dist[P];
    u64 pxp[P / 2], pyp[P / 2], pzp[P / 2];
    {
        float px[P], py[P], pz[P];
#pragma unroll
        for (int j = 0; j < P; j++) {
            float4 q = g_packed[gbase + j];
            px[j] = q.x; py[j] = q.y; pz[j] = q.z;
            tile[tid * P + j] = q;
        }
#pragma unroll
        for (int p = 0; p < P / 2; p++) {
            pxp[p] = packx2(px[2 * p], px[2 * p + 1]);
            pyp[p] = packx2(py[2 * p], py[2 * p + 1]);
            pzp[p] = packx2(pz[2 * p], pz[2 * p + 1]);
        }
        float4 p0 = g_packed[b * Nn];
#pragma unroll
        for (int j = 0; j < P; j++)
            dist[j] = d2f(px[j], py[j], pz[j], p0.x, p0.y, p0.z);
    }
    float bd = dist[0];
#pragma unroll
    for (int j = 1; j < P; j++) bd = fmaxf(bd, dist[j]);
    if (rank == 0 && tid == 0) g_sidx[b * NGn + 0] = b * Nn;

    __syncthreads();
    cluster_sync_asm();   // mbarriers + tiles ready before any st.async

    for (int k = 1; k < NGn; k++) {
        int kb = k & 1;
        uint32_t parity = (uint32_t)(((k - 1) >> 1) & 1);
        uint32_t mbk = kb ? mb1 : mb0;
        if (tid == 0) mbar_expect_tx(mbk, TXB);

        // smallest j with dist[j] == bd (jnp.argmax tie-break)
        int bj = P - 1;
#pragma unroll
        for (int j = P - 2; j >= 0; j--) bj = (dist[j] == bd) ? j : bj;
        uint32_t myinv = 0xFFFFFFFFu - (local_base + (uint32_t)bj);

        // warp argmax: redux(d2) then redux(~idx among tied)
        uint32_t dbits = __float_as_uint(bd);
        uint32_t wmax  = __reduce_max_sync(FULL, dbits);
        uint32_t inv   = (dbits == wmax) ? myinv : 0u;
        uint32_t winv  = __reduce_max_sync(FULL, inv);
        if (lane == 0) slotK[wid] = ((u64)wmax << 32) | winv;
        __syncthreads();

        if (wid == 0) {
            u64 k0 = slotK[lane & (NW - 1)];
            uint32_t hi = (lane < NW) ? (uint32_t)(k0 >> 32) : 0u;
            uint32_t hm = __reduce_max_sync(FULL, hi);
            uint32_t lo = (hi == hm) ? (uint32_t)k0 : 0u;
            uint32_t lm = __reduce_max_sync(FULL, lo);
            uint32_t ci = 0xFFFFFFFFu - lm;         // batch-local winner idx
            float4 w = tile[ci & (PTS - 1)];        // broadcast LDS.128
            if (lane < C) {
                st_async_u64(rC4[kb],
                             ((u64)__float_as_uint(w.x) << 32) | hm, rMB[kb]);
                st_async_u64(rC4[kb] + 8,
                             ((u64)__float_as_uint(w.z) << 32)
                             | __float_as_uint(w.y), rMB[kb]);
            }
            if (lane == 0) st_async_u32(rI[kb], ci, rMB[kb]);
        }

        mbar_wait_parity(mbk, parity);

        // cluster pick: lane r holds candidate of CTA r (one LDS.128);
        // winner broadcast via 3-shfl chain (R7-proven form)
        int cl = lane & (C - 1);
        float4 cv = cand4[kb][cl];     // {d2, x, y, z}
        uint32_t d = (lane < C) ? __float_as_uint(cv.x) : 0u;
        uint32_t m = __reduce_max_sync(FULL, d);
        int src = __ffs(__ballot_sync(FULL, d == m)) - 1;  // smallest rank==idx
        float gx = __shfl_sync(FULL, cv.y, src);
        float gy = __shfl_sync(FULL, cv.z, src);
        float gz = __shfl_sync(FULL, cv.w, src);
        if (rank == 0 && tid == 0)
            g_sidx[b * NGn + k] = b * Nn + (int)candI[kb][src];

        // packed-f32x2 dist update (pre-negated winner), scalar min/max
        u64 ngx = packx2(-gx, -gx);
        u64 ngy = packx2(-gy, -gy);
        u64 ngz = packx2(-gz, -gz);
        bd = -1.f;
#pragma unroll
        for (int p = 0; p < P / 2; p++) {
            u64 dx = addx2(pxp[p], ngx);
            u64 dy = addx2(pyp[p], ngy);
            u64 dz = addx2(pzp[p], ngz);
            u64 s = addx2(addx2(mulx2(dx, dx), mulx2(dy, dy)), mulx2(dz, dz));
            float s0, s1; unpackx2(s0, s1, s);
            float m0 = fminf(dist[2 * p], s0);
            float m1 = fminf(dist[2 * p + 1], s1);
            dist[2 * p] = m0; dist[2 * p + 1] = m1;
            bd = fmaxf(bd, m0); bd = fmaxf(bd, m1);
        }
    }
}

// ---------------------------------------------------------------------------
// FPS fallback (cluster 8 x 1024, P=4) — only if cluster size 16 is rejected.
// ---------------------------------------------------------------------------
__global__ void __cluster_dims__(8, 1, 1) __launch_bounds__(1024, 1)
fps_kernel8() {
    constexpr int C = 8, T = 1024, P = 4;
    constexpr int NW = T / 32;
    constexpr int PTS = T * P;
    constexpr uint32_t TXB = 20u * C;

    __shared__ uint32_t slotD[NW], slotI[NW];
    __shared__ float    slotX[NW], slotY[NW], slotZ[NW];
    __shared__ u64      candDI[2][C];
    __shared__ u64      candXY[2][C];
    __shared__ uint32_t candZ[2][C];
    __shared__ u64      mbarrier_s[2];

    const unsigned FULL = 0xffffffffu;
    int tid = threadIdx.x, lane = tid & 31, wid = tid >> 5;
    uint32_t rank = ctarank();
    int b = blockIdx.x / C;
    uint32_t local_base = rank * PTS + (uint32_t)tid * P;
    int gbase = b * Nn + (int)local_base;

    uint32_t mb0 = s2u(&mbarrier_s[0]), mb1 = s2u(&mbarrier_s[1]);
    if (tid == 0) { mbar_init(mb0, 1); mbar_init(mb1, 1); }

    uint32_t rDI[2], rXY[2], rZ[2], rMB[2];
    if (wid == 0 && lane < C) {
#pragma unroll
        for (int q = 0; q < 2; q++) {
            rDI[q] = mapa_u32(s2u(&candDI[q][rank]), (uint32_t)lane);
            rXY[q] = mapa_u32(s2u(&candXY[q][rank]), (uint32_t)lane);
            rZ[q]  = mapa_u32(s2u(&candZ[q][rank]),  (uint32_t)lane);
            rMB[q] = mapa_u32(q ? mb1 : mb0, (uint32_t)lane);
        }
    }

    float px[P], py[P], pz[P], dist[P];
#pragma unroll
    for (int j = 0; j < P; j++) {
        float4 q = g_packed[gbase + j];
        px[j] = q.x; py[j] = q.y; pz[j] = q.z;
    }

    float4 p0 = g_packed[b * Nn];
    float bd = -1.f; int bj = 0;
#pragma unroll
    for (int j = 0; j < P; j++) {
        float d = d2f(px[j], py[j], pz[j], p0.x, p0.y, p0.z);
        dist[j] = d;
        if (d > bd) { bd = d; bj = j; }
    }
    if (rank == 0 && tid == 0) g_sidx[b * NGn + 0] = b * Nn;

    __syncthreads();
    cluster_sync_asm();

    for (int k = 1; k < NGn; k++) {
        int kb = k & 1;
        uint32_t parity = (uint32_t)(((k - 1) >> 1) & 1);
        uint32_t mbk = kb ? mb1 : mb0;
        if (tid == 0) mbar_expect_tx(mbk, TXB);

        float cx, cy, cz;
        {
            int j = bj;
            float x01 = (j & 1) ? px[1] : px[0], x23 = (j & 1) ? px[3] : px[2];
            float y01 = (j & 1) ? py[1] : py[0], y23 = (j & 1) ? py[3] : py[2];
            float z01 = (j & 1) ? pz[1] : pz[0], z23 = (j & 1) ? pz[3] : pz[2];
            cx = (j & 2) ? x23 : x01; cy = (j & 2) ? y23 : y01; cz = (j & 2) ? z23 : z01;
        }
        uint32_t myidx = local_base + (uint32_t)bj;

        uint32_t dbits = __float_as_uint(bd);
        uint32_t wmax  = __reduce_max_sync(FULL, dbits);
        int wsrc = __ffs(__ballot_sync(FULL, dbits == wmax)) - 1;
        uint32_t widx = __shfl_sync(FULL, myidx, wsrc);
        float wx = __shfl_sync(FULL, cx, wsrc);
        float wy = __shfl_sync(FULL, cy, wsrc);
        float wz = __shfl_sync(FULL, cz, wsrc);
        if (lane == 0) {
            slotD[wid] = wmax; slotI[wid] = widx;
            slotX[wid] = wx; slotY[wid] = wy; slotZ[wid] = wz;
        }
        __syncthreads();

        if (wid == 0) {
            int sl = lane & (NW - 1);
            uint32_t d = (lane < NW) ? slotD[sl] : 0u;
            uint32_t i = slotI[sl];
            float x = slotX[sl], y = slotY[sl], z = slotZ[sl];
            uint32_t m = __reduce_max_sync(FULL, d);
            int src = __ffs(__ballot_sync(FULL, d == m)) - 1;
            uint32_t ci = __shfl_sync(FULL, i, src);
            float fx = __shfl_sync(FULL, x, src);
            float fy = __shfl_sync(FULL, y, src);
            float fz = __shfl_sync(FULL, z, src);
            if (lane < C) {
                st_async_u64(rDI[kb], ((u64)m << 32) | ci, rMB[kb]);
                st_async_u64(rXY[kb],
                             ((u64)__float_as_uint(fy) << 32) | __float_as_uint(fx),
                             rMB[kb]);
                st_async_u32(rZ[kb], __float_as_uint(fz), rMB[kb]);
            }
        }

        mbar_wait_parity(mbk, parity);

        int cl = lane & (C - 1);
        u64 di = candDI[kb][cl];
        u64 xy = candXY[kb][cl];
        uint32_t zz = candZ[kb][cl];
        uint32_t d = (lane < C) ? (uint32_t)(di >> 32) : 0u;
        uint32_t m = __reduce_max_sync(FULL, d);
        int src = __ffs(__ballot_sync(FULL, d == m)) - 1;
        uint32_t wl = __shfl_sync(FULL, (uint32_t)di, src);
        u64 wxy = __shfl_sync(FULL, xy, src);
        uint32_t wzb = __shfl_sync(FULL, zz, src);
        float gx = __uint_as_float((uint32_t)wxy);
        float gy = __uint_as_float((uint32_t)(wxy >> 32));
        float gz = __uint_as_float(wzb);
        if (rank == 0 && tid == 0) g_sidx[b * NGn + k] = b * Nn + (int)wl;

        bd = -1.f; bj = 0;
#pragma unroll
        for (int j = 0; j < P; j++) {
            float nd = d2f(px[j], py[j], pz[j], gx, gy, gz);
            float mn = fminf(dist[j], nd);
            dist[j] = mn;
            if (mn > bd) { bd = mn; bj = j; }
        }
    }
}

// ---------------------------------------------------------------------------
// Kernel 3: kNN (top-32 by (d2, idx) lex order) + angle/curvature + outputs.
// 256 threads = 8 warps = 8 samples/CTA, grid 1024: 4 CTAs/SM co-resident
// (192KB smem) -> 32 warps/SM latency hiding + 4x smaller tail quantum.
// Wide scan: 128 points/group via ulonglong2 LDS.128 on pair-SoA tiles,
// one combined early-skip ballot gating four insertion masks.
// ---------------------------------------------------------------------------
__global__ void __launch_bounds__(256, 1)
knn_kernel(const float* __restrict__ coord, const float* __restrict__ feat,
           const int* __restrict__ labels, float* __restrict__ out) {
    __shared__ __align__(16) u64 scx[2][KCHUNK / 2];
    __shared__ __align__(16) u64 scy[2][KCHUNK / 2];
    __shared__ __align__(16) u64 scz[2][KCHUNK / 2];
    const unsigned FULL = 0xffffffffu;
    int tid = threadIdx.x, lane = tid & 31, wid = tid >> 5;
    int s = blockIdx.x * 8 + wid;    // sample id [0, 8192)
    int b = s >> 10;                 // batch
    int si = g_sidx[s];
    float4 sp = g_packed[si];
    u64 nspx = packx2(-sp.x, -sp.x);
    u64 nspy = packx2(-sp.y, -sp.y);
    u64 nspz = packx2(-sp.z, -sp.z);

    float kd = 3.4028235e38f; unsigned ki = 0xffffffffu;    // kept (per lane)
    float tmd = 3.4028235e38f; unsigned tmi = 0xffffffffu; int tml = 0;

    constexpr int NT = Nn / KCHUNK;      // 16 tiles
    int pbase = b * (Nn / 2);
    // 256 threads stage 1024 u64 per axis: 4 u64 (2 cp.async16) per thread
    auto stage = [&](int buf, int c) {
        int po = pbase + c * (KCHUNK / 2) + tid * 4;
        uint32_t o = (uint32_t)tid * 32;
        cp_async16(s2u(&scx[buf][0]) + o,      &g_px[po]);
        cp_async16(s2u(&scx[buf][0]) + o + 16, &g_px[po + 2]);
        cp_async16(s2u(&scy[buf][0]) + o,      &g_py[po]);
        cp_async16(s2u(&scy[buf][0]) + o + 16, &g_py[po + 2]);
        cp_async16(s2u(&scz[buf][0]) + o,      &g_pz[po]);
        cp_async16(s2u(&scz[buf][0]) + o + 16, &g_pz[po + 2]);
        cp_commit();
    };
    stage(0, 0);
    for (int c = 0; c < NT; c++) {
        int buf = c & 1;
        if (c + 1 < NT) { stage(buf ^ 1, c + 1); cp_wait<1>(); }
        else           { cp_wait<0>(); }
        __syncthreads();
        int cbase = b * Nn + c * KCHUNK;
        const ulonglong2* sx2 = (const ulonglong2*)scx[buf];
        const ulonglong2* sy2 = (const ulonglong2*)scy[buf];
        const ulonglong2* sz2 = (const ulonglong2*)scz[buf];
        for (int j = 0; j < KCHUNK / 128; j++) {         // 16 groups of 128
            int pi = j * 32 + lane;
            ulonglong2 vx = sx2[pi], vy = sy2[pi], vz = sz2[pi];
            u64 dx0 = addx2(vx.x, nspx), dx1 = addx2(vx.y, nspx);
            u64 dy0 = addx2(vy.x, nspy), dy1 = addx2(vy.y, nspy);
            u64 dz0 = addx2(vz.x, nspz), dz1 = addx2(vz.y, nspz);
            u64 s0 = addx2(addx2(mulx2(dx0, dx0), mulx2(dy0, dy0)), mulx2(dz0, dz0));
            u64 s1 = addx2(addx2(mulx2(dx1, dx1), mulx2(dy1, dy1)), mulx2(dz1, dz1));
            float dA, dB, dC, dD;
            unpackx2(dA, dB, s0);
            unpackx2(dC, dD, s1);
            int gb = cbase + j * 128;                    // group base point idx
            unsigned giA = (unsigned)(gb + 4 * lane);
            bool cA = (dA < tmd) || (dA == tmd && giA < tmi);
            bool cB = (dB < tmd) || (dB == tmd && giA + 1 < tmi);
            bool cC = (dC < tmd) || (dC == tmd && giA + 2 < tmi);
            bool cD = (dD < tmd) || (dD == tmd && giA + 3 < tmi);
            if (__ballot_sync(FULL, cA || cB || cC || cD) == 0u) continue;
            unsigned mA = __ballot_sync(FULL, cA);
            unsigned mB = __ballot_sync(FULL, cB);
            unsigned mC = __ballot_sync(FULL, cC);
            unsigned mD = __ballot_sync(FULL, cD);
#pragma unroll
            for (int h = 0; h < 4; h++) {
                unsigned mm = (h == 0) ? mA : (h == 1) ? mB : (h == 2) ? mC : mD;
                float dv = (h == 0) ? dA : (h == 1) ? dB : (h == 2) ? dC : dD;
                while (mm) {
                    int ins = __ffs(mm) - 1; mm &= mm - 1;
                    float cd = __shfl_sync(FULL, dv, ins);
                    unsigned cgi = (unsigned)(gb + 4 * ins + h);
                    if ((cd < tmd) || (cd == tmd && cgi < tmi)) {
                        if (lane == tml) { kd = cd; ki = cgi; }
                        unsigned db = __float_as_uint(kd);
                        unsigned m  = __reduce_max_sync(FULL, db);
                        bool tie    = (db == m);
                        unsigned mi2 = __reduce_max_sync(FULL, tie ? ki : 0u);
                        tml = __ffs(__ballot_sync(FULL, tie && ki == mi2)) - 1;
                        tmd = __uint_as_float(m); tmi = mi2;
                    }
                }
            }
        }
        __syncthreads();   // scan done before next overwrite of buf
    }

    // ---- angles: angle = 2*atan2(sqrt(t - a.b), sqrt(t + a.b)), t=|a||b| ----
    float a_own = feat[(size_t)si * FDn + lane];
    float dot = 0.f, an2 = 0.f, bn2 = 0.f;
    const float4* frow = (const float4*)(feat + (size_t)ki * FDn);
#pragma unroll
    for (int g = 0; g < FDn / 4; g++) {
        float4 bv = frow[g];
        float a0 = __shfl_sync(FULL, a_own, g * 4 + 0);
        float a1 = __shfl_sync(FULL, a_own, g * 4 + 1);
        float a2 = __shfl_sync(FULL, a_own, g * 4 + 2);
        float a3 = __shfl_sync(FULL, a_own, g * 4 + 3);
        dot = fmaf(a0, bv.x, dot); an2 = fmaf(a0, a0, an2); bn2 = fmaf(bv.x, bv.x, bn2);
        dot = fmaf(a1, bv.y, dot); an2 = fmaf(a1, a1, an2); bn2 = fmaf(bv.y, bv.y, bn2);
        dot = fmaf(a2, bv.z, dot); an2 = fmaf(a2, a2, an2); bn2 = fmaf(bv.z, bv.z, bn2);
        dot = fmaf(a3, bv.w, dot); an2 = fmaf(a3, a3, an2); bn2 = fmaf(bv.w, bv.w, bn2);
    }
    float t = sqrtf(an2) * sqrtf(bn2);
    float ang = 2.f * atan2f(sqrtf(fmaxf(t - dot, 0.f)), sqrtf(fmaxf(t + dot, 0.f)));
    if (ki == (unsigned)si) ang = 0.f;   // self neighbor contributes 0
    float ssum = ang;
#pragma unroll
    for (int o = 16; o; o >>= 1) ssum += __shfl_xor_sync(FULL, ssum, o);
    float pc = ssum / 31.f;

    // ---- outputs (tuple flattened+concatenated as float32) ----
    const int OFF_FEAT = Bn * NGn * 3;
    const int OFF_SW   = OFF_FEAT + Bn * NGn * (FDn + 1);
    const int OFF_LAB  = OFF_SW + Bn * NGn;
    const int OFF_SIDX = OFF_LAB + Bn * NGn;
    if (lane < 3) out[s * 3 + lane] = coord[si * 3 + lane];
    out[OFF_FEAT + s * 33 + lane] = a_own;
    if (lane == 0) {
        out[OFF_FEAT + s * 33 + 32] = pc;
        out[OFF_SW + s]   = pc > 0.087266f ? 1.f : 0.f;
        out[OFF_LAB + s]  = (float)labels[si];
        out[OFF_SIDX + s] = (float)si;
    }
}

// ---------------------------------------------------------------------------
extern "C" void kernel_launch(void* const* d_in, const int* in_sizes, int n_in,
                              void* d_out, int out_size) {
    const float* coord  = (const float*)d_in[0];
    const float* feat   = (const float*)d_in[1];
    const int*   labels = (const int*)d_in[2];
    float* out = (float*)d_out;

    pack_kernel<<<(Bn * Nn / 4 + 255) / 256, 256>>>(coord);

    cudaError_t rc = cudaFuncSetAttribute(
        (const void*)fps_kernel16,
        cudaFuncAttributeNonPortableClusterSizeAllowed, 1);
    if (rc == cudaSuccess) {
        fps_kernel16<<<Bn * 16, 256>>>();
    } else {
        (void)cudaGetLastError();
        fps_kernel8<<<Bn * 8, 1024>>>();
    }

    knn_kernel<<<(Bn * NGn) / 8, 256>>>(coord, feat, labels, out);
}

// round 14
// speedup vs baseline: 1.4082x; 1.0051x over previous
#include <cuda_runtime.h>
#include <cstdint>

#define Bn   8
#define Nn   32768
#define FDn  32
#define NGn  1024
#define KCHUNK 2048   // kNN tile (points) per buffer

typedef unsigned long long u64;

// Scratch (no allocations allowed)
__device__ u64    g_px[Bn * Nn / 2];        // pair-SoA: {x[2i], x[2i+1]}
__device__ u64    g_py[Bn * Nn / 2];
__device__ u64    g_pz[Bn * Nn / 2];
__device__ float4 g_packed[Bn * Nn];        // used by fallback path only
__device__ int    g_sidx[Bn * NGn];         // FPS-selected global point idx

// Exact (non-FMA, left-to-right) squared distance == XLA sum((a-b)**2) f32.
__device__ __forceinline__ float d2f(float ax, float ay, float az,
                                     float bx, float by, float bz) {
    float dx = ax - bx, dy = ay - by, dz = az - bz;
    return __fadd_rn(__fadd_rn(__fmul_rn(dx, dx), __fmul_rn(dy, dy)),
                     __fmul_rn(dz, dz));
}

// ---------------------------------------------------------------------------
// small PTX helpers
// ---------------------------------------------------------------------------
__device__ __forceinline__ uint32_t s2u(const void* p) {
    return (uint32_t)__cvta_generic_to_shared(p);
}
__device__ __forceinline__ uint32_t ctarank() {
    uint32_t r; asm("mov.u32 %0, %%cluster_ctarank;" : "=r"(r)); return r;
}
__device__ __forceinline__ uint32_t mapa_u32(uint32_t addr, uint32_t rank) {
    uint32_t r;
    asm("mapa.shared::cluster.u32 %0, %1, %2;" : "=r"(r) : "r"(addr), "r"(rank));
    return r;
}
__device__ __forceinline__ void st_async_u64(uint32_t raddr, u64 v, uint32_t rmbar) {
    asm volatile("st.async.shared::cluster.mbarrier::complete_tx::bytes.u64 [%0], %1, [%2];"
                 :: "r"(raddr), "l"(v), "r"(rmbar) : "memory");
}
__device__ __forceinline__ void st_async_u32(uint32_t raddr, uint32_t v, uint32_t rmbar) {
    asm volatile("st.async.shared::cluster.mbarrier::complete_tx::bytes.u32 [%0], %1, [%2];"
                 :: "r"(raddr), "r"(v), "r"(rmbar) : "memory");
}
__device__ __forceinline__ void mbar_init(uint32_t addr, uint32_t cnt) {
    asm volatile("mbarrier.init.shared.b64 [%0], %1;" :: "r"(addr), "r"(cnt) : "memory");
}
__device__ __forceinline__ void mbar_expect_tx(uint32_t addr, uint32_t bytes) {
    asm volatile("mbarrier.arrive.expect_tx.shared.b64 _, [%0], %1;"
                 :: "r"(addr), "r"(bytes) : "memory");
}
__device__ __forceinline__ void mbar_wait_parity(uint32_t addr, uint32_t parity) {
    uint32_t done;
    asm volatile("{\n\t.reg .pred p;\n\t"
                 "mbarrier.try_wait.parity.acquire.cta.shared::cta.b64 p, [%1], %2;\n\t"
                 "selp.b32 %0, 1, 0, p;\n\t}"
                 : "=r"(done) : "r"(addr), "r"(parity) : "memory");
    while (!done) {
        asm volatile("{\n\t.reg .pred p;\n\t"
                     "mbarrier.try_wait.parity.acquire.cta.shared::cta.b64 p, [%1], %2, 0x989680;\n\t"
                     "selp.b32 %0, 1, 0, p;\n\t}"
                     : "=r"(done) : "r"(addr), "r"(parity) : "memory");
    }
}
__device__ __forceinline__ void cluster_sync_asm() {
    asm volatile("barrier.cluster.arrive.aligned;" ::: "memory");
    asm volatile("barrier.cluster.wait.aligned;" ::: "memory");
}
__device__ __forceinline__ void cp_async16(uint32_t saddr, const void* gaddr) {
    asm volatile("cp.async.cg.shared.global [%0], [%1], 16;"
                 :: "r"(saddr), "l"(gaddr) : "memory");
}
__device__ __forceinline__ void cp_commit() {
    asm volatile("cp.async.commit_group;" ::: "memory");
}
template<int N>
__device__ __forceinline__ void cp_wait() {
    asm volatile("cp.async.wait_group %0;" :: "n"(N) : "memory");
}
// packed f32x2 (sm_103a): add/mul only — IEEE-rn per lane, bit-exact vs scalar
__device__ __forceinline__ u64 addx2(u64 a, u64 b) {
    u64 r; asm("add.rn.f32x2 %0, %1, %2;" : "=l"(r) : "l"(a), "l"(b)); return r;
}
__device__ __forceinline__ u64 mulx2(u64 a, u64 b) {
    u64 r; asm("mul.rn.f32x2 %0, %1, %2;" : "=l"(r) : "l"(a), "l"(b)); return r;
}
__device__ __forceinline__ u64 packx2(float lo, float hi) {
    u64 r; asm("mov.b64 %0, {%1, %2};" : "=l"(r) : "f"(lo), "f"(hi)); return r;
}
__device__ __forceinline__ void unpackx2(float& lo, float& hi, u64 v) {
    asm("mov.b64 {%0, %1}, %2;" : "=f"(lo), "=f"(hi) : "l"(v));
}

// ---------------------------------------------------------------------------
// pack kernel: FALLBACK PATH ONLY (fps_kernel8 consumes g_packed)
// ---------------------------------------------------------------------------
__global__ void pack_kernel(const float* __restrict__ coord) {
    int t = blockIdx.x * blockDim.x + threadIdx.x;   // points 4t..4t+3
    if (t * 4 >= Bn * Nn) return;
    const float4* c4 = (const float4*)(coord + (size_t)t * 12);
    float4 a = c4[0], b = c4[1], c = c4[2];
    g_packed[t * 4 + 0] = make_float4(a.x, a.y, a.z, 0.f);
    g_packed[t * 4 + 1] = make_float4(a.w, b.x, b.y, 0.f);
    g_packed[t * 4 + 2] = make_float4(b.z, b.w, c.x, 0.f);
    g_packed[t * 4 + 3] = make_float4(c.y, c.z, c.w, 0.f);
    g_px[2 * t]     = packx2(a.x, a.w);
    g_px[2 * t + 1] = packx2(b.z, c.y);
    g_py[2 * t]     = packx2(a.y, b.x);
    g_py[2 * t + 1] = packx2(b.w, c.z);
    g_pz[2 * t]     = packx2(a.z, b.y);
    g_pz[2 * t + 1] = packx2(c.x, c.w);
}

// ---------------------------------------------------------------------------
// FPS (R7-proven loop). Cluster of 16 CTAs x 256 thr x 8 pts/thread per
// batch. Prologue packs coord directly (registers + smem tile + pair-SoA
// g_px/g_py/g_pz for kNN) — no separate pack kernel, no g_packed. Exchange
// ships ONLY {d2,x,y,z} (2 st.async.u64); the WINNING CTA resolves the
// winner index locally (its warp0 kept ci in a register) and writes g_sidx —
// index traffic is off the critical path. redux-only argmax at every level
// (jnp.argmax smallest-index tie-break: lane/slot/rank order == index order).
// ---------------------------------------------------------------------------
__global__ void __cluster_dims__(16, 1, 1) __launch_bounds__(256, 1)
fps_kernel16(const float* __restrict__ coord) {
    constexpr int C = 16, T = 256, P = 8;
    constexpr int NW = T / 32;            // 8 warps
    constexpr int PTS = T * P;            // 2048 points per CTA
    constexpr uint32_t TXB = 16u * C;     // bytes per exchange phase

    __shared__ __align__(16) float4 tile[PTS];          // 32KB coord tile
    __shared__ u64 slotK[NW];                            // {d2bits, ~idx}
    __shared__ __align__(16) float4 cand4[2][C];         // {d2, x, y, z}
    __shared__ u64 mbarrier_s[2];

    const unsigned FULL = 0xffffffffu;
    int tid = threadIdx.x, lane = tid & 31, wid = tid >> 5;
    uint32_t rank = ctarank();
    int b = blockIdx.x / C;
    uint32_t local_base = rank * PTS + (uint32_t)tid * P;
    int gpt = b * Nn + (int)local_base;   // first global point of this thread

    uint32_t mb0 = s2u(&mbarrier_s[0]), mb1 = s2u(&mbarrier_s[1]);
    if (tid == 0) { mbar_init(mb0, 1); mbar_init(mb1, 1); }

    // hoisted remote addresses (warp0 only)
    uint32_t rC4[2], rMB[2];
    if (wid == 0 && lane < C) {
#pragma unroll
        for (int q = 0; q < 2; q++) {
            rC4[q] = mapa_u32(s2u(&cand4[q][rank]), (uint32_t)lane);
            rMB[q] = mapa_u32(q ? mb1 : mb0, (uint32_t)lane);
        }
    }

    float dist[P];
    u64 pxp[P / 2], pyp[P / 2], pzp[P / 2];
    {
        // load 8 points (24 floats = 6 float4, coalesced) straight from coord
        const float4* c4 = (const float4*)(coord + (size_t)gpt * 3);
        float f[24];
#pragma unroll
        for (int q = 0; q < 6; q++) {
            float4 v = c4[q];
            f[4 * q] = v.x; f[4 * q + 1] = v.y; f[4 * q + 2] = v.z; f[4 * q + 3] = v.w;
        }
        float px[P], py[P], pz[P];
#pragma unroll
        for (int j = 0; j < P; j++) {
            px[j] = f[3 * j]; py[j] = f[3 * j + 1]; pz[j] = f[3 * j + 2];
            tile[tid * P + j] = make_float4(px[j], py[j], pz[j], 0.f);
        }
#pragma unroll
        for (int p = 0; p < P / 2; p++) {
            pxp[p] = packx2(px[2 * p], px[2 * p + 1]);
            pyp[p] = packx2(py[2 * p], py[2 * p + 1]);
            pzp[p] = packx2(pz[2 * p], pz[2 * p + 1]);
            g_px[gpt / 2 + p] = pxp[p];
            g_py[gpt / 2 + p] = pyp[p];
            g_pz[gpt / 2 + p] = pzp[p];
        }
        float p0x = coord[(size_t)b * Nn * 3];
        float p0y = coord[(size_t)b * Nn * 3 + 1];
        float p0z = coord[(size_t)b * Nn * 3 + 2];
#pragma unroll
        for (int j = 0; j < P; j++)
            dist[j] = d2f(px[j], py[j], pz[j], p0x, p0y, p0z);
    }
    float bd = dist[0];
#pragma unroll
    for (int j = 1; j < P; j++) bd = fmaxf(bd, dist[j]);
    if (rank == 0 && tid == 0) g_sidx[b * NGn + 0] = b * Nn;

    __syncthreads();
    cluster_sync_asm();   // mbarriers + tiles ready before any st.async

    uint32_t my_ci = 0;   // warp0: this CTA's candidate idx for current k
    for (int k = 1; k < NGn; k++) {
        int kb = k & 1;
        uint32_t parity = (uint32_t)(((k - 1) >> 1) & 1);
        uint32_t mbk = kb ? mb1 : mb0;
        if (tid == 0) mbar_expect_tx(mbk, TXB);

        // smallest j with dist[j] == bd (jnp.argmax tie-break)
        int bj = P - 1;
#pragma unroll
        for (int j = P - 2; j >= 0; j--) bj = (dist[j] == bd) ? j : bj;
        uint32_t myinv = 0xFFFFFFFFu - (local_base + (uint32_t)bj);

        // warp argmax: redux(d2) then redux(~idx among tied)
        uint32_t dbits = __float_as_uint(bd);
        uint32_t wmax  = __reduce_max_sync(FULL, dbits);
        uint32_t inv   = (dbits == wmax) ? myinv : 0u;
        uint32_t winv  = __reduce_max_sync(FULL, inv);
        if (lane == 0) slotK[wid] = ((u64)wmax << 32) | winv;
        __syncthreads();

        if (wid == 0) {
            u64 k0 = slotK[lane & (NW - 1)];
            uint32_t hi = (lane < NW) ? (uint32_t)(k0 >> 32) : 0u;
            uint32_t hm = __reduce_max_sync(FULL, hi);
            uint32_t lo = (hi == hm) ? (uint32_t)k0 : 0u;
            uint32_t lm = __reduce_max_sync(FULL, lo);
            my_ci = 0xFFFFFFFFu - lm;               // batch-local winner idx
            float4 w = tile[my_ci & (PTS - 1)];     // broadcast LDS.128
            if (lane < C) {
                st_async_u64(rC4[kb],
                             ((u64)__float_as_uint(w.x) << 32) | hm, rMB[kb]);
                st_async_u64(rC4[kb] + 8,
                             ((u64)__float_as_uint(w.z) << 32)
                             | __float_as_uint(w.y), rMB[kb]);
            }
        }

        mbar_wait_parity(mbk, parity);

        // cluster pick: lane r holds candidate of CTA r (one LDS.128);
        // winner broadcast via 3-shfl chain (R7-proven form)
        int cl = lane & (C - 1);
        float4 cv = cand4[kb][cl];     // {d2, x, y, z}
        uint32_t d = (lane < C) ? __float_as_uint(cv.x) : 0u;
        uint32_t m = __reduce_max_sync(FULL, d);
        int src = __ffs(__ballot_sync(FULL, d == m)) - 1;  // smallest rank==idx
        float gx = __shfl_sync(FULL, cv.y, src);
        float gy = __shfl_sync(FULL, cv.z, src);
        float gz = __shfl_sync(FULL, cv.w, src);
        // winning CTA resolves index locally (off the critical path)
        if (wid == 0 && lane == 0 && src == (int)rank)
            g_sidx[b * NGn + k] = b * Nn + (int)my_ci;

        // packed-f32x2 dist update (pre-negated winner), scalar min/max
        u64 ngx = packx2(-gx, -gx);
        u64 ngy = packx2(-gy, -gy);
        u64 ngz = packx2(-gz, -gz);
        bd = -1.f;
#pragma unroll
        for (int p = 0; p < P / 2; p++) {
            u64 dx = addx2(pxp[p], ngx);
            u64 dy = addx2(pyp[p], ngy);
            u64 dz = addx2(pzp[p], ngz);
            u64 s = addx2(addx2(mulx2(dx, dx), mulx2(dy, dy)), mulx2(dz, dz));
            float s0, s1; unpackx2(s0, s1, s);
            float m0 = fminf(dist[2 * p], s0);
            float m1 = fminf(dist[2 * p + 1], s1);
            dist[2 * p] = m0; dist[2 * p + 1] = m1;
            bd = fmaxf(bd, m0); bd = fmaxf(bd, m1);
        }
    }
}

// ---------------------------------------------------------------------------
// FPS fallback (cluster 8 x 1024, P=4; uses g_packed from pack_kernel).
// ---------------------------------------------------------------------------
__global__ void __cluster_dims__(8, 1, 1) __launch_bounds__(1024, 1)
fps_kernel8() {
    constexpr int C = 8, T = 1024, P = 4;
    constexpr int NW = T / 32;
    constexpr int PTS = T * P;
    constexpr uint32_t TXB = 20u * C;

    __shared__ uint32_t slotD[NW], slotI[NW];
    __shared__ float    slotX[NW], slotY[NW], slotZ[NW];
    __shared__ u64      candDI[2][C];
    __shared__ u64      candXY[2][C];
    __shared__ uint32_t candZ[2][C];
    __shared__ u64      mbarrier_s[2];

    const unsigned FULL = 0xffffffffu;
    int tid = threadIdx.x, lane = tid & 31, wid = tid >> 5;
    uint32_t rank = ctarank();
    int b = blockIdx.x / C;
    uint32_t local_base = rank * PTS + (uint32_t)tid * P;
    int gbase = b * Nn + (int)local_base;

    uint32_t mb0 = s2u(&mbarrier_s[0]), mb1 = s2u(&mbarrier_s[1]);
    if (tid == 0) { mbar_init(mb0, 1); mbar_init(mb1, 1); }

    uint32_t rDI[2], rXY[2], rZ[2], rMB[2];
    if (wid == 0 && lane < C) {
#pragma unroll
        for (int q = 0; q < 2; q++) {
            rDI[q] = mapa_u32(s2u(&candDI[q][rank]), (uint32_t)lane);
            rXY[q] = mapa_u32(s2u(&candXY[q][rank]), (uint32_t)lane);
            rZ[q]  = mapa_u32(s2u(&candZ[q][rank]),  (uint32_t)lane);
            rMB[q] = mapa_u32(q ? mb1 : mb0, (uint32_t)lane);
        }
    }

    float px[P], py[P], pz[P], dist[P];
#pragma unroll
    for (int j = 0; j < P; j++) {
        float4 q = g_packed[gbase + j];
        px[j] = q.x; py[j] = q.y; pz[j] = q.z;
    }

    float4 p0 = g_packed[b * Nn];
    float bd = -1.f; int bj = 0;
#pragma unroll
    for (int j = 0; j < P; j++) {
        float d = d2f(px[j], py[j], pz[j], p0.x, p0.y, p0.z);
        dist[j] = d;
        if (d > bd) { bd = d; bj = j; }
    }
    if (rank == 0 && tid == 0) g_sidx[b * NGn + 0] = b * Nn;

    __syncthreads();
    cluster_sync_asm();

    for (int k = 1; k < NGn; k++) {
        int kb = k & 1;
        uint32_t parity = (uint32_t)(((k - 1) >> 1) & 1);
        uint32_t mbk = kb ? mb1 : mb0;
        if (tid == 0) mbar_expect_tx(mbk, TXB);

        float cx, cy, cz;
        {
            int j = bj;
            float x01 = (j & 1) ? px[1] : px[0], x23 = (j & 1) ? px[3] : px[2];
            float y01 = (j & 1) ? py[1] : py[0], y23 = (j & 1) ? py[3] : py[2];
            float z01 = (j & 1) ? pz[1] : pz[0], z23 = (j & 1) ? pz[3] : pz[2];
            cx = (j & 2) ? x23 : x01; cy = (j & 2) ? y23 : y01; cz = (j & 2) ? z23 : z01;
        }
        uint32_t myidx = local_base + (uint32_t)bj;

        uint32_t dbits = __float_as_uint(bd);
        uint32_t wmax  = __reduce_max_sync(FULL, dbits);
        int wsrc = __ffs(__ballot_sync(FULL, dbits == wmax)) - 1;
        uint32_t widx = __shfl_sync(FULL, myidx, wsrc);
        float wx = __shfl_sync(FULL, cx, wsrc);
        float wy = __shfl_sync(FULL, cy, wsrc);
        float wz = __shfl_sync(FULL, cz, wsrc);
        if (lane == 0) {
            slotD[wid] = wmax; slotI[wid] = widx;
            slotX[wid] = wx; slotY[wid] = wy; slotZ[wid] = wz;
        }
        __syncthreads();

        if (wid == 0) {
            int sl = lane & (NW - 1);
            uint32_t d = (lane < NW) ? slotD[sl] : 0u;
            uint32_t i = slotI[sl];
            float x = slotX[sl], y = slotY[sl], z = slotZ[sl];
            uint32_t m = __reduce_max_sync(FULL, d);
            int src = __ffs(__ballot_sync(FULL, d == m)) - 1;
            uint32_t ci = __shfl_sync(FULL, i, src);
            float fx = __shfl_sync(FULL, x, src);
            float fy = __shfl_sync(FULL, y, src);
            float fz = __shfl_sync(FULL, z, src);
            if (lane < C) {
                st_async_u64(rDI[kb], ((u64)m << 32) | ci, rMB[kb]);
                st_async_u64(rXY[kb],
                             ((u64)__float_as_uint(fy) << 32) | __float_as_uint(fx),
                             rMB[kb]);
                st_async_u32(rZ[kb], __float_as_uint(fz), rMB[kb]);
            }
        }

        mbar_wait_parity(mbk, parity);

        int cl = lane & (C - 1);
        u64 di = candDI[kb][cl];
        u64 xy = candXY[kb][cl];
        uint32_t zz = candZ[kb][cl];
        uint32_t d = (lane < C) ? (uint32_t)(di >> 32) : 0u;
        uint32_t m = __reduce_max_sync(FULL, d);
        int src = __ffs(__ballot_sync(FULL, d == m)) - 1;
        uint32_t wl = __shfl_sync(FULL, (uint32_t)di, src);
        u64 wxy = __shfl_sync(FULL, xy, src);
        uint32_t wzb = __shfl_sync(FULL, zz, src);
        float gx = __uint_as_float((uint32_t)wxy);
        float gy = __uint_as_float((uint32_t)(wxy >> 32));
        float gz = __uint_as_float(wzb);
        if (rank == 0 && tid == 0) g_sidx[b * NGn + k] = b * Nn + (int)wl;

        bd = -1.f; bj = 0;
#pragma unroll
        for (int j = 0; j < P; j++) {
            float nd = d2f(px[j], py[j], pz[j], gx, gy, gz);
            float mn = fminf(dist[j], nd);
            dist[j] = mn;
            if (mn > bd) { bd = mn; bj = j; }
        }
    }
}

// ---------------------------------------------------------------------------
// kNN (top-32 by (d2, idx) lex order) + angle/curvature + outputs.
// 256 threads = 8 warps = 8 samples/CTA, grid 1024 (4 CTAs/SM co-resident).
// Wide scan: 128 points/group via ulonglong2 LDS.128 on pair-SoA tiles,
// one combined early-skip ballot gating four insertion masks.
// ---------------------------------------------------------------------------
__global__ void __launch_bounds__(256, 1)
knn_kernel(const float* __restrict__ coord, const float* __restrict__ feat,
           const int* __restrict__ labels, float* __restrict__ out) {
    __shared__ __align__(16) u64 scx[2][KCHUNK / 2];
    __shared__ __align__(16) u64 scy[2][KCHUNK / 2];
    __shared__ __align__(16) u64 scz[2][KCHUNK / 2];
    const unsigned FULL = 0xffffffffu;
    int tid = threadIdx.x, lane = tid & 31, wid = tid >> 5;
    int s = blockIdx.x * 8 + wid;    // sample id [0, 8192)
    int b = s >> 10;                 // batch
    int si = g_sidx[s];
    const float* cp = coord + (size_t)si * 3;
    float spx = cp[0], spy = cp[1], spz = cp[2];
    u64 nspx = packx2(-spx, -spx);
    u64 nspy = packx2(-spy, -spy);
    u64 nspz = packx2(-spz, -spz);

    float kd = 3.4028235e38f; unsigned ki = 0xffffffffu;    // kept (per lane)
    float tmd = 3.4028235e38f; unsigned tmi = 0xffffffffu; int tml = 0;

    constexpr int NT = Nn / KCHUNK;      // 16 tiles
    int pbase = b * (Nn / 2);
    // 256 threads stage 1024 u64 per axis: 4 u64 (2 cp.async16) per thread
    auto stage = [&](int buf, int c) {
        int po = pbase + c * (KCHUNK / 2) + tid * 4;
        uint32_t o = (uint32_t)tid * 32;
        cp_async16(s2u(&scx[buf][0]) + o,      &g_px[po]);
        cp_async16(s2u(&scx[buf][0]) + o + 16, &g_px[po + 2]);
        cp_async16(s2u(&scy[buf][0]) + o,      &g_py[po]);
        cp_async16(s2u(&scy[buf][0]) + o + 16, &g_py[po + 2]);
        cp_async16(s2u(&scz[buf][0]) + o,      &g_pz[po]);
        cp_async16(s2u(&scz[buf][0]) + o + 16, &g_pz[po + 2]);
        cp_commit();
    };
    stage(0, 0);
    for (int c = 0; c < NT; c++) {
        int buf = c & 1;
        if (c + 1 < NT) { stage(buf ^ 1, c + 1); cp_wait<1>(); }
        else           { cp_wait<0>(); }
        __syncthreads();
        int cbase = b * Nn + c * KCHUNK;
        const ulonglong2* sx2 = (const ulonglong2*)scx[buf];
        const ulonglong2* sy2 = (const ulonglong2*)scy[buf];
        const ulonglong2* sz2 = (const ulonglong2*)scz[buf];
        for (int j = 0; j < KCHUNK / 128; j++) {         // 16 groups of 128
            int pi = j * 32 + lane;
            ulonglong2 vx = sx2[pi], vy = sy2[pi], vz = sz2[pi];
            u64 dx0 = addx2(vx.x, nspx), dx1 = addx2(vx.y, nspx);
            u64 dy0 = addx2(vy.x, nspy), dy1 = addx2(vy.y, nspy);
            u64 dz0 = addx2(vz.x, nspz), dz1 = addx2(vz.y, nspz);
            u64 s0 = addx2(addx2(mulx2(dx0, dx0), mulx2(dy0, dy0)), mulx2(dz0, dz0));
            u64 s1 = addx2(addx2(mulx2(dx1, dx1), mulx2(dy1, dy1)), mulx2(dz1, dz1));
            float dA, dB, dC, dD;
            unpackx2(dA, dB, s0);
            unpackx2(dC, dD, s1);
            int gb = cbase + j * 128;                    // group base point idx
            unsigned giA = (unsigned)(gb + 4 * lane);
            bool cA = (dA < tmd) || (dA == tmd && giA < tmi);
            bool cB = (dB < tmd) || (dB == tmd && giA + 1 < tmi);
            bool cC = (dC < tmd) || (dC == tmd && giA + 2 < tmi);
            bool cD = (dD < tmd) || (dD == tmd && giA + 3 < tmi);
            if (__ballot_sync(FULL, cA || cB || cC || cD) == 0u) continue;
            unsigned mA = __ballot_sync(FULL, cA);
            unsigned mB = __ballot_sync(FULL, cB);
            unsigned mC = __ballot_sync(FULL, cC);
            unsigned mD = __ballot_sync(FULL, cD);
#pragma unroll
            for (int h = 0; h < 4; h++) {
                unsigned mm = (h == 0) ? mA : (h == 1) ? mB : (h == 2) ? mC : mD;
                float dv = (h == 0) ? dA : (h == 1) ? dB : (h == 2) ? dC : dD;
                while (mm) {
                    int ins = __ffs(mm) - 1; mm &= mm - 1;
                    float cd = __shfl_sync(FULL, dv, ins);
                    unsigned cgi = (unsigned)(gb + 4 * ins + h);
                    if ((cd < tmd) || (cd == tmd && cgi < tmi)) {
                        if (lane == tml) { kd = cd; ki = cgi; }
                        unsigned db = __float_as_uint(kd);
                        unsigned m  = __reduce_max_sync(FULL, db);
                        bool tie    = (db == m);
                        unsigned mi2 = __reduce_max_sync(FULL, tie ? ki : 0u);
                        tml = __ffs(__ballot_sync(FULL, tie && ki == mi2)) - 1;
                        tmd = __uint_as_float(m); tmi = mi2;
                    }
                }
            }
        }
        __syncthreads();   // scan done before next overwrite of buf
    }

    // ---- angles: angle = 2*atan2(sqrt(t - a.b), sqrt(t + a.b)), t=|a||b| ----
    float a_own = feat[(size_t)si * FDn + lane];
    float dot = 0.f, an2 = 0.f, bn2 = 0.f;
    const float4* frow = (const float4*)(feat + (size_t)ki * FDn);
#pragma unroll
    for (int g = 0; g < FDn / 4; g++) {
        float4 bv = frow[g];
        float a0 = __shfl_sync(FULL, a_own, g * 4 + 0);
        float a1 = __shfl_sync(FULL, a_own, g * 4 + 1);
        float a2 = __shfl_sync(FULL, a_own, g * 4 + 2);
        float a3 = __shfl_sync(FULL, a_own, g * 4 + 3);
        dot = fmaf(a0, bv.x, dot); an2 = fmaf(a0, a0, an2); bn2 = fmaf(bv.x, bv.x, bn2);
        dot = fmaf(a1, bv.y, dot); an2 = fmaf(a1, a1, an2); bn2 = fmaf(bv.y, bv.y, bn2);
        dot = fmaf(a2, bv.z, dot); an2 = fmaf(a2, a2, an2); bn2 = fmaf(bv.z, bv.z, bn2);
        dot = fmaf(a3, bv.w, dot); an2 = fmaf(a3, a3, an2); bn2 = fmaf(bv.w, bv.w, bn2);
    }
    float t = sqrtf(an2) * sqrtf(bn2);
    float ang = 2.f * atan2f(sqrtf(fmaxf(t - dot, 0.f)), sqrtf(fmaxf(t + dot, 0.f)));
    if (ki == (unsigned)si) ang = 0.f;   // self neighbor contributes 0
    float ssum = ang;
#pragma unroll
    for (int o = 16; o; o >>= 1) ssum += __shfl_xor_sync(FULL, ssum, o);
    float pc = ssum / 31.f;

    // ---- outputs (tuple flattened+concatenated as float32) ----
    const int OFF_FEAT = Bn * NGn * 3;
    const int OFF_SW   = OFF_FEAT + Bn * NGn * (FDn + 1);
    const int OFF_LAB  = OFF_SW + Bn * NGn;
    const int OFF_SIDX = OFF_LAB + Bn * NGn;
    if (lane < 3) out[s * 3 + lane] = coord[si * 3 + lane];
    out[OFF_FEAT + s * 33 + lane] = a_own;
    if (lane == 0) {
        out[OFF_FEAT + s * 33 + 32] = pc;
        out[OFF_SW + s]   = pc > 0.087266f ? 1.f : 0.f;
        out[OFF_LAB + s]  = (float)labels[si];
        out[OFF_SIDX + s] = (float)si;
    }
}

// ---------------------------------------------------------------------------
extern "C" void kernel_launch(void* const* d_in, const int* in_sizes, int n_in,
                              void* d_out, int out_size) {
    const float* coord  = (const float*)d_in[0];
    const float* feat   = (const float*)d_in[1];
    const int*   labels = (const int*)d_in[2];
    float* out = (float*)d_out;

    cudaError_t rc = cudaFuncSetAttribute(
        (const void*)fps_kernel16,
        cudaFuncAttributeNonPortableClusterSizeAllowed, 1);
    if (rc == cudaSuccess) {
        fps_kernel16<<<Bn * 16, 256>>>(coord);   // packs g_px/g_py/g_pz itself
    } else {
        (void)cudaGetLastError();
        pack_kernel<<<(Bn * Nn / 4 + 255) / 256, 256>>>(coord);
        fps_kernel8<<<Bn * 8, 1024>>>();
    }

    knn_kernel<<<(Bn * NGn) / 8, 256>>>(coord, feat, labels, out);
}

// round 15
// speedup vs baseline: 1.4951x; 1.0617x over previous
#include <cuda_runtime.h>
#include <cstdint>

#define Bn   8
#define Nn   32768
#define FDn  32
#define NGn  1024
#define KCHUNK 1024   // kNN tile (points) per buffer (24KB/CTA -> 8 CTAs/SM)

typedef unsigned long long u64;

// Scratch (no allocations allowed)
__device__ u64    g_px[Bn * Nn / 2];        // pair-SoA: {x[2i], x[2i+1]}
__device__ u64    g_py[Bn * Nn / 2];
__device__ u64    g_pz[Bn * Nn / 2];
__device__ float4 g_packed[Bn * Nn];        // used by fallback path only
__device__ int    g_sidx[Bn * NGn];         // FPS-selected global point idx

// Exact (non-FMA, left-to-right) squared distance == XLA sum((a-b)**2) f32.
__device__ __forceinline__ float d2f(float ax, float ay, float az,
                                     float bx, float by, float bz) {
    float dx = ax - bx, dy = ay - by, dz = az - bz;
    return __fadd_rn(__fadd_rn(__fmul_rn(dx, dx), __fmul_rn(dy, dy)),
                     __fmul_rn(dz, dz));
}

// ---------------------------------------------------------------------------
// small PTX helpers
// ---------------------------------------------------------------------------
__device__ __forceinline__ uint32_t s2u(const void* p) {
    return (uint32_t)__cvta_generic_to_shared(p);
}
__device__ __forceinline__ uint32_t ctarank() {
    uint32_t r; asm("mov.u32 %0, %%cluster_ctarank;" : "=r"(r)); return r;
}
__device__ __forceinline__ uint32_t mapa_u32(uint32_t addr, uint32_t rank) {
    uint32_t r;
    asm("mapa.shared::cluster.u32 %0, %1, %2;" : "=r"(r) : "r"(addr), "r"(rank));
    return r;
}
__device__ __forceinline__ void st_async_u64(uint32_t raddr, u64 v, uint32_t rmbar) {
    asm volatile("st.async.shared::cluster.mbarrier::complete_tx::bytes.u64 [%0], %1, [%2];"
                 :: "r"(raddr), "l"(v), "r"(rmbar) : "memory");
}
__device__ __forceinline__ void st_async_u32(uint32_t raddr, uint32_t v, uint32_t rmbar) {
    asm volatile("st.async.shared::cluster.mbarrier::complete_tx::bytes.u32 [%0], %1, [%2];"
                 :: "r"(raddr), "r"(v), "r"(rmbar) : "memory");
}
__device__ __forceinline__ void mbar_init(uint32_t addr, uint32_t cnt) {
    asm volatile("mbarrier.init.shared.b64 [%0], %1;" :: "r"(addr), "r"(cnt) : "memory");
}
__device__ __forceinline__ void mbar_expect_tx(uint32_t addr, uint32_t bytes) {
    asm volatile("mbarrier.arrive.expect_tx.shared.b64 _, [%0], %1;"
                 :: "r"(addr), "r"(bytes) : "memory");
}
__device__ __forceinline__ void mbar_wait_parity(uint32_t addr, uint32_t parity) {
    uint32_t done;
    asm volatile("{\n\t.reg .pred p;\n\t"
                 "mbarrier.try_wait.parity.acquire.cta.shared::cta.b64 p, [%1], %2;\n\t"
                 "selp.b32 %0, 1, 0, p;\n\t}"
                 : "=r"(done) : "r"(addr), "r"(parity) : "memory");
    while (!done) {
        asm volatile("{\n\t.reg .pred p;\n\t"
                     "mbarrier.try_wait.parity.acquire.cta.shared::cta.b64 p, [%1], %2, 0x989680;\n\t"
                     "selp.b32 %0, 1, 0, p;\n\t}"
                     : "=r"(done) : "r"(addr), "r"(parity) : "memory");
    }
}
__device__ __forceinline__ void cluster_sync_asm() {
    asm volatile("barrier.cluster.arrive.aligned;" ::: "memory");
    asm volatile("barrier.cluster.wait.aligned;" ::: "memory");
}
__device__ __forceinline__ void cp_async16(uint32_t saddr, const void* gaddr) {
    asm volatile("cp.async.cg.shared.global [%0], [%1], 16;"
                 :: "r"(saddr), "l"(gaddr) : "memory");
}
__device__ __forceinline__ void cp_commit() {
    asm volatile("cp.async.commit_group;" ::: "memory");
}
template<int N>
__device__ __forceinline__ void cp_wait() {
    asm volatile("cp.async.wait_group %0;" :: "n"(N) : "memory");
}
// packed f32x2 (sm_103a): add/mul only — IEEE-rn per lane, bit-exact vs scalar
__device__ __forceinline__ u64 addx2(u64 a, u64 b) {
    u64 r; asm("add.rn.f32x2 %0, %1, %2;" : "=l"(r) : "l"(a), "l"(b)); return r;
}
__device__ __forceinline__ u64 mulx2(u64 a, u64 b) {
    u64 r; asm("mul.rn.f32x2 %0, %1, %2;" : "=l"(r) : "l"(a), "l"(b)); return r;
}
__device__ __forceinline__ u64 packx2(float lo, float hi) {
    u64 r; asm("mov.b64 %0, {%1, %2};" : "=l"(r) : "f"(lo), "f"(hi)); return r;
}
__device__ __forceinline__ void unpackx2(float& lo, float& hi, u64 v) {
    asm("mov.b64 {%0, %1}, %2;" : "=f"(lo), "=f"(hi) : "l"(v));
}

// ---------------------------------------------------------------------------
// pack kernel: FALLBACK PATH ONLY (fps_kernel8 consumes g_packed)
// ---------------------------------------------------------------------------
__global__ void pack_kernel(const float* __restrict__ coord) {
    int t = blockIdx.x * blockDim.x + threadIdx.x;   // points 4t..4t+3
    if (t * 4 >= Bn * Nn) return;
    const float4* c4 = (const float4*)(coord + (size_t)t * 12);
    float4 a = c4[0], b = c4[1], c = c4[2];
    g_packed[t * 4 + 0] = make_float4(a.x, a.y, a.z, 0.f);
    g_packed[t * 4 + 1] = make_float4(a.w, b.x, b.y, 0.f);
    g_packed[t * 4 + 2] = make_float4(b.z, b.w, c.x, 0.f);
    g_packed[t * 4 + 3] = make_float4(c.y, c.z, c.w, 0.f);
    g_px[2 * t]     = packx2(a.x, a.w);
    g_px[2 * t + 1] = packx2(b.z, c.y);
    g_py[2 * t]     = packx2(a.y, b.x);
    g_py[2 * t + 1] = packx2(b.w, c.z);
    g_pz[2 * t]     = packx2(a.z, b.y);
    g_pz[2 * t + 1] = packx2(c.x, c.w);
}

// ---------------------------------------------------------------------------
// FPS (R7-proven loop, R13 prologue). Cluster of 16 CTAs x 256 thr x 8
// pts/thread per batch; packs coord directly into registers + smem tile +
// pair-SoA g_px/g_py/g_pz. Exchange ships ONLY {d2,x,y,z}; the winning CTA
// resolves the winner index locally and writes g_sidx. redux-only argmax
// (jnp.argmax smallest-index tie-break: lane/slot/rank order == index order).
// ---------------------------------------------------------------------------
__global__ void __cluster_dims__(16, 1, 1) __launch_bounds__(256, 1)
fps_kernel16(const float* __restrict__ coord) {
    constexpr int C = 16, T = 256, P = 8;
    constexpr int NW = T / 32;            // 8 warps
    constexpr int PTS = T * P;            // 2048 points per CTA
    constexpr uint32_t TXB = 16u * C;     // bytes per exchange phase

    __shared__ __align__(16) float4 tile[PTS];          // 32KB coord tile
    __shared__ u64 slotK[NW];                            // {d2bits, ~idx}
    __shared__ __align__(16) float4 cand4[2][C];         // {d2, x, y, z}
    __shared__ u64 mbarrier_s[2];

    const unsigned FULL = 0xffffffffu;
    int tid = threadIdx.x, lane = tid & 31, wid = tid >> 5;
    uint32_t rank = ctarank();
    int b = blockIdx.x / C;
    uint32_t local_base = rank * PTS + (uint32_t)tid * P;
    int gpt = b * Nn + (int)local_base;   // first global point of this thread

    uint32_t mb0 = s2u(&mbarrier_s[0]), mb1 = s2u(&mbarrier_s[1]);
    if (tid == 0) { mbar_init(mb0, 1); mbar_init(mb1, 1); }

    // hoisted remote addresses (warp0 only)
    uint32_t rC4[2], rMB[2];
    if (wid == 0 && lane < C) {
#pragma unroll
        for (int q = 0; q < 2; q++) {
            rC4[q] = mapa_u32(s2u(&cand4[q][rank]), (uint32_t)lane);
            rMB[q] = mapa_u32(q ? mb1 : mb0, (uint32_t)lane);
        }
    }

    float dist[P];
    u64 pxp[P / 2], pyp[P / 2], pzp[P / 2];
    {
        // load 8 points (24 floats = 6 float4, coalesced) straight from coord
        const float4* c4 = (const float4*)(coord + (size_t)gpt * 3);
        float f[24];
#pragma unroll
        for (int q = 0; q < 6; q++) {
            float4 v = c4[q];
            f[4 * q] = v.x; f[4 * q + 1] = v.y; f[4 * q + 2] = v.z; f[4 * q + 3] = v.w;
        }
        float px[P], py[P], pz[P];
#pragma unroll
        for (int j = 0; j < P; j++) {
            px[j] = f[3 * j]; py[j] = f[3 * j + 1]; pz[j] = f[3 * j + 2];
            tile[tid * P + j] = make_float4(px[j], py[j], pz[j], 0.f);
        }
#pragma unroll
        for (int p = 0; p < P / 2; p++) {
            pxp[p] = packx2(px[2 * p], px[2 * p + 1]);
            pyp[p] = packx2(py[2 * p], py[2 * p + 1]);
            pzp[p] = packx2(pz[2 * p], pz[2 * p + 1]);
            g_px[gpt / 2 + p] = pxp[p];
            g_py[gpt / 2 + p] = pyp[p];
            g_pz[gpt / 2 + p] = pzp[p];
        }
        float p0x = coord[(size_t)b * Nn * 3];
        float p0y = coord[(size_t)b * Nn * 3 + 1];
        float p0z = coord[(size_t)b * Nn * 3 + 2];
#pragma unroll
        for (int j = 0; j < P; j++)
            dist[j] = d2f(px[j], py[j], pz[j], p0x, p0y, p0z);
    }
    float bd = dist[0];
#pragma unroll
    for (int j = 1; j < P; j++) bd = fmaxf(bd, dist[j]);
    if (rank == 0 && tid == 0) g_sidx[b * NGn + 0] = b * Nn;

    __syncthreads();
    cluster_sync_asm();   // mbarriers + tiles ready before any st.async

    uint32_t my_ci = 0;   // warp0: this CTA's candidate idx for current k
    for (int k = 1; k < NGn; k++) {
        int kb = k & 1;
        uint32_t parity = (uint32_t)(((k - 1) >> 1) & 1);
        uint32_t mbk = kb ? mb1 : mb0;
        if (tid == 0) mbar_expect_tx(mbk, TXB);

        // smallest j with dist[j] == bd (jnp.argmax tie-break)
        int bj = P - 1;
#pragma unroll
        for (int j = P - 2; j >= 0; j--) bj = (dist[j] == bd) ? j : bj;
        uint32_t myinv = 0xFFFFFFFFu - (local_base + (uint32_t)bj);

        // warp argmax: redux(d2) then redux(~idx among tied)
        uint32_t dbits = __float_as_uint(bd);
        uint32_t wmax  = __reduce_max_sync(FULL, dbits);
        uint32_t inv   = (dbits == wmax) ? myinv : 0u;
        uint32_t winv  = __reduce_max_sync(FULL, inv);
        if (lane == 0) slotK[wid] = ((u64)wmax << 32) | winv;
        __syncthreads();

        if (wid == 0) {
            u64 k0 = slotK[lane & (NW - 1)];
            uint32_t hi = (lane < NW) ? (uint32_t)(k0 >> 32) : 0u;
            uint32_t hm = __reduce_max_sync(FULL, hi);
            uint32_t lo = (hi == hm) ? (uint32_t)k0 : 0u;
            uint32_t lm = __reduce_max_sync(FULL, lo);
            my_ci = 0xFFFFFFFFu - lm;               // batch-local winner idx
            float4 w = tile[my_ci & (PTS - 1)];     // broadcast LDS.128
            if (lane < C) {
                st_async_u64(rC4[kb],
                             ((u64)__float_as_uint(w.x) << 32) | hm, rMB[kb]);
                st_async_u64(rC4[kb] + 8,
                             ((u64)__float_as_uint(w.z) << 32)
                             | __float_as_uint(w.y), rMB[kb]);
            }
        }

        mbar_wait_parity(mbk, parity);

        // cluster pick: lane r holds candidate of CTA r (one LDS.128);
        // winner broadcast via 3-shfl chain (R7-proven form)
        int cl = lane & (C - 1);
        float4 cv = cand4[kb][cl];     // {d2, x, y, z}
        uint32_t d = (lane < C) ? __float_as_uint(cv.x) : 0u;
        uint32_t m = __reduce_max_sync(FULL, d);
        int src = __ffs(__ballot_sync(FULL, d == m)) - 1;  // smallest rank==idx
        float gx = __shfl_sync(FULL, cv.y, src);
        float gy = __shfl_sync(FULL, cv.z, src);
        float gz = __shfl_sync(FULL, cv.w, src);
        // winning CTA resolves index locally (off the critical path)
        if (wid == 0 && lane == 0 && src == (int)rank)
            g_sidx[b * NGn + k] = b * Nn + (int)my_ci;

        // packed-f32x2 dist update (pre-negated winner), scalar min/max
        u64 ngx = packx2(-gx, -gx);
        u64 ngy = packx2(-gy, -gy);
        u64 ngz = packx2(-gz, -gz);
        bd = -1.f;
#pragma unroll
        for (int p = 0; p < P / 2; p++) {
            u64 dx = addx2(pxp[p], ngx);
            u64 dy = addx2(pyp[p], ngy);
            u64 dz = addx2(pzp[p], ngz);
            u64 s = addx2(addx2(mulx2(dx, dx), mulx2(dy, dy)), mulx2(dz, dz));
            float s0, s1; unpackx2(s0, s1, s);
            float m0 = fminf(dist[2 * p], s0);
            float m1 = fminf(dist[2 * p + 1], s1);
            dist[2 * p] = m0; dist[2 * p + 1] = m1;
            bd = fmaxf(bd, m0); bd = fmaxf(bd, m1);
        }
    }
}

// ---------------------------------------------------------------------------
// FPS fallback (cluster 8 x 1024, P=4; uses g_packed from pack_kernel).
// ---------------------------------------------------------------------------
__global__ void __cluster_dims__(8, 1, 1) __launch_bounds__(1024, 1)
fps_kernel8() {
    constexpr int C = 8, T = 1024, P = 4;
    constexpr int NW = T / 32;
    constexpr int PTS = T * P;
    constexpr uint32_t TXB = 20u * C;

    __shared__ uint32_t slotD[NW], slotI[NW];
    __shared__ float    slotX[NW], slotY[NW], slotZ[NW];
    __shared__ u64      candDI[2][C];
    __shared__ u64      candXY[2][C];
    __shared__ uint32_t candZ[2][C];
    __shared__ u64      mbarrier_s[2];

    const unsigned FULL = 0xffffffffu;
    int tid = threadIdx.x, lane = tid & 31, wid = tid >> 5;
    uint32_t rank = ctarank();
    int b = blockIdx.x / C;
    uint32_t local_base = rank * PTS + (uint32_t)tid * P;
    int gbase = b * Nn + (int)local_base;

    uint32_t mb0 = s2u(&mbarrier_s[0]), mb1 = s2u(&mbarrier_s[1]);
    if (tid == 0) { mbar_init(mb0, 1); mbar_init(mb1, 1); }

    uint32_t rDI[2], rXY[2], rZ[2], rMB[2];
    if (wid == 0 && lane < C) {
#pragma unroll
        for (int q = 0; q < 2; q++) {
            rDI[q] = mapa_u32(s2u(&candDI[q][rank]), (uint32_t)lane);
            rXY[q] = mapa_u32(s2u(&candXY[q][rank]), (uint32_t)lane);
            rZ[q]  = mapa_u32(s2u(&candZ[q][rank]),  (uint32_t)lane);
            rMB[q] = mapa_u32(q ? mb1 : mb0, (uint32_t)lane);
        }
    }

    float px[P], py[P], pz[P], dist[P];
#pragma unroll
    for (int j = 0; j < P; j++) {
        float4 q = g_packed[gbase + j];
        px[j] = q.x; py[j] = q.y; pz[j] = q.z;
    }

    float4 p0 = g_packed[b * Nn];
    float bd = -1.f; int bj = 0;
#pragma unroll
    for (int j = 0; j < P; j++) {
        float d = d2f(px[j], py[j], pz[j], p0.x, p0.y, p0.z);
        dist[j] = d;
        if (d > bd) { bd = d; bj = j; }
    }
    if (rank == 0 && tid == 0) g_sidx[b * NGn + 0] = b * Nn;

    __syncthreads();
    cluster_sync_asm();

    for (int k = 1; k < NGn; k++) {
        int kb = k & 1;
        uint32_t parity = (uint32_t)(((k - 1) >> 1) & 1);
        uint32_t mbk = kb ? mb1 : mb0;
        if (tid == 0) mbar_expect_tx(mbk, TXB);

        float cx, cy, cz;
        {
            int j = bj;
            float x01 = (j & 1) ? px[1] : px[0], x23 = (j & 1) ? px[3] : px[2];
            float y01 = (j & 1) ? py[1] : py[0], y23 = (j & 1) ? py[3] : py[2];
            float z01 = (j & 1) ? pz[1] : pz[0], z23 = (j & 1) ? pz[3] : pz[2];
            cx = (j & 2) ? x23 : x01; cy = (j & 2) ? y23 : y01; cz = (j & 2) ? z23 : z01;
        }
        uint32_t myidx = local_base + (uint32_t)bj;

        uint32_t dbits = __float_as_uint(bd);
        uint32_t wmax  = __reduce_max_sync(FULL, dbits);
        int wsrc = __ffs(__ballot_sync(FULL, dbits == wmax)) - 1;
        uint32_t widx = __shfl_sync(FULL, myidx, wsrc);
        float wx = __shfl_sync(FULL, cx, wsrc);
        float wy = __shfl_sync(FULL, cy, wsrc);
        float wz = __shfl_sync(FULL, cz, wsrc);
        if (lane == 0) {
            slotD[wid] = wmax; slotI[wid] = widx;
            slotX[wid] = wx; slotY[wid] = wy; slotZ[wid] = wz;
        }
        __syncthreads();

        if (wid == 0) {
            int sl = lane & (NW - 1);
            uint32_t d = (lane < NW) ? slotD[sl] : 0u;
            uint32_t i = slotI[sl];
            float x = slotX[sl], y = slotY[sl], z = slotZ[sl];
            uint32_t m = __reduce_max_sync(FULL, d);
            int src = __ffs(__ballot_sync(FULL, d == m)) - 1;
            uint32_t ci = __shfl_sync(FULL, i, src);
            float fx = __shfl_sync(FULL, x, src);
            float fy = __shfl_sync(FULL, y, src);
            float fz = __shfl_sync(FULL, z, src);
            if (lane < C) {
                st_async_u64(rDI[kb], ((u64)m << 32) | ci, rMB[kb]);
                st_async_u64(rXY[kb],
                             ((u64)__float_as_uint(fy) << 32) | __float_as_uint(fx),
                             rMB[kb]);
                st_async_u32(rZ[kb], __float_as_uint(fz), rMB[kb]);
            }
        }

        mbar_wait_parity(mbk, parity);

        int cl = lane & (C - 1);
        u64 di = candDI[kb][cl];
        u64 xy = candXY[kb][cl];
        uint32_t zz = candZ[kb][cl];
        uint32_t d = (lane < C) ? (uint32_t)(di >> 32) : 0u;
        uint32_t m = __reduce_max_sync(FULL, d);
        int src = __ffs(__ballot_sync(FULL, d == m)) - 1;
        uint32_t wl = __shfl_sync(FULL, (uint32_t)di, src);
        u64 wxy = __shfl_sync(FULL, xy, src);
        uint32_t wzb = __shfl_sync(FULL, zz, src);
        float gx = __uint_as_float((uint32_t)wxy);
        float gy = __uint_as_float((uint32_t)(wxy >> 32));
        float gz = __uint_as_float(wzb);
        if (rank == 0 && tid == 0) g_sidx[b * NGn + k] = b * Nn + (int)wl;

        bd = -1.f; bj = 0;
#pragma unroll
        for (int j = 0; j < P; j++) {
            float nd = d2f(px[j], py[j], pz[j], gx, gy, gz);
            float mn = fminf(dist[j], nd);
            dist[j] = mn;
            if (mn > bd) { bd = mn; bj = j; }
        }
    }
}

// ---------------------------------------------------------------------------
// kNN (top-32 by (d2, idx) lex order) + angle/curvature + outputs.
// 256 threads = 8 warps = 8 samples/CTA, grid 1024; KCHUNK=1024 (24KB smem)
// -> 8 CTAs/SM = 2048 thr/SM. Scan predicate is a single d2<=tmd per point
// (false positives on exact ties re-checked by the full lex test inside the
// insertion loop — kept set bit-identical). 128 points/group via ulonglong2
// LDS.128; combined early-skip ballot.
// ---------------------------------------------------------------------------
__global__ void __launch_bounds__(256, 1)
knn_kernel(const float* __restrict__ coord, const float* __restrict__ feat,
           const int* __restrict__ labels, float* __restrict__ out) {
    __shared__ __align__(16) u64 scx[2][KCHUNK / 2];
    __shared__ __align__(16) u64 scy[2][KCHUNK / 2];
    __shared__ __align__(16) u64 scz[2][KCHUNK / 2];
    const unsigned FULL = 0xffffffffu;
    int tid = threadIdx.x, lane = tid & 31, wid = tid >> 5;
    int s = blockIdx.x * 8 + wid;    // sample id [0, 8192)
    int b = s >> 10;                 // batch
    int si = g_sidx[s];
    const float* cp = coord + (size_t)si * 3;
    float spx = cp[0], spy = cp[1], spz = cp[2];
    u64 nspx = packx2(-spx, -spx);
    u64 nspy = packx2(-spy, -spy);
    u64 nspz = packx2(-spz, -spz);

    float kd = 3.4028235e38f; unsigned ki = 0xffffffffu;    // kept (per lane)
    float tmd = 3.4028235e38f; unsigned tmi = 0xffffffffu; int tml = 0;

    constexpr int NT = Nn / KCHUNK;      // 32 tiles
    int pbase = b * (Nn / 2);
    // 256 threads stage 512 u64 per axis: 2 u64 = 1 cp.async16 per thread
    auto stage = [&](int buf, int c) {
        int po = pbase + c * (KCHUNK / 2) + tid * 2;
        uint32_t o = (uint32_t)tid * 16;
        cp_async16(s2u(&scx[buf][0]) + o, &g_px[po]);
        cp_async16(s2u(&scy[buf][0]) + o, &g_py[po]);
        cp_async16(s2u(&scz[buf][0]) + o, &g_pz[po]);
        cp_commit();
    };
    stage(0, 0);
    for (int c = 0; c < NT; c++) {
        int buf = c & 1;
        if (c + 1 < NT) { stage(buf ^ 1, c + 1); cp_wait<1>(); }
        else           { cp_wait<0>(); }
        __syncthreads();
        int cbase = b * Nn + c * KCHUNK;
        const ulonglong2* sx2 = (const ulonglong2*)scx[buf];
        const ulonglong2* sy2 = (const ulonglong2*)scy[buf];
        const ulonglong2* sz2 = (const ulonglong2*)scz[buf];
#pragma unroll 4
        for (int j = 0; j < KCHUNK / 128; j++) {         // 8 groups of 128
            int pi = j * 32 + lane;
            ulonglong2 vx = sx2[pi], vy = sy2[pi], vz = sz2[pi];
            u64 dx0 = addx2(vx.x, nspx), dx1 = addx2(vx.y, nspx);
            u64 dy0 = addx2(vy.x, nspy), dy1 = addx2(vy.y, nspy);
            u64 dz0 = addx2(vz.x, nspz), dz1 = addx2(vz.y, nspz);
            u64 s0 = addx2(addx2(mulx2(dx0, dx0), mulx2(dy0, dy0)), mulx2(dz0, dz0));
            u64 s1 = addx2(addx2(mulx2(dx1, dx1), mulx2(dy1, dy1)), mulx2(dz1, dz1));
            float dA, dB, dC, dD;
            unpackx2(dA, dB, s0);
            unpackx2(dC, dD, s1);
            // cheap predicate: d2 <= tmd (ties re-checked with full lex below)
            bool cA = dA <= tmd, cB = dB <= tmd, cC = dC <= tmd, cD = dD <= tmd;
            if (__ballot_sync(FULL, cA || cB || cC || cD) == 0u) continue;
            int gb = cbase + j * 128;                    // group base point idx
            unsigned mA = __ballot_sync(FULL, cA);
            unsigned mB = __ballot_sync(FULL, cB);
            unsigned mC = __ballot_sync(FULL, cC);
            unsigned mD = __ballot_sync(FULL, cD);
#pragma unroll
            for (int h = 0; h < 4; h++) {
                unsigned mm = (h == 0) ? mA : (h == 1) ? mB : (h == 2) ? mC : mD;
                float dv = (h == 0) ? dA : (h == 1) ? dB : (h == 2) ? dC : dD;
                while (mm) {
                    int ins = __ffs(mm) - 1; mm &= mm - 1;
                    float cd = __shfl_sync(FULL, dv, ins);
                    unsigned cgi = (unsigned)(gb + 4 * ins + h);
                    if ((cd < tmd) || (cd == tmd && cgi < tmi)) {  // full lex
                        if (lane == tml) { kd = cd; ki = cgi; }
                        unsigned db = __float_as_uint(kd);
                        unsigned m  = __reduce_max_sync(FULL, db);
                        bool tie    = (db == m);
                        unsigned mi2 = __reduce_max_sync(FULL, tie ? ki : 0u);
                        tml = __ffs(__ballot_sync(FULL, tie && ki == mi2)) - 1;
                        tmd = __uint_as_float(m); tmi = mi2;
                    }
                }
            }
        }
        __syncthreads();   // scan done before next overwrite of buf
    }

    // ---- angles: angle = 2*atan2(sqrt(t - a.b), sqrt(t + a.b)), t=|a||b| ----
    float a_own = feat[(size_t)si * FDn + lane];
    float dot = 0.f, an2 = 0.f, bn2 = 0.f;
    const float4* frow = (const float4*)(feat + (size_t)ki * FDn);
#pragma unroll
    for (int g = 0; g < FDn / 4; g++) {
        float4 bv = frow[g];
        float a0 = __shfl_sync(FULL, a_own, g * 4 + 0);
        float a1 = __shfl_sync(FULL, a_own, g * 4 + 1);
        float a2 = __shfl_sync(FULL, a_own, g * 4 + 2);
        float a3 = __shfl_sync(FULL, a_own, g * 4 + 3);
        dot = fmaf(a0, bv.x, dot); an2 = fmaf(a0, a0, an2); bn2 = fmaf(bv.x, bv.x, bn2);
        dot = fmaf(a1, bv.y, dot); an2 = fmaf(a1, a1, an2); bn2 = fmaf(bv.y, bv.y, bn2);
        dot = fmaf(a2, bv.z, dot); an2 = fmaf(a2, a2, an2); bn2 = fmaf(bv.z, bv.z, bn2);
        dot = fmaf(a3, bv.w, dot); an2 = fmaf(a3, a3, an2); bn2 = fmaf(bv.w, bv.w, bn2);
    }
    float t = sqrtf(an2) * sqrtf(bn2);
    float ang = 2.f * atan2f(sqrtf(fmaxf(t - dot, 0.f)), sqrtf(fmaxf(t + dot, 0.f)));
    if (ki == (unsigned)si) ang = 0.f;   // self neighbor contributes 0
    float ssum = ang;
#pragma unroll
    for (int o = 16; o; o >>= 1) ssum += __shfl_xor_sync(FULL, ssum, o);
    float pc = ssum / 31.f;

    // ---- outputs (tuple flattened+concatenated as float32) ----
    const int OFF_FEAT = Bn * NGn * 3;
    const int OFF_SW   = OFF_FEAT + Bn * NGn * (FDn + 1);
    const int OFF_LAB  = OFF_SW + Bn * NGn;
    const int OFF_SIDX = OFF_LAB + Bn * NGn;
    if (lane < 3) out[s * 3 + lane] = coord[si * 3 + lane];
    out[OFF_FEAT + s * 33 + lane] = a_own;
    if (lane == 0) {
        out[OFF_FEAT + s * 33 + 32] = pc;
        out[OFF_SW + s]   = pc > 0.087266f ? 1.f : 0.f;
        out[OFF_LAB + s]  = (float)labels[si];
        out[OFF_SIDX + s] = (float)si;
    }
}

// ---------------------------------------------------------------------------
extern "C" void kernel_launch(void* const* d_in, const int* in_sizes, int n_in,
                              void* d_out, int out_size) {
    const float* coord  = (const float*)d_in[0];
    const float* feat   = (const float*)d_in[1];
    const int*   labels = (const int*)d_in[2];
    float* out = (float*)d_out;

    cudaError_t rc = cudaFuncSetAttribute(
        (const void*)fps_kernel16,
        cudaFuncAttributeNonPortableClusterSizeAllowed, 1);
    if (rc == cudaSuccess) {
        fps_kernel16<<<Bn * 16, 256>>>(coord);   // packs g_px/g_py/g_pz itself
    } else {
        (void)cudaGetLastError();
        pack_kernel<<<(Bn * Nn / 4 + 255) / 256, 256>>>(coord);
        fps_kernel8<<<Bn * 8, 1024>>>();
    }

    knn_kernel<<<(Bn * NGn) / 8, 256>>>(coord, feat, labels, out);
}